// round 1
// baseline (speedup 1.0000x reference)
#include <cuda_runtime.h>
#include <cuda_bf16.h>

#define HIDDEN 1024
#define BATCH 8
#define SEQ 2048
#define MTOT (BATCH * SEQ)          // 16384 rows
#define NEG_INF -1e38f

// ---------------------------------------------------------------------------
// Scratch (device globals; no allocation allowed in kernel_launch)
// ---------------------------------------------------------------------------
__device__ float g_xk[MTOT * HIDDEN];
__device__ float g_xv[MTOT * HIDDEN];
__device__ float g_xr[MTOT * HIDDEN];
__device__ float g_k [MTOT * HIDDEN];
__device__ float g_v [MTOT * HIDDEN];
__device__ float g_r [MTOT * HIDDEN];
__device__ float g_rwkv[MTOT * HIDDEN];

// ---------------------------------------------------------------------------
// 1) Time-mix: xk/xv/xr = x*m + x_prev*(1-m), x_prev = x shifted by one step
//    (zero at t==0). Vectorized float4; H divisible by 4.
// ---------------------------------------------------------------------------
__global__ void mix_kernel(const float* __restrict__ x,
                           const float* __restrict__ mk,
                           const float* __restrict__ mv,
                           const float* __restrict__ mr) {
    int i = blockIdx.x * blockDim.x + threadIdx.x;     // over MTOT*HIDDEN/4
    if (i >= MTOT * HIDDEN / 4) return;
    int idx = i * 4;
    int h = idx & (HIDDEN - 1);
    int t = (idx / HIDDEN) & (SEQ - 1);

    float4 xc = *reinterpret_cast<const float4*>(x + idx);
    float4 xp = (t == 0) ? make_float4(0.f, 0.f, 0.f, 0.f)
                         : *reinterpret_cast<const float4*>(x + idx - HIDDEN);
    float4 k4 = *reinterpret_cast<const float4*>(mk + h);
    float4 v4 = *reinterpret_cast<const float4*>(mv + h);
    float4 r4 = *reinterpret_cast<const float4*>(mr + h);

    float4 ok, ov, orr;
    ok.x = xc.x * k4.x + xp.x * (1.f - k4.x);
    ok.y = xc.y * k4.y + xp.y * (1.f - k4.y);
    ok.z = xc.z * k4.z + xp.z * (1.f - k4.z);
    ok.w = xc.w * k4.w + xp.w * (1.f - k4.w);
    ov.x = xc.x * v4.x + xp.x * (1.f - v4.x);
    ov.y = xc.y * v4.y + xp.y * (1.f - v4.y);
    ov.z = xc.z * v4.z + xp.z * (1.f - v4.z);
    ov.w = xc.w * v4.w + xp.w * (1.f - v4.w);
    orr.x = xc.x * r4.x + xp.x * (1.f - r4.x);
    orr.y = xc.y * r4.y + xp.y * (1.f - r4.y);
    orr.z = xc.z * r4.z + xp.z * (1.f - r4.z);
    orr.w = xc.w * r4.w + xp.w * (1.f - r4.w);

    *reinterpret_cast<float4*>(g_xk + idx) = ok;
    *reinterpret_cast<float4*>(g_xv + idx) = ov;
    *reinterpret_cast<float4*>(g_xr + idx) = orr;
}

// ---------------------------------------------------------------------------
// 2) SGEMM NT: C[M,N] = A[M,K] * W[N,K]^T, all row-major, K = N = 1024,
//    M = 16384. BM=BN=128, BK=8, 256 threads, 8x8 per-thread tile.
//    Optional sigmoid epilogue (for r).
// ---------------------------------------------------------------------------
template <bool SIGMOID>
__global__ __launch_bounds__(256)
void sgemm_nt(const float* __restrict__ A, const float* __restrict__ W,
              float* __restrict__ C, int M, int N, int K) {
    __shared__ float As[8][128];
    __shared__ float Bs[8][128];

    const int bm = blockIdx.y * 128;
    const int bn = blockIdx.x * 128;
    const int tid = threadIdx.x;

    // load mapping: 128 rows x 8 cols per tile, one float4 per thread
    const int lrow = tid >> 1;          // 0..127
    const int lseg = (tid & 1) * 4;     // 0 or 4

    // compute mapping: 16x16 thread grid of 8x8 tiles
    const int tcol = (tid & 15) * 8;
    const int trow = (tid >> 4) * 8;

    const float* Aptr = A + (size_t)(bm + lrow) * K + lseg;
    const float* Wptr = W + (size_t)(bn + lrow) * K + lseg;

    float acc[8][8];
#pragma unroll
    for (int i = 0; i < 8; i++)
#pragma unroll
        for (int j = 0; j < 8; j++) acc[i][j] = 0.f;

    for (int k0 = 0; k0 < K; k0 += 8) {
        float4 av = *reinterpret_cast<const float4*>(Aptr + k0);
        float4 bv = *reinterpret_cast<const float4*>(Wptr + k0);
        As[lseg + 0][lrow] = av.x;
        As[lseg + 1][lrow] = av.y;
        As[lseg + 2][lrow] = av.z;
        As[lseg + 3][lrow] = av.w;
        Bs[lseg + 0][lrow] = bv.x;
        Bs[lseg + 1][lrow] = bv.y;
        Bs[lseg + 2][lrow] = bv.z;
        Bs[lseg + 3][lrow] = bv.w;
        __syncthreads();

#pragma unroll
        for (int kk = 0; kk < 8; kk++) {
            float4 a0 = *reinterpret_cast<const float4*>(&As[kk][trow]);
            float4 a1 = *reinterpret_cast<const float4*>(&As[kk][trow + 4]);
            float4 b0 = *reinterpret_cast<const float4*>(&Bs[kk][tcol]);
            float4 b1 = *reinterpret_cast<const float4*>(&Bs[kk][tcol + 4]);
            float af[8] = {a0.x, a0.y, a0.z, a0.w, a1.x, a1.y, a1.z, a1.w};
            float bf[8] = {b0.x, b0.y, b0.z, b0.w, b1.x, b1.y, b1.z, b1.w};
#pragma unroll
            for (int i = 0; i < 8; i++)
#pragma unroll
                for (int j = 0; j < 8; j++)
                    acc[i][j] = fmaf(af[i], bf[j], acc[i][j]);
        }
        __syncthreads();
    }

#pragma unroll
    for (int i = 0; i < 8; i++) {
        float* crow = C + (size_t)(bm + trow + i) * N + bn + tcol;
#pragma unroll
        for (int j = 0; j < 8; j += 4) {
            float4 o;
            if (SIGMOID) {
                o.x = 1.f / (1.f + __expf(-acc[i][j + 0]));
                o.y = 1.f / (1.f + __expf(-acc[i][j + 1]));
                o.z = 1.f / (1.f + __expf(-acc[i][j + 2]));
                o.w = 1.f / (1.f + __expf(-acc[i][j + 3]));
            } else {
                o.x = acc[i][j + 0];
                o.y = acc[i][j + 1];
                o.z = acc[i][j + 2];
                o.w = acc[i][j + 3];
            }
            *reinterpret_cast<float4*>(crow + j) = o;
        }
    }
}

// ---------------------------------------------------------------------------
// 3) WKV scan: one thread per (b, h) channel, sequential over T.
//    Writes rwkv = r * wkv directly.
// ---------------------------------------------------------------------------
__global__ void wkv_scan(const float* __restrict__ w_,
                         const float* __restrict__ u_) {
    int idx = blockIdx.x * blockDim.x + threadIdx.x;   // over BATCH*HIDDEN
    if (idx >= BATCH * HIDDEN) return;
    int b = idx / HIDDEN;
    int h = idx & (HIDDEN - 1);

    const float w = w_[h];
    const float u = u_[h];

    const size_t base = (size_t)b * SEQ * HIDDEN + h;
    const float* kp = g_k + base;
    const float* vp = g_v + base;
    const float* rp = g_r + base;
    float* op = g_rwkv + base;

    float aa = 0.f, bb = 0.f, pp = NEG_INF;

    for (int t = 0; t < SEQ; t++) {
        size_t off = (size_t)t * HIDDEN;
        float k = kp[off];
        float v = vp[off];

        float ww = u + k;
        float p = fmaxf(pp, ww);
        float e1 = __expf(pp - p);
        float e2 = __expf(ww - p);
        float wkv = (e1 * aa + e2 * v) / (e1 * bb + e2 + 1e-9f);
        op[off] = rp[off] * wkv;

        float ww2 = w + pp;
        float p2 = fmaxf(ww2, k);
        float e1b = __expf(ww2 - p2);
        float e2b = __expf(k - p2);
        aa = e1b * aa + e2b * v;
        bb = e1b * bb + e2b;
        pp = p2;
    }
}

// ---------------------------------------------------------------------------
// Launch: inputs in metadata order:
//   0 x, 1 time_decay, 2 time_first, 3 time_mix_k, 4 time_mix_v,
//   5 time_mix_r, 6 W_k, 7 W_v, 8 W_r, 9 W_o
// ---------------------------------------------------------------------------
extern "C" void kernel_launch(void* const* d_in, const int* in_sizes, int n_in,
                              void* d_out, int out_size) {
    const float* x  = (const float*)d_in[0];
    const float* td = (const float*)d_in[1];
    const float* tf = (const float*)d_in[2];
    const float* mk = (const float*)d_in[3];
    const float* mv = (const float*)d_in[4];
    const float* mr = (const float*)d_in[5];
    const float* Wk = (const float*)d_in[6];
    const float* Wv = (const float*)d_in[7];
    const float* Wr = (const float*)d_in[8];
    const float* Wo = (const float*)d_in[9];
    float* out = (float*)d_out;

    float *xk, *xv, *xr, *k, *v, *r, *rwkv;
    cudaGetSymbolAddress((void**)&xk, g_xk);
    cudaGetSymbolAddress((void**)&xv, g_xv);
    cudaGetSymbolAddress((void**)&xr, g_xr);
    cudaGetSymbolAddress((void**)&k,  g_k);
    cudaGetSymbolAddress((void**)&v,  g_v);
    cudaGetSymbolAddress((void**)&r,  g_r);
    cudaGetSymbolAddress((void**)&rwkv, g_rwkv);

    // 1) time-mix
    {
        int n4 = MTOT * HIDDEN / 4;
        mix_kernel<<<(n4 + 255) / 256, 256>>>(x, mk, mv, mr);
    }

    // 2) k / v / r projections
    dim3 ggrid(HIDDEN / 128, MTOT / 128);
    sgemm_nt<false><<<ggrid, 256>>>(xk, Wk, k, MTOT, HIDDEN, HIDDEN);
    sgemm_nt<false><<<ggrid, 256>>>(xv, Wv, v, MTOT, HIDDEN, HIDDEN);
    sgemm_nt<true ><<<ggrid, 256>>>(xr, Wr, r, MTOT, HIDDEN, HIDDEN);

    // 3) wkv scan (writes r * wkv)
    {
        int nch = BATCH * HIDDEN;
        wkv_scan<<<(nch + 255) / 256, 256>>>(td, tf);
    }

    // 4) output projection
    sgemm_nt<false><<<ggrid, 256>>>(rwkv, Wo, out, MTOT, HIDDEN, HIDDEN);
}

// round 2
// speedup vs baseline: 1.5724x; 1.5724x over previous
#include <cuda_runtime.h>
#include <cuda_bf16.h>

#define HIDDEN 1024
#define BATCH 8
#define SEQ 2048
#define MTOT (BATCH * SEQ)          // 16384 rows
#define NEG_INF -1e38f
#define CH (BATCH * HIDDEN)         // 8192 channels
#define LCHUNK 128
#define NCHUNK (SEQ / LCHUNK)       // 16

// ---------------------------------------------------------------------------
// Scratch (device globals; no allocation allowed)
// ---------------------------------------------------------------------------
__device__ float g_xk[MTOT * HIDDEN];
__device__ float g_xv[MTOT * HIDDEN];
__device__ float g_xr[MTOT * HIDDEN];
__device__ float g_k [MTOT * HIDDEN];
__device__ float g_v [MTOT * HIDDEN];
__device__ float g_r [MTOT * HIDDEN];
__device__ float g_rwkv[MTOT * HIDDEN];

// chunk-scan summaries & prefixes
__device__ float g_saa[CH * NCHUNK];
__device__ float g_sbb[CH * NCHUNK];
__device__ float g_spp[CH * NCHUNK];
__device__ float g_iaa[CH * NCHUNK];
__device__ float g_ibb[CH * NCHUNK];
__device__ float g_ipp[CH * NCHUNK];

// ---------------------------------------------------------------------------
// tf32 helpers
// ---------------------------------------------------------------------------
__device__ __forceinline__ unsigned tf32_rna(float f) {
    unsigned u;
    asm("cvt.rna.tf32.f32 %0, %1;" : "=r"(u) : "f"(f));
    return u;
}

#define MMA_TF32(c, a, b)                                                     \
    asm volatile(                                                             \
        "mma.sync.aligned.m16n8k8.row.col.f32.tf32.tf32.f32 "                 \
        "{%0,%1,%2,%3},{%4,%5,%6,%7},{%8,%9},{%0,%1,%2,%3};"                  \
        : "+f"((c)[0]), "+f"((c)[1]), "+f"((c)[2]), "+f"((c)[3])              \
        : "r"((a)[0]), "r"((a)[1]), "r"((a)[2]), "r"((a)[3]),                 \
          "r"((b)[0]), "r"((b)[1]))

// ---------------------------------------------------------------------------
// 1) Time-mix
// ---------------------------------------------------------------------------
__global__ void mix_kernel(const float* __restrict__ x,
                           const float* __restrict__ mk,
                           const float* __restrict__ mv,
                           const float* __restrict__ mr) {
    int i = blockIdx.x * blockDim.x + threadIdx.x;
    if (i >= MTOT * HIDDEN / 4) return;
    int idx = i * 4;
    int h = idx & (HIDDEN - 1);
    int t = (idx / HIDDEN) & (SEQ - 1);

    float4 xc = *reinterpret_cast<const float4*>(x + idx);
    float4 xp = (t == 0) ? make_float4(0.f, 0.f, 0.f, 0.f)
                         : *reinterpret_cast<const float4*>(x + idx - HIDDEN);
    float4 k4 = *reinterpret_cast<const float4*>(mk + h);
    float4 v4 = *reinterpret_cast<const float4*>(mv + h);
    float4 r4 = *reinterpret_cast<const float4*>(mr + h);

    float4 ok, ov, orr;
    ok.x = xc.x * k4.x + xp.x * (1.f - k4.x);
    ok.y = xc.y * k4.y + xp.y * (1.f - k4.y);
    ok.z = xc.z * k4.z + xp.z * (1.f - k4.z);
    ok.w = xc.w * k4.w + xp.w * (1.f - k4.w);
    ov.x = xc.x * v4.x + xp.x * (1.f - v4.x);
    ov.y = xc.y * v4.y + xp.y * (1.f - v4.y);
    ov.z = xc.z * v4.z + xp.z * (1.f - v4.z);
    ov.w = xc.w * v4.w + xp.w * (1.f - v4.w);
    orr.x = xc.x * r4.x + xp.x * (1.f - r4.x);
    orr.y = xc.y * r4.y + xp.y * (1.f - r4.y);
    orr.z = xc.z * r4.z + xp.z * (1.f - r4.z);
    orr.w = xc.w * r4.w + xp.w * (1.f - r4.w);

    *reinterpret_cast<float4*>(g_xk + idx) = ok;
    *reinterpret_cast<float4*>(g_xv + idx) = ov;
    *reinterpret_cast<float4*>(g_xr + idx) = orr;
}

// ---------------------------------------------------------------------------
// 2) TF32 tensor-core GEMM (3xTF32 split for fp32-class accuracy)
//    C[M,N] = A[M,K] * W[N,K]^T.  BM=BN=128, BK=16, 256 threads (8 warps),
//    warp tile 64x32 via m16n8k8.
// ---------------------------------------------------------------------------
template <bool SIGMOID>
__global__ __launch_bounds__(256)
void gemm_tf32(const float* __restrict__ A, const float* __restrict__ W,
               float* __restrict__ C, int M, int N, int K) {
    __shared__ float Ah[16][132];
    __shared__ float Al[16][132];
    __shared__ float Bh[16][132];
    __shared__ float Bl[16][132];

    const int tid  = threadIdx.x;
    const int lane = tid & 31;
    const int wid  = tid >> 5;
    const int wm   = wid >> 2;      // 0..1
    const int wn   = wid & 3;       // 0..3
    const int bm   = blockIdx.y * 128;
    const int bn   = blockIdx.x * 128;

    // gmem load mapping: row = tid/2, 8 contiguous k per thread
    const int lr = tid >> 1;
    const int lk = (tid & 1) * 8;

    const float* Ap = A + (size_t)(bm + lr) * K + lk;
    const float* Wp = W + (size_t)(bn + lr) * K + lk;

    float4 av0 = *reinterpret_cast<const float4*>(Ap);
    float4 av1 = *reinterpret_cast<const float4*>(Ap + 4);
    float4 wv0 = *reinterpret_cast<const float4*>(Wp);
    float4 wv1 = *reinterpret_cast<const float4*>(Wp + 4);

    float acc[4][4][4];
#pragma unroll
    for (int i = 0; i < 4; i++)
#pragma unroll
        for (int j = 0; j < 4; j++)
#pragma unroll
            for (int q = 0; q < 4; q++) acc[i][j][q] = 0.f;

#pragma unroll 1
    for (int k0 = 0; k0 < K; k0 += 16) {
        // split current tile into hi/lo and stage to smem
        float af[8] = {av0.x, av0.y, av0.z, av0.w, av1.x, av1.y, av1.z, av1.w};
        float wf[8] = {wv0.x, wv0.y, wv0.z, wv0.w, wv1.x, wv1.y, wv1.z, wv1.w};
#pragma unroll
        for (int j = 0; j < 8; j++) {
            unsigned h = tf32_rna(af[j]);
            Ah[lk + j][lr] = __uint_as_float(h);
            Al[lk + j][lr] = __uint_as_float(tf32_rna(af[j] - __uint_as_float(h)));
            h = tf32_rna(wf[j]);
            Bh[lk + j][lr] = __uint_as_float(h);
            Bl[lk + j][lr] = __uint_as_float(tf32_rna(wf[j] - __uint_as_float(h)));
        }
        __syncthreads();

        // prefetch next tile (overlaps with mma work below)
        if (k0 + 16 < K) {
            av0 = *reinterpret_cast<const float4*>(Ap + k0 + 16);
            av1 = *reinterpret_cast<const float4*>(Ap + k0 + 20);
            wv0 = *reinterpret_cast<const float4*>(Wp + k0 + 16);
            wv1 = *reinterpret_cast<const float4*>(Wp + k0 + 20);
        }

#pragma unroll
        for (int kc = 0; kc < 16; kc += 8) {
            const int kr = kc + (lane & 3);
            unsigned ahf[4][4], alf[4][4], bhf[4][2], blf[4][2];
#pragma unroll
            for (int mf = 0; mf < 4; mf++) {
                int r = wm * 64 + mf * 16 + (lane >> 2);
                ahf[mf][0] = __float_as_uint(Ah[kr][r]);
                ahf[mf][1] = __float_as_uint(Ah[kr][r + 8]);
                ahf[mf][2] = __float_as_uint(Ah[kr + 4][r]);
                ahf[mf][3] = __float_as_uint(Ah[kr + 4][r + 8]);
                alf[mf][0] = __float_as_uint(Al[kr][r]);
                alf[mf][1] = __float_as_uint(Al[kr][r + 8]);
                alf[mf][2] = __float_as_uint(Al[kr + 4][r]);
                alf[mf][3] = __float_as_uint(Al[kr + 4][r + 8]);
            }
#pragma unroll
            for (int nf = 0; nf < 4; nf++) {
                int cn = wn * 32 + nf * 8 + (lane >> 2);
                bhf[nf][0] = __float_as_uint(Bh[kr][cn]);
                bhf[nf][1] = __float_as_uint(Bh[kr + 4][cn]);
                blf[nf][0] = __float_as_uint(Bl[kr][cn]);
                blf[nf][1] = __float_as_uint(Bl[kr + 4][cn]);
            }
#pragma unroll
            for (int mf = 0; mf < 4; mf++)
#pragma unroll
                for (int nf = 0; nf < 4; nf++) {
                    MMA_TF32(acc[mf][nf], ahf[mf], bhf[nf]);
                    MMA_TF32(acc[mf][nf], ahf[mf], blf[nf]);
                    MMA_TF32(acc[mf][nf], alf[mf], bhf[nf]);
                }
        }
        __syncthreads();
    }

    // epilogue
#pragma unroll
    for (int mf = 0; mf < 4; mf++) {
        int r0 = bm + wm * 64 + mf * 16 + (lane >> 2);
#pragma unroll
        for (int nf = 0; nf < 4; nf++) {
            int cc = bn + wn * 32 + nf * 8 + 2 * (lane & 3);
            float c0 = acc[mf][nf][0], c1 = acc[mf][nf][1];
            float c2 = acc[mf][nf][2], c3 = acc[mf][nf][3];
            if (SIGMOID) {
                c0 = 1.f / (1.f + __expf(-c0));
                c1 = 1.f / (1.f + __expf(-c1));
                c2 = 1.f / (1.f + __expf(-c2));
                c3 = 1.f / (1.f + __expf(-c3));
            }
            *reinterpret_cast<float2*>(C + (size_t)r0 * N + cc) = make_float2(c0, c1);
            *reinterpret_cast<float2*>(C + (size_t)(r0 + 8) * N + cc) = make_float2(c2, c3);
        }
    }
}

// ---------------------------------------------------------------------------
// 3) Chunk-parallel WKV scan
//    Phase 1: local chunk summaries (aa, bb, pp) from init (0, 0, -inf)
//    Phase 2: sequential combine over 16 chunks per channel; record prefixes
//    Phase 3: rescan chunk with exact prefix state; write r * wkv
// ---------------------------------------------------------------------------
__global__ void wkv_phase1(const float* __restrict__ td) {
    int idx = blockIdx.x * blockDim.x + threadIdx.x;
    if (idx >= CH * NCHUNK) return;
    int h = idx & (HIDDEN - 1);
    int bc = idx >> 10;             // b * NCHUNK + c
    int c = bc & (NCHUNK - 1);
    int b = bc >> 4;

    const float w = td[h];
    const size_t base = ((size_t)b * SEQ + (size_t)c * LCHUNK) * HIDDEN + h;
    const float* kp = g_k + base;
    const float* vp = g_v + base;

    float aa = 0.f, bb = 0.f, pp = NEG_INF;
#pragma unroll 4
    for (int t = 0; t < LCHUNK; t++) {
        float k = kp[(size_t)t * HIDDEN];
        float v = vp[(size_t)t * HIDDEN];
        float ww2 = w + pp;
        float p2 = fmaxf(ww2, k);
        float e1 = __expf(ww2 - p2);
        float e2 = __expf(k - p2);
        aa = e1 * aa + e2 * v;
        bb = e1 * bb + e2;
        pp = p2;
    }
    g_saa[idx] = aa;
    g_sbb[idx] = bb;
    g_spp[idx] = pp;
}

__global__ void wkv_phase2(const float* __restrict__ td) {
    int idx = blockIdx.x * blockDim.x + threadIdx.x;
    if (idx >= CH) return;
    int h = idx & (HIDDEN - 1);
    int b = idx >> 10;
    const float wl = td[h] * (float)LCHUNK;

    float aa = 0.f, bb = 0.f, pp = NEG_INF;
#pragma unroll
    for (int c = 0; c < NCHUNK; c++) {
        int s = (b * NCHUNK + c) * HIDDEN + h;
        g_iaa[s] = aa;
        g_ibb[s] = bb;
        g_ipp[s] = pp;
        float laa = g_saa[s], lbb = g_sbb[s], lpp = g_spp[s];
        float sp = pp + wl;
        float p = fmaxf(sp, lpp);
        float e1 = __expf(sp - p);
        float e2 = __expf(lpp - p);
        aa = e1 * aa + e2 * laa;
        bb = e1 * bb + e2 * lbb;
        pp = p;
    }
}

__global__ void wkv_phase3(const float* __restrict__ td,
                           const float* __restrict__ tf) {
    int idx = blockIdx.x * blockDim.x + threadIdx.x;
    if (idx >= CH * NCHUNK) return;
    int h = idx & (HIDDEN - 1);
    int bc = idx >> 10;
    int c = bc & (NCHUNK - 1);
    int b = bc >> 4;

    const float w = td[h];
    const float u = tf[h];
    const size_t base = ((size_t)b * SEQ + (size_t)c * LCHUNK) * HIDDEN + h;
    const float* kp = g_k + base;
    const float* vp = g_v + base;
    const float* rp = g_r + base;
    float* op = g_rwkv + base;

    float aa = g_iaa[idx], bb = g_ibb[idx], pp = g_ipp[idx];

#pragma unroll 4
    for (int t = 0; t < LCHUNK; t++) {
        size_t off = (size_t)t * HIDDEN;
        float k = kp[off];
        float v = vp[off];

        float ww = u + k;
        float p = fmaxf(pp, ww);
        float e1 = __expf(pp - p);
        float e2 = __expf(ww - p);
        float wkv = (e1 * aa + e2 * v) / (e1 * bb + e2 + 1e-9f);
        op[off] = rp[off] * wkv;

        float ww2 = w + pp;
        float p2 = fmaxf(ww2, k);
        float e1b = __expf(ww2 - p2);
        float e2b = __expf(k - p2);
        aa = e1b * aa + e2b * v;
        bb = e1b * bb + e2b;
        pp = p2;
    }
}

// ---------------------------------------------------------------------------
// Launch
// ---------------------------------------------------------------------------
extern "C" void kernel_launch(void* const* d_in, const int* in_sizes, int n_in,
                              void* d_out, int out_size) {
    const float* x  = (const float*)d_in[0];
    const float* td = (const float*)d_in[1];
    const float* tf = (const float*)d_in[2];
    const float* mk = (const float*)d_in[3];
    const float* mv = (const float*)d_in[4];
    const float* mr = (const float*)d_in[5];
    const float* Wk = (const float*)d_in[6];
    const float* Wv = (const float*)d_in[7];
    const float* Wr = (const float*)d_in[8];
    const float* Wo = (const float*)d_in[9];
    float* out = (float*)d_out;

    float *xk, *xv, *xr, *k, *v, *r, *rwkv;
    cudaGetSymbolAddress((void**)&xk, g_xk);
    cudaGetSymbolAddress((void**)&xv, g_xv);
    cudaGetSymbolAddress((void**)&xr, g_xr);
    cudaGetSymbolAddress((void**)&k,  g_k);
    cudaGetSymbolAddress((void**)&v,  g_v);
    cudaGetSymbolAddress((void**)&r,  g_r);
    cudaGetSymbolAddress((void**)&rwkv, g_rwkv);

    // 1) time-mix
    {
        int n4 = MTOT * HIDDEN / 4;
        mix_kernel<<<(n4 + 255) / 256, 256>>>(x, mk, mv, mr);
    }

    // 2) k / v / r projections (tensor cores, 3xTF32)
    dim3 ggrid(HIDDEN / 128, MTOT / 128);
    gemm_tf32<false><<<ggrid, 256>>>(xk, Wk, k, MTOT, HIDDEN, HIDDEN);
    gemm_tf32<false><<<ggrid, 256>>>(xv, Wv, v, MTOT, HIDDEN, HIDDEN);
    gemm_tf32<true ><<<ggrid, 256>>>(xr, Wr, r, MTOT, HIDDEN, HIDDEN);

    // 3) chunk-parallel wkv scan (writes r * wkv)
    wkv_phase1<<<(CH * NCHUNK + 255) / 256, 256>>>(td);
    wkv_phase2<<<(CH + 255) / 256, 256>>>(td);
    wkv_phase3<<<(CH * NCHUNK + 255) / 256, 256>>>(td, tf);

    // 4) output projection
    gemm_tf32<false><<<ggrid, 256>>>(rwkv, Wo, out, MTOT, HIDDEN, HIDDEN);
}

// round 4
// speedup vs baseline: 3.8651x; 2.4581x over previous
#include <cuda_runtime.h>
#include <cuda_bf16.h>
#include <cstdint>

#define HIDDEN 1024
#define BATCH 8
#define SEQ 2048
#define MTOT (BATCH * SEQ)          // 16384 rows
#define NEG_INF -1e38f
#define CH (BATCH * HIDDEN)         // 8192 channels
#define LCHUNK 128
#define NCHUNK (SEQ / LCHUNK)       // 16

// GEMM tiling (legacy mma.sync bf16 m16n8k16)
#define BM 128
#define BN 128
#define BK 32
#define KITER (HIDDEN / BK)         // 32
#define APITCH 40                   // 32 + 8 pad (bf16 elems) -> 80B row pitch
#define TILE_BYTES (BM * APITCH * 2)        // 10240
#define AH_OFF 0
#define AL_OFF TILE_BYTES
#define BH_OFF (2 * TILE_BYTES)
#define BL_OFF (3 * TILE_BYTES)
#define STAGE_BYTES (4 * TILE_BYTES)        // 40960
#define SMEM_TOTAL (2 * STAGE_BYTES)        // 81920

// ---------------------------------------------------------------------------
// Scratch (device globals)
// ---------------------------------------------------------------------------
__device__ __nv_bfloat16 g_xkh[MTOT * HIDDEN];
__device__ __nv_bfloat16 g_xkl[MTOT * HIDDEN];
__device__ __nv_bfloat16 g_xvh[MTOT * HIDDEN];
__device__ __nv_bfloat16 g_xvl[MTOT * HIDDEN];
__device__ __nv_bfloat16 g_xrh[MTOT * HIDDEN];
__device__ __nv_bfloat16 g_xrl[MTOT * HIDDEN];
__device__ __nv_bfloat16 g_oh [MTOT * HIDDEN];
__device__ __nv_bfloat16 g_ol [MTOT * HIDDEN];

__device__ __nv_bfloat16 g_Wkh[HIDDEN * HIDDEN];
__device__ __nv_bfloat16 g_Wkl[HIDDEN * HIDDEN];
__device__ __nv_bfloat16 g_Wvh[HIDDEN * HIDDEN];
__device__ __nv_bfloat16 g_Wvl[HIDDEN * HIDDEN];
__device__ __nv_bfloat16 g_Wrh[HIDDEN * HIDDEN];
__device__ __nv_bfloat16 g_Wrl[HIDDEN * HIDDEN];
__device__ __nv_bfloat16 g_Woh[HIDDEN * HIDDEN];
__device__ __nv_bfloat16 g_Wol[HIDDEN * HIDDEN];

__device__ float g_k[MTOT * HIDDEN];
__device__ float g_v[MTOT * HIDDEN];
__device__ float g_r[MTOT * HIDDEN];

__device__ float g_saa[CH * NCHUNK];
__device__ float g_sbb[CH * NCHUNK];
__device__ float g_spp[CH * NCHUNK];
__device__ float g_iaa[CH * NCHUNK];
__device__ float g_ibb[CH * NCHUNK];
__device__ float g_ipp[CH * NCHUNK];

// ---------------------------------------------------------------------------
// Helpers
// ---------------------------------------------------------------------------
__device__ __forceinline__ uint32_t smem_u32(const void* p) {
    uint32_t a;
    asm("{ .reg .u64 t; cvta.to.shared.u64 t, %1; cvt.u32.u64 %0, t; }"
        : "=r"(a) : "l"(p));
    return a;
}

__device__ __forceinline__ void cp16(uint32_t s, const void* g) {
    asm volatile("cp.async.cg.shared.global [%0], [%1], 16;" :: "r"(s), "l"(g));
}

__device__ __forceinline__ void split1(float a, __nv_bfloat16* h, __nv_bfloat16* l) {
    __nv_bfloat16 hh = __float2bfloat16(a);
    *h = hh;
    *l = __float2bfloat16(a - __bfloat162float(hh));
}

#define MMA_BF16(c, a, b)                                                     \
    asm volatile(                                                             \
        "mma.sync.aligned.m16n8k16.row.col.f32.bf16.bf16.f32 "                \
        "{%0,%1,%2,%3},{%4,%5,%6,%7},{%8,%9},{%0,%1,%2,%3};"                  \
        : "+f"((c)[0]), "+f"((c)[1]), "+f"((c)[2]), "+f"((c)[3])              \
        : "r"((a)[0]), "r"((a)[1]), "r"((a)[2]), "r"((a)[3]),                 \
          "r"((b)[0]), "r"((b)[1]))

// ---------------------------------------------------------------------------
// 1) Time-mix + bf16 hi/lo split
// ---------------------------------------------------------------------------
__global__ void mix_kernel(const float* __restrict__ x,
                           const float* __restrict__ mk,
                           const float* __restrict__ mv,
                           const float* __restrict__ mr) {
    int i = blockIdx.x * blockDim.x + threadIdx.x;
    if (i >= MTOT * HIDDEN / 4) return;
    int idx = i * 4;
    int h = idx & (HIDDEN - 1);
    int t = (idx / HIDDEN) & (SEQ - 1);

    float4 xc = *reinterpret_cast<const float4*>(x + idx);
    float4 xp = (t == 0) ? make_float4(0.f, 0.f, 0.f, 0.f)
                         : *reinterpret_cast<const float4*>(x + idx - HIDDEN);
    float4 k4 = *reinterpret_cast<const float4*>(mk + h);
    float4 v4 = *reinterpret_cast<const float4*>(mv + h);
    float4 r4 = *reinterpret_cast<const float4*>(mr + h);

    float xcf[4] = {xc.x, xc.y, xc.z, xc.w};
    float xpf[4] = {xp.x, xp.y, xp.z, xp.w};
    float kf[4] = {k4.x, k4.y, k4.z, k4.w};
    float vf[4] = {v4.x, v4.y, v4.z, v4.w};
    float rf[4] = {r4.x, r4.y, r4.z, r4.w};
    float ok[4], ov[4], orr[4];
#pragma unroll
    for (int j = 0; j < 4; j++) {
        ok[j]  = xcf[j] * kf[j] + xpf[j] * (1.f - kf[j]);
        ov[j]  = xcf[j] * vf[j] + xpf[j] * (1.f - vf[j]);
        orr[j] = xcf[j] * rf[j] + xpf[j] * (1.f - rf[j]);
    }
    __nv_bfloat16 bh[4], bl[4];
#pragma unroll
    for (int j = 0; j < 4; j++) split1(ok[j], &bh[j], &bl[j]);
    *reinterpret_cast<uint2*>(g_xkh + idx) = *reinterpret_cast<uint2*>(bh);
    *reinterpret_cast<uint2*>(g_xkl + idx) = *reinterpret_cast<uint2*>(bl);
#pragma unroll
    for (int j = 0; j < 4; j++) split1(ov[j], &bh[j], &bl[j]);
    *reinterpret_cast<uint2*>(g_xvh + idx) = *reinterpret_cast<uint2*>(bh);
    *reinterpret_cast<uint2*>(g_xvl + idx) = *reinterpret_cast<uint2*>(bl);
#pragma unroll
    for (int j = 0; j < 4; j++) split1(orr[j], &bh[j], &bl[j]);
    *reinterpret_cast<uint2*>(g_xrh + idx) = *reinterpret_cast<uint2*>(bh);
    *reinterpret_cast<uint2*>(g_xrl + idx) = *reinterpret_cast<uint2*>(bl);
}

__global__ void wsplit(const float* __restrict__ W,
                       __nv_bfloat16* __restrict__ h, __nv_bfloat16* __restrict__ l) {
    int i = blockIdx.x * blockDim.x + threadIdx.x;
    if (i >= HIDDEN * HIDDEN) return;
    split1(W[i], &h[i], &l[i]);
}

// ---------------------------------------------------------------------------
// 2) bf16 mma.sync GEMM, 3-term split. C[M,N] = A[M,K] * W[N,K]^T (fp32 out).
//    BM=BN=128, BK=32, 256 threads (8 warps, 2x4), warp tile 64x32.
//    2 CTAs/SM target.
// ---------------------------------------------------------------------------
template <bool SIGMOID>
__global__ __launch_bounds__(256, 2)
void gemm_mma(const __nv_bfloat16* __restrict__ Ahg, const __nv_bfloat16* __restrict__ Alg,
              const __nv_bfloat16* __restrict__ Bhg, const __nv_bfloat16* __restrict__ Blg,
              float* __restrict__ C) {
    extern __shared__ __align__(128) char smem[];

    const int tid = threadIdx.x;
    const int wid = tid >> 5;
    const int lane = tid & 31;
    const int wm = wid >> 2;        // 0..1
    const int wn = wid & 3;         // 0..3
    const int gr = lane >> 2;       // 0..7
    const int tg = (lane & 3) * 2;  // 0,2,4,6
    const int bm = blockIdx.y * BM;
    const int bn = blockIdx.x * BN;
    const uint32_t sbase = smem_u32(smem);

    // per-stage loader: 512 16B-chunks per array pair; 2 chunks/thread/array
    auto load_stage = [&](int c, int stg) {
        const uint32_t sb = sbase + stg * STAGE_BYTES;
        const int k0 = c * BK;
#pragma unroll
        for (int i = 0; i < 2; i++) {
            int u = tid + i * 256;          // 0..511
            int row = u >> 2;               // 0..127
            int ch = u & 3;                 // 0..3 (8 bf16 per chunk)
            uint32_t so = row * 80 + ch * 16;
            size_t ga = (size_t)(bm + row) * HIDDEN + k0 + ch * 8;
            size_t gb = (size_t)(bn + row) * HIDDEN + k0 + ch * 8;
            cp16(sb + AH_OFF + so, Ahg + ga);
            cp16(sb + AL_OFF + so, Alg + ga);
            cp16(sb + BH_OFF + so, Bhg + gb);
            cp16(sb + BL_OFF + so, Blg + gb);
        }
        asm volatile("cp.async.commit_group;" ::: "memory");
    };

    float acc[4][4][4];
#pragma unroll
    for (int i = 0; i < 4; i++)
#pragma unroll
        for (int j = 0; j < 4; j++)
#pragma unroll
            for (int q = 0; q < 4; q++) acc[i][j][q] = 0.f;

    load_stage(0, 0);
    load_stage(1, 1);

#pragma unroll 1
    for (int c = 0; c < KITER; c++) {
        const int s = c & 1;
        if (c < KITER - 1)
            asm volatile("cp.async.wait_group 1;" ::: "memory");
        else
            asm volatile("cp.async.wait_group 0;" ::: "memory");
        __syncthreads();

        const char* stg = smem + s * STAGE_BYTES;
        const __nv_bfloat16* Ah = (const __nv_bfloat16*)(stg + AH_OFF);
        const __nv_bfloat16* Al = (const __nv_bfloat16*)(stg + AL_OFF);
        const __nv_bfloat16* Bh = (const __nv_bfloat16*)(stg + BH_OFF);
        const __nv_bfloat16* Bl = (const __nv_bfloat16*)(stg + BL_OFF);

#pragma unroll
        for (int ks = 0; ks < 2; ks++) {
            const int kb = ks * 16;
            // B fragments for this k-step (held across m-tiles)
            uint32_t bhf[4][2], blf[4][2];
#pragma unroll
            for (int nf = 0; nf < 4; nf++) {
                int n = wn * 32 + nf * 8 + gr;
                bhf[nf][0] = *(const uint32_t*)(Bh + n * APITCH + kb + tg);
                bhf[nf][1] = *(const uint32_t*)(Bh + n * APITCH + kb + tg + 8);
                blf[nf][0] = *(const uint32_t*)(Bl + n * APITCH + kb + tg);
                blf[nf][1] = *(const uint32_t*)(Bl + n * APITCH + kb + tg + 8);
            }
#pragma unroll
            for (int mf = 0; mf < 4; mf++) {
                int r = wm * 64 + mf * 16 + gr;
                uint32_t ahf[4], alf[4];
                ahf[0] = *(const uint32_t*)(Ah + r * APITCH + kb + tg);
                ahf[1] = *(const uint32_t*)(Ah + (r + 8) * APITCH + kb + tg);
                ahf[2] = *(const uint32_t*)(Ah + r * APITCH + kb + tg + 8);
                ahf[3] = *(const uint32_t*)(Ah + (r + 8) * APITCH + kb + tg + 8);
                alf[0] = *(const uint32_t*)(Al + r * APITCH + kb + tg);
                alf[1] = *(const uint32_t*)(Al + (r + 8) * APITCH + kb + tg);
                alf[2] = *(const uint32_t*)(Al + r * APITCH + kb + tg + 8);
                alf[3] = *(const uint32_t*)(Al + (r + 8) * APITCH + kb + tg + 8);
#pragma unroll
                for (int nf = 0; nf < 4; nf++) {
                    MMA_BF16(acc[mf][nf], ahf, bhf[nf]);
                    MMA_BF16(acc[mf][nf], ahf, blf[nf]);
                    MMA_BF16(acc[mf][nf], alf, bhf[nf]);
                }
            }
        }
        __syncthreads();
        if (c + 2 < KITER) load_stage(c + 2, s);
    }

    // epilogue
#pragma unroll
    for (int mf = 0; mf < 4; mf++) {
        int r0 = bm + wm * 64 + mf * 16 + gr;
#pragma unroll
        for (int nf = 0; nf < 4; nf++) {
            int cc = bn + wn * 32 + nf * 8 + tg;
            float c0 = acc[mf][nf][0], c1 = acc[mf][nf][1];
            float c2 = acc[mf][nf][2], c3 = acc[mf][nf][3];
            if (SIGMOID) {
                c0 = 1.f / (1.f + __expf(-c0));
                c1 = 1.f / (1.f + __expf(-c1));
                c2 = 1.f / (1.f + __expf(-c2));
                c3 = 1.f / (1.f + __expf(-c3));
            }
            *reinterpret_cast<float2*>(C + (size_t)r0 * HIDDEN + cc) = make_float2(c0, c1);
            *reinterpret_cast<float2*>(C + (size_t)(r0 + 8) * HIDDEN + cc) = make_float2(c2, c3);
        }
    }
}

// ---------------------------------------------------------------------------
// 3) Chunk-parallel WKV scan
// ---------------------------------------------------------------------------
__global__ void wkv_phase1(const float* __restrict__ td) {
    int idx = blockIdx.x * blockDim.x + threadIdx.x;
    if (idx >= CH * NCHUNK) return;
    int h = idx & (HIDDEN - 1);
    int bc = idx >> 10;
    int c = bc & (NCHUNK - 1);
    int b = bc >> 4;

    const float w = td[h];
    const size_t base = ((size_t)b * SEQ + (size_t)c * LCHUNK) * HIDDEN + h;
    const float* kp = g_k + base;
    const float* vp = g_v + base;

    float aa = 0.f, bb = 0.f, pp = NEG_INF;
#pragma unroll 4
    for (int t = 0; t < LCHUNK; t++) {
        float k = kp[(size_t)t * HIDDEN];
        float v = vp[(size_t)t * HIDDEN];
        float ww2 = w + pp;
        float p2 = fmaxf(ww2, k);
        float e1 = __expf(ww2 - p2);
        float e2 = __expf(k - p2);
        aa = e1 * aa + e2 * v;
        bb = e1 * bb + e2;
        pp = p2;
    }
    g_saa[idx] = aa;
    g_sbb[idx] = bb;
    g_spp[idx] = pp;
}

__global__ void wkv_phase2(const float* __restrict__ td) {
    int idx = blockIdx.x * blockDim.x + threadIdx.x;
    if (idx >= CH) return;
    int h = idx & (HIDDEN - 1);
    int b = idx >> 10;
    const float wl = td[h] * (float)LCHUNK;

    float aa = 0.f, bb = 0.f, pp = NEG_INF;
#pragma unroll
    for (int c = 0; c < NCHUNK; c++) {
        int s = (b * NCHUNK + c) * HIDDEN + h;
        g_iaa[s] = aa;
        g_ibb[s] = bb;
        g_ipp[s] = pp;
        float laa = g_saa[s], lbb = g_sbb[s], lpp = g_spp[s];
        float sp = pp + wl;
        float p = fmaxf(sp, lpp);
        float e1 = __expf(sp - p);
        float e2 = __expf(lpp - p);
        aa = e1 * aa + e2 * laa;
        bb = e1 * bb + e2 * lbb;
        pp = p;
    }
}

__global__ void wkv_phase3(const float* __restrict__ td,
                           const float* __restrict__ tf) {
    int idx = blockIdx.x * blockDim.x + threadIdx.x;
    if (idx >= CH * NCHUNK) return;
    int h = idx & (HIDDEN - 1);
    int bc = idx >> 10;
    int c = bc & (NCHUNK - 1);
    int b = bc >> 4;

    const float w = td[h];
    const float u = tf[h];
    const size_t base = ((size_t)b * SEQ + (size_t)c * LCHUNK) * HIDDEN + h;
    const float* kp = g_k + base;
    const float* vp = g_v + base;
    const float* rp = g_r + base;

    float aa = g_iaa[idx], bb = g_ibb[idx], pp = g_ipp[idx];

#pragma unroll 4
    for (int t = 0; t < LCHUNK; t++) {
        size_t off = (size_t)t * HIDDEN;
        float k = kp[off];
        float v = vp[off];

        float ww = u + k;
        float p = fmaxf(pp, ww);
        float e1 = __expf(pp - p);
        float e2 = __expf(ww - p);
        float wkv = (e1 * aa + e2 * v) / (e1 * bb + e2 + 1e-9f);
        float o = rp[off] * wkv;
        __nv_bfloat16 hh, ll;
        split1(o, &hh, &ll);
        g_oh[base + off] = hh;
        g_ol[base + off] = ll;

        float ww2 = w + pp;
        float p2 = fmaxf(ww2, k);
        float e1b = __expf(ww2 - p2);
        float e2b = __expf(k - p2);
        aa = e1b * aa + e2b * v;
        bb = e1b * bb + e2b;
        pp = p2;
    }
}

// ---------------------------------------------------------------------------
// Launch
// ---------------------------------------------------------------------------
extern "C" void kernel_launch(void* const* d_in, const int* in_sizes, int n_in,
                              void* d_out, int out_size) {
    const float* x  = (const float*)d_in[0];
    const float* td = (const float*)d_in[1];
    const float* tf = (const float*)d_in[2];
    const float* mk = (const float*)d_in[3];
    const float* mv = (const float*)d_in[4];
    const float* mr = (const float*)d_in[5];
    const float* Wk = (const float*)d_in[6];
    const float* Wv = (const float*)d_in[7];
    const float* Wr = (const float*)d_in[8];
    const float* Wo = (const float*)d_in[9];
    float* out = (float*)d_out;

    __nv_bfloat16 *xkh, *xkl, *xvh, *xvl, *xrh, *xrl, *oh, *ol;
    __nv_bfloat16 *wkh, *wkl, *wvh, *wvl, *wrh, *wrl, *woh, *wol;
    float *kf, *vf, *rf;
    cudaGetSymbolAddress((void**)&xkh, g_xkh);
    cudaGetSymbolAddress((void**)&xkl, g_xkl);
    cudaGetSymbolAddress((void**)&xvh, g_xvh);
    cudaGetSymbolAddress((void**)&xvl, g_xvl);
    cudaGetSymbolAddress((void**)&xrh, g_xrh);
    cudaGetSymbolAddress((void**)&xrl, g_xrl);
    cudaGetSymbolAddress((void**)&oh, g_oh);
    cudaGetSymbolAddress((void**)&ol, g_ol);
    cudaGetSymbolAddress((void**)&wkh, g_Wkh);
    cudaGetSymbolAddress((void**)&wkl, g_Wkl);
    cudaGetSymbolAddress((void**)&wvh, g_Wvh);
    cudaGetSymbolAddress((void**)&wvl, g_Wvl);
    cudaGetSymbolAddress((void**)&wrh, g_Wrh);
    cudaGetSymbolAddress((void**)&wrl, g_Wrl);
    cudaGetSymbolAddress((void**)&woh, g_Woh);
    cudaGetSymbolAddress((void**)&wol, g_Wol);
    cudaGetSymbolAddress((void**)&kf, g_k);
    cudaGetSymbolAddress((void**)&vf, g_v);
    cudaGetSymbolAddress((void**)&rf, g_r);

    cudaFuncSetAttribute(gemm_mma<false>, cudaFuncAttributeMaxDynamicSharedMemorySize, SMEM_TOTAL);
    cudaFuncSetAttribute(gemm_mma<true>,  cudaFuncAttributeMaxDynamicSharedMemorySize, SMEM_TOTAL);

    // 1) time-mix + split
    {
        int n4 = MTOT * HIDDEN / 4;
        mix_kernel<<<(n4 + 255) / 256, 256>>>(x, mk, mv, mr);
    }
    // weight splits
    {
        int n = HIDDEN * HIDDEN;
        int g = (n + 255) / 256;
        wsplit<<<g, 256>>>(Wk, wkh, wkl);
        wsplit<<<g, 256>>>(Wv, wvh, wvl);
        wsplit<<<g, 256>>>(Wr, wrh, wrl);
        wsplit<<<g, 256>>>(Wo, woh, wol);
    }

    // 2) projections
    dim3 ggrid(HIDDEN / BN, MTOT / BM);   // (8, 128)
    gemm_mma<false><<<ggrid, 256, SMEM_TOTAL>>>(xkh, xkl, wkh, wkl, kf);
    gemm_mma<false><<<ggrid, 256, SMEM_TOTAL>>>(xvh, xvl, wvh, wvl, vf);
    gemm_mma<true ><<<ggrid, 256, SMEM_TOTAL>>>(xrh, xrl, wrh, wrl, rf);

    // 3) chunk-parallel wkv (writes bf16-split r*wkv)
    wkv_phase1<<<(CH * NCHUNK + 255) / 256, 256>>>(td);
    wkv_phase2<<<(CH + 255) / 256, 256>>>(td);
    wkv_phase3<<<(CH * NCHUNK + 255) / 256, 256>>>(td, tf);

    // 4) output projection
    gemm_mma<false><<<ggrid, 256, SMEM_TOTAL>>>(oh, ol, woh, wol, out);
}

// round 5
// speedup vs baseline: 4.3392x; 1.1227x over previous
#include <cuda_runtime.h>
#include <cuda_bf16.h>
#include <cstdint>

#define HIDDEN 1024
#define BATCH 8
#define SEQ 2048
#define MTOT (BATCH * SEQ)          // 16384 rows
#define NEG_INF -1e38f
#define CH (BATCH * HIDDEN)         // 8192 channels
#define LCHUNK 128
#define NCHUNK (SEQ / LCHUNK)       // 16

// GEMM tiling (legacy mma.sync bf16 m16n8k16)
#define BM 128
#define BN 128
#define BK 32
#define KITER (HIDDEN / BK)         // 32
#define APITCH 40                   // 32 + 8 pad (bf16 elems) -> 80B row pitch
#define TILE_BYTES (BM * APITCH * 2)        // 10240
#define AH_OFF 0
#define AL_OFF TILE_BYTES
#define BH_OFF (2 * TILE_BYTES)
#define BL_OFF (3 * TILE_BYTES)
#define STAGE_BYTES (4 * TILE_BYTES)        // 40960
#define SMEM_TOTAL (2 * STAGE_BYTES)        // 81920

// ---------------------------------------------------------------------------
// Scratch (device globals)
// ---------------------------------------------------------------------------
__device__ __nv_bfloat16 g_xkh[MTOT * HIDDEN];
__device__ __nv_bfloat16 g_xkl[MTOT * HIDDEN];
__device__ __nv_bfloat16 g_xvh[MTOT * HIDDEN];
__device__ __nv_bfloat16 g_xvl[MTOT * HIDDEN];
__device__ __nv_bfloat16 g_xrh[MTOT * HIDDEN];
__device__ __nv_bfloat16 g_xrl[MTOT * HIDDEN];
__device__ __nv_bfloat16 g_oh [MTOT * HIDDEN];
__device__ __nv_bfloat16 g_ol [MTOT * HIDDEN];

__device__ __nv_bfloat16 g_Wkh[HIDDEN * HIDDEN];
__device__ __nv_bfloat16 g_Wkl[HIDDEN * HIDDEN];
__device__ __nv_bfloat16 g_Wvh[HIDDEN * HIDDEN];
__device__ __nv_bfloat16 g_Wvl[HIDDEN * HIDDEN];
__device__ __nv_bfloat16 g_Wrh[HIDDEN * HIDDEN];
__device__ __nv_bfloat16 g_Wrl[HIDDEN * HIDDEN];
__device__ __nv_bfloat16 g_Woh[HIDDEN * HIDDEN];
__device__ __nv_bfloat16 g_Wol[HIDDEN * HIDDEN];

__device__ float g_k[MTOT * HIDDEN];
__device__ float g_v[MTOT * HIDDEN];
__device__ float g_r[MTOT * HIDDEN];

__device__ float g_saa[CH * NCHUNK];
__device__ float g_sbb[CH * NCHUNK];
__device__ float g_spp[CH * NCHUNK];
__device__ float g_iaa[CH * NCHUNK];
__device__ float g_ibb[CH * NCHUNK];
__device__ float g_ipp[CH * NCHUNK];

// ---------------------------------------------------------------------------
// Helpers
// ---------------------------------------------------------------------------
__device__ __forceinline__ uint32_t smem_u32(const void* p) {
    uint32_t a;
    asm("{ .reg .u64 t; cvta.to.shared.u64 t, %1; cvt.u32.u64 %0, t; }"
        : "=r"(a) : "l"(p));
    return a;
}

__device__ __forceinline__ void cp16(uint32_t s, const void* g) {
    asm volatile("cp.async.cg.shared.global [%0], [%1], 16;" :: "r"(s), "l"(g));
}

__device__ __forceinline__ void split1(float a, __nv_bfloat16* h, __nv_bfloat16* l) {
    __nv_bfloat16 hh = __float2bfloat16(a);
    *h = hh;
    *l = __float2bfloat16(a - __bfloat162float(hh));
}

#define MMA_BF16(c, a, b)                                                     \
    asm volatile(                                                             \
        "mma.sync.aligned.m16n8k16.row.col.f32.bf16.bf16.f32 "                \
        "{%0,%1,%2,%3},{%4,%5,%6,%7},{%8,%9},{%0,%1,%2,%3};"                  \
        : "+f"((c)[0]), "+f"((c)[1]), "+f"((c)[2]), "+f"((c)[3])              \
        : "r"((a)[0]), "r"((a)[1]), "r"((a)[2]), "r"((a)[3]),                 \
          "r"((b)[0]), "r"((b)[1]))

#define LDMATRIX_X4(r0, r1, r2, r3, addr)                                     \
    asm volatile(                                                             \
        "ldmatrix.sync.aligned.m8n8.x4.shared.b16 {%0,%1,%2,%3}, [%4];"       \
        : "=r"(r0), "=r"(r1), "=r"(r2), "=r"(r3) : "r"(addr))

// ---------------------------------------------------------------------------
// 1) Time-mix + bf16 hi/lo split
// ---------------------------------------------------------------------------
__global__ void mix_kernel(const float* __restrict__ x,
                           const float* __restrict__ mk,
                           const float* __restrict__ mv,
                           const float* __restrict__ mr) {
    int i = blockIdx.x * blockDim.x + threadIdx.x;
    if (i >= MTOT * HIDDEN / 4) return;
    int idx = i * 4;
    int h = idx & (HIDDEN - 1);
    int t = (idx / HIDDEN) & (SEQ - 1);

    float4 xc = *reinterpret_cast<const float4*>(x + idx);
    float4 xp = (t == 0) ? make_float4(0.f, 0.f, 0.f, 0.f)
                         : *reinterpret_cast<const float4*>(x + idx - HIDDEN);
    float4 k4 = *reinterpret_cast<const float4*>(mk + h);
    float4 v4 = *reinterpret_cast<const float4*>(mv + h);
    float4 r4 = *reinterpret_cast<const float4*>(mr + h);

    float xcf[4] = {xc.x, xc.y, xc.z, xc.w};
    float xpf[4] = {xp.x, xp.y, xp.z, xp.w};
    float kf[4] = {k4.x, k4.y, k4.z, k4.w};
    float vf[4] = {v4.x, v4.y, v4.z, v4.w};
    float rf[4] = {r4.x, r4.y, r4.z, r4.w};
    float ok[4], ov[4], orr[4];
#pragma unroll
    for (int j = 0; j < 4; j++) {
        ok[j]  = xcf[j] * kf[j] + xpf[j] * (1.f - kf[j]);
        ov[j]  = xcf[j] * vf[j] + xpf[j] * (1.f - vf[j]);
        orr[j] = xcf[j] * rf[j] + xpf[j] * (1.f - rf[j]);
    }
    __nv_bfloat16 bh[4], bl[4];
#pragma unroll
    for (int j = 0; j < 4; j++) split1(ok[j], &bh[j], &bl[j]);
    *reinterpret_cast<uint2*>(g_xkh + idx) = *reinterpret_cast<uint2*>(bh);
    *reinterpret_cast<uint2*>(g_xkl + idx) = *reinterpret_cast<uint2*>(bl);
#pragma unroll
    for (int j = 0; j < 4; j++) split1(ov[j], &bh[j], &bl[j]);
    *reinterpret_cast<uint2*>(g_xvh + idx) = *reinterpret_cast<uint2*>(bh);
    *reinterpret_cast<uint2*>(g_xvl + idx) = *reinterpret_cast<uint2*>(bl);
#pragma unroll
    for (int j = 0; j < 4; j++) split1(orr[j], &bh[j], &bl[j]);
    *reinterpret_cast<uint2*>(g_xrh + idx) = *reinterpret_cast<uint2*>(bh);
    *reinterpret_cast<uint2*>(g_xrl + idx) = *reinterpret_cast<uint2*>(bl);
}

// All 4 weight splits in one launch; float4 vectorized.
// 4 * 1M elems / 4 per thread = 1,048,576 threads; sel = i >> 18.
__global__ void wsplit_all(const float* __restrict__ W0, const float* __restrict__ W1,
                           const float* __restrict__ W2, const float* __restrict__ W3,
                           __nv_bfloat16* __restrict__ h0, __nv_bfloat16* __restrict__ l0,
                           __nv_bfloat16* __restrict__ h1, __nv_bfloat16* __restrict__ l1,
                           __nv_bfloat16* __restrict__ h2, __nv_bfloat16* __restrict__ l2,
                           __nv_bfloat16* __restrict__ h3, __nv_bfloat16* __restrict__ l3) {
    int i = blockIdx.x * blockDim.x + threadIdx.x;
    if (i >= 4 * HIDDEN * HIDDEN / 4) return;
    int sel = i >> 18;
    int off = (i & 0x3FFFF) * 4;
    const float* W; __nv_bfloat16 *h, *l;
    switch (sel) {
        case 0: W = W0; h = h0; l = l0; break;
        case 1: W = W1; h = h1; l = l1; break;
        case 2: W = W2; h = h2; l = l2; break;
        default: W = W3; h = h3; l = l3; break;
    }
    float4 w = *reinterpret_cast<const float4*>(W + off);
    float wf[4] = {w.x, w.y, w.z, w.w};
    __nv_bfloat16 bh[4], bl[4];
#pragma unroll
    for (int j = 0; j < 4; j++) split1(wf[j], &bh[j], &bl[j]);
    *reinterpret_cast<uint2*>(h + off) = *reinterpret_cast<uint2*>(bh);
    *reinterpret_cast<uint2*>(l + off) = *reinterpret_cast<uint2*>(bl);
}

// ---------------------------------------------------------------------------
// 2) bf16 mma.sync GEMM with ldmatrix fragment loads.
//    C[M,N] = A[M,K] * W[N,K]^T, 3-term hi/lo split, fp32 out.
//    BM=BN=128, BK=32, 256 threads (8 warps 2x4), warp tile 64x32, 2 CTA/SM.
//    FUSED=true: blockIdx.z selects (xk,Wk)->k / (xv,Wv)->v / (xr,Wr,sigmoid)->r
// ---------------------------------------------------------------------------
template <bool FUSED>
__global__ __launch_bounds__(256, 2)
void gemm_mma(const __nv_bfloat16* __restrict__ Ahg, const __nv_bfloat16* __restrict__ Alg,
              const __nv_bfloat16* __restrict__ Bhg, const __nv_bfloat16* __restrict__ Blg,
              float* __restrict__ C) {
    extern __shared__ __align__(128) char smem[];

    bool sigmoid = false;
    if (FUSED) {
        int z = blockIdx.z;
        if (z == 0)      { Ahg = g_xkh; Alg = g_xkl; Bhg = g_Wkh; Blg = g_Wkl; C = g_k; }
        else if (z == 1) { Ahg = g_xvh; Alg = g_xvl; Bhg = g_Wvh; Blg = g_Wvl; C = g_v; }
        else             { Ahg = g_xrh; Alg = g_xrl; Bhg = g_Wrh; Blg = g_Wrl; C = g_r; sigmoid = true; }
    }

    const int tid = threadIdx.x;
    const int wid = tid >> 5;
    const int lane = tid & 31;
    const int wm = wid >> 2;        // 0..1
    const int wn = wid & 3;         // 0..3
    const int gr = lane >> 2;       // 0..7
    const int tg = (lane & 3) * 2;  // 0,2,4,6
    const int bm = blockIdx.y * BM;
    const int bn = blockIdx.x * BN;
    const uint32_t sbase = smem_u32(smem);

    // ldmatrix per-thread address components
    const int a_row = lane & 15;            // row within 16-row tile
    const int a_k8  = (lane >> 4) * 8;      // 0 or 8 (k offset)
    const int b_row = (lane & 7) + ((lane >> 4) & 1) * 8;  // row within 16-n tile
    const int b_k8  = ((lane >> 3) & 1) * 8;               // 0 or 8

    auto load_stage = [&](int c, int stg) {
        const uint32_t sb = sbase + stg * STAGE_BYTES;
        const int k0 = c * BK;
#pragma unroll
        for (int i = 0; i < 2; i++) {
            int u = tid + i * 256;          // 0..511
            int row = u >> 2;               // 0..127
            int ch = u & 3;                 // 0..3
            uint32_t so = row * 80 + ch * 16;
            size_t ga = (size_t)(bm + row) * HIDDEN + k0 + ch * 8;
            size_t gb = (size_t)(bn + row) * HIDDEN + k0 + ch * 8;
            cp16(sb + AH_OFF + so, Ahg + ga);
            cp16(sb + AL_OFF + so, Alg + ga);
            cp16(sb + BH_OFF + so, Bhg + gb);
            cp16(sb + BL_OFF + so, Blg + gb);
        }
        asm volatile("cp.async.commit_group;" ::: "memory");
    };

    float acc[4][4][4];
#pragma unroll
    for (int i = 0; i < 4; i++)
#pragma unroll
        for (int j = 0; j < 4; j++)
#pragma unroll
            for (int q = 0; q < 4; q++) acc[i][j][q] = 0.f;

    load_stage(0, 0);
    load_stage(1, 1);

#pragma unroll 1
    for (int c = 0; c < KITER; c++) {
        const int s = c & 1;
        if (c < KITER - 1)
            asm volatile("cp.async.wait_group 1;" ::: "memory");
        else
            asm volatile("cp.async.wait_group 0;" ::: "memory");
        __syncthreads();

        const uint32_t sb = sbase + s * STAGE_BYTES;

#pragma unroll
        for (int ks = 0; ks < 2; ks++) {
            const int kb = ks * 16;
            // B fragments: 2 ldmatrix.x4 per hi/lo (covers 4 n-frags of 8)
            uint32_t bhf[4][2], blf[4][2];
#pragma unroll
            for (int np = 0; np < 2; np++) {
                int n0 = wn * 32 + np * 16;
                uint32_t ro = (uint32_t)(n0 + b_row) * 80 + (kb + b_k8) * 2;
                LDMATRIX_X4(bhf[np * 2][0], bhf[np * 2][1],
                            bhf[np * 2 + 1][0], bhf[np * 2 + 1][1], sb + BH_OFF + ro);
                LDMATRIX_X4(blf[np * 2][0], blf[np * 2][1],
                            blf[np * 2 + 1][0], blf[np * 2 + 1][1], sb + BL_OFF + ro);
            }
#pragma unroll
            for (int mf = 0; mf < 4; mf++) {
                int r0 = wm * 64 + mf * 16;
                uint32_t ro = (uint32_t)(r0 + a_row) * 80 + (kb + a_k8) * 2;
                uint32_t ahf[4], alf[4];
                LDMATRIX_X4(ahf[0], ahf[1], ahf[2], ahf[3], sb + AH_OFF + ro);
                LDMATRIX_X4(alf[0], alf[1], alf[2], alf[3], sb + AL_OFF + ro);
#pragma unroll
                for (int nf = 0; nf < 4; nf++) {
                    MMA_BF16(acc[mf][nf], ahf, bhf[nf]);
                    MMA_BF16(acc[mf][nf], ahf, blf[nf]);
                    MMA_BF16(acc[mf][nf], alf, bhf[nf]);
                }
            }
        }
        __syncthreads();
        if (c + 2 < KITER) load_stage(c + 2, s);
    }

    // epilogue
#pragma unroll
    for (int mf = 0; mf < 4; mf++) {
        int r0 = bm + wm * 64 + mf * 16 + gr;
#pragma unroll
        for (int nf = 0; nf < 4; nf++) {
            int cc = bn + wn * 32 + nf * 8 + tg;
            float c0 = acc[mf][nf][0], c1 = acc[mf][nf][1];
            float c2 = acc[mf][nf][2], c3 = acc[mf][nf][3];
            if (FUSED && sigmoid) {
                c0 = 1.f / (1.f + __expf(-c0));
                c1 = 1.f / (1.f + __expf(-c1));
                c2 = 1.f / (1.f + __expf(-c2));
                c3 = 1.f / (1.f + __expf(-c3));
            }
            *reinterpret_cast<float2*>(C + (size_t)r0 * HIDDEN + cc) = make_float2(c0, c1);
            *reinterpret_cast<float2*>(C + (size_t)(r0 + 8) * HIDDEN + cc) = make_float2(c2, c3);
        }
    }
}

// ---------------------------------------------------------------------------
// 3) Chunk-parallel WKV scan
// ---------------------------------------------------------------------------
__global__ void wkv_phase1(const float* __restrict__ td) {
    int idx = blockIdx.x * blockDim.x + threadIdx.x;
    if (idx >= CH * NCHUNK) return;
    int h = idx & (HIDDEN - 1);
    int bc = idx >> 10;
    int c = bc & (NCHUNK - 1);
    int b = bc >> 4;

    const float w = td[h];
    const size_t base = ((size_t)b * SEQ + (size_t)c * LCHUNK) * HIDDEN + h;
    const float* kp = g_k + base;
    const float* vp = g_v + base;

    float aa = 0.f, bb = 0.f, pp = NEG_INF;
#pragma unroll 4
    for (int t = 0; t < LCHUNK; t++) {
        float k = kp[(size_t)t * HIDDEN];
        float v = vp[(size_t)t * HIDDEN];
        float ww2 = w + pp;
        float p2 = fmaxf(ww2, k);
        float e1 = __expf(ww2 - p2);
        float e2 = __expf(k - p2);
        aa = e1 * aa + e2 * v;
        bb = e1 * bb + e2;
        pp = p2;
    }
    g_saa[idx] = aa;
    g_sbb[idx] = bb;
    g_spp[idx] = pp;
}

__global__ void wkv_phase2(const float* __restrict__ td) {
    int idx = blockIdx.x * blockDim.x + threadIdx.x;
    if (idx >= CH) return;
    int h = idx & (HIDDEN - 1);
    int b = idx >> 10;
    const float wl = td[h] * (float)LCHUNK;

    float aa = 0.f, bb = 0.f, pp = NEG_INF;
#pragma unroll
    for (int c = 0; c < NCHUNK; c++) {
        int s = (b * NCHUNK + c) * HIDDEN + h;
        g_iaa[s] = aa;
        g_ibb[s] = bb;
        g_ipp[s] = pp;
        float laa = g_saa[s], lbb = g_sbb[s], lpp = g_spp[s];
        float sp = pp + wl;
        float p = fmaxf(sp, lpp);
        float e1 = __expf(sp - p);
        float e2 = __expf(lpp - p);
        aa = e1 * aa + e2 * laa;
        bb = e1 * bb + e2 * lbb;
        pp = p;
    }
}

__global__ void wkv_phase3(const float* __restrict__ td,
                           const float* __restrict__ tf) {
    int idx = blockIdx.x * blockDim.x + threadIdx.x;
    if (idx >= CH * NCHUNK) return;
    int h = idx & (HIDDEN - 1);
    int bc = idx >> 10;
    int c = bc & (NCHUNK - 1);
    int b = bc >> 4;

    const float w = td[h];
    const float u = tf[h];
    const size_t base = ((size_t)b * SEQ + (size_t)c * LCHUNK) * HIDDEN + h;
    const float* kp = g_k + base;
    const float* vp = g_v + base;
    const float* rp = g_r + base;

    float aa = g_iaa[idx], bb = g_ibb[idx], pp = g_ipp[idx];

#pragma unroll 4
    for (int t = 0; t < LCHUNK; t++) {
        size_t off = (size_t)t * HIDDEN;
        float k = kp[off];
        float v = vp[off];

        float ww = u + k;
        float p = fmaxf(pp, ww);
        float e1 = __expf(pp - p);
        float e2 = __expf(ww - p);
        float wkv = (e1 * aa + e2 * v) / (e1 * bb + e2 + 1e-9f);
        float o = rp[off] * wkv;
        __nv_bfloat16 hh, ll;
        split1(o, &hh, &ll);
        g_oh[base + off] = hh;
        g_ol[base + off] = ll;

        float ww2 = w + pp;
        float p2 = fmaxf(ww2, k);
        float e1b = __expf(ww2 - p2);
        float e2b = __expf(k - p2);
        aa = e1b * aa + e2b * v;
        bb = e1b * bb + e2b;
        pp = p2;
    }
}

// ---------------------------------------------------------------------------
// Launch
// ---------------------------------------------------------------------------
extern "C" void kernel_launch(void* const* d_in, const int* in_sizes, int n_in,
                              void* d_out, int out_size) {
    const float* x  = (const float*)d_in[0];
    const float* td = (const float*)d_in[1];
    const float* tf = (const float*)d_in[2];
    const float* mk = (const float*)d_in[3];
    const float* mv = (const float*)d_in[4];
    const float* mr = (const float*)d_in[5];
    const float* Wk = (const float*)d_in[6];
    const float* Wv = (const float*)d_in[7];
    const float* Wr = (const float*)d_in[8];
    const float* Wo = (const float*)d_in[9];
    float* out = (float*)d_out;

    __nv_bfloat16 *oh, *ol, *woh, *wol;
    __nv_bfloat16 *wkh, *wkl, *wvh, *wvl, *wrh, *wrl;
    cudaGetSymbolAddress((void**)&oh, g_oh);
    cudaGetSymbolAddress((void**)&ol, g_ol);
    cudaGetSymbolAddress((void**)&wkh, g_Wkh);
    cudaGetSymbolAddress((void**)&wkl, g_Wkl);
    cudaGetSymbolAddress((void**)&wvh, g_Wvh);
    cudaGetSymbolAddress((void**)&wvl, g_Wvl);
    cudaGetSymbolAddress((void**)&wrh, g_Wrh);
    cudaGetSymbolAddress((void**)&wrl, g_Wrl);
    cudaGetSymbolAddress((void**)&woh, g_Woh);
    cudaGetSymbolAddress((void**)&wol, g_Wol);

    cudaFuncSetAttribute(gemm_mma<true>,  cudaFuncAttributeMaxDynamicSharedMemorySize, SMEM_TOTAL);
    cudaFuncSetAttribute(gemm_mma<false>, cudaFuncAttributeMaxDynamicSharedMemorySize, SMEM_TOTAL);

    // 1) time-mix + split, and all weight splits in one launch
    {
        int n4 = MTOT * HIDDEN / 4;
        mix_kernel<<<(n4 + 255) / 256, 256>>>(x, mk, mv, mr);
        int nw = 4 * HIDDEN * HIDDEN / 4;
        wsplit_all<<<(nw + 255) / 256, 256>>>(Wk, Wv, Wr, Wo,
                                              wkh, wkl, wvh, wvl, wrh, wrl, woh, wol);
    }

    // 2) fused k/v/r projections: one launch, z selects operands
    dim3 ggrid(HIDDEN / BN, MTOT / BM, 3);   // (8, 128, 3)
    gemm_mma<true><<<ggrid, 256, SMEM_TOTAL>>>(nullptr, nullptr, nullptr, nullptr, nullptr);

    // 3) chunk-parallel wkv (writes bf16-split r*wkv)
    wkv_phase1<<<(CH * NCHUNK + 255) / 256, 256>>>(td);
    wkv_phase2<<<(CH + 255) / 256, 256>>>(td);
    wkv_phase3<<<(CH * NCHUNK + 255) / 256, 256>>>(td, tf);

    // 4) output projection
    dim3 ogrid(HIDDEN / BN, MTOT / BM, 1);
    gemm_mma<false><<<ogrid, 256, SMEM_TOTAL>>>(oh, ol, woh, wol, out);
}

// round 6
// speedup vs baseline: 5.7360x; 1.3219x over previous
#include <cuda_runtime.h>
#include <cuda_bf16.h>
#include <cstdint>

#define HIDDEN 1024
#define BATCH 8
#define SEQ 2048
#define MTOT (BATCH * SEQ)          // 16384 rows
#define NEG_INF -1e38f
#define CH (BATCH * HIDDEN)         // 8192 channels
#define LCHUNK 128
#define NCHUNK (SEQ / LCHUNK)       // 16
#define QMAXF 16256.0f              // 127 * 128

// GEMM tiling (imma m16n8k32, int8 2-limb)
#define BM 128
#define BN 128
#define BK 64                        // 64 int8 per row per stage
#define KITER (HIDDEN / BK)          // 16
#define PITCH 80                     // 64 + 16 pad bytes
#define TILE_BYTES (BM * PITCH)      // 10240
#define A1_OFF 0
#define A0_OFF TILE_BYTES
#define B1_OFF (2 * TILE_BYTES)
#define B0_OFF (3 * TILE_BYTES)
#define STAGE_BYTES (4 * TILE_BYTES) // 40960
#define NSTAGE 3
#define SMEM_TOTAL (NSTAGE * STAGE_BYTES)   // 122880

// ---------------------------------------------------------------------------
// Scratch (device globals)
// ---------------------------------------------------------------------------
__device__ __align__(16) int8_t g_xk1[MTOT * HIDDEN];
__device__ __align__(16) int8_t g_xk0[MTOT * HIDDEN];
__device__ __align__(16) int8_t g_xv1[MTOT * HIDDEN];
__device__ __align__(16) int8_t g_xv0[MTOT * HIDDEN];
__device__ __align__(16) int8_t g_xr1[MTOT * HIDDEN];
__device__ __align__(16) int8_t g_xr0[MTOT * HIDDEN];
__device__ __align__(16) int8_t g_o1 [MTOT * HIDDEN];
__device__ __align__(16) int8_t g_o0 [MTOT * HIDDEN];

__device__ __align__(16) int8_t g_Wk1[HIDDEN * HIDDEN];
__device__ __align__(16) int8_t g_Wk0[HIDDEN * HIDDEN];
__device__ __align__(16) int8_t g_Wv1[HIDDEN * HIDDEN];
__device__ __align__(16) int8_t g_Wv0[HIDDEN * HIDDEN];
__device__ __align__(16) int8_t g_Wr1[HIDDEN * HIDDEN];
__device__ __align__(16) int8_t g_Wr0[HIDDEN * HIDDEN];
__device__ __align__(16) int8_t g_Wo1[HIDDEN * HIDDEN];
__device__ __align__(16) int8_t g_Wo0[HIDDEN * HIDDEN];

__device__ float g_k[MTOT * HIDDEN];
__device__ float g_v[MTOT * HIDDEN];
__device__ float g_r[MTOT * HIDDEN];

__device__ float g_saa[CH * NCHUNK];
__device__ float g_sbb[CH * NCHUNK];
__device__ float g_spp[CH * NCHUNK];
__device__ float g_iaa[CH * NCHUNK];
__device__ float g_ibb[CH * NCHUNK];
__device__ float g_ipp[CH * NCHUNK];

// scale scalars (abs-max as uint bits; reset each invocation)
__device__ unsigned g_sxb;      // max|x|  -> bounds xk/xv/xr
__device__ unsigned g_swb[4];   // max|Wk|,|Wv|,|Wr|,|Wo|
__device__ unsigned g_svb;      // max|v|  -> bounds r*wkv

// ---------------------------------------------------------------------------
// Helpers
// ---------------------------------------------------------------------------
__device__ __forceinline__ uint32_t smem_u32(const void* p) {
    uint32_t a;
    asm("{ .reg .u64 t; cvta.to.shared.u64 t, %1; cvt.u32.u64 %0, t; }"
        : "=r"(a) : "l"(p));
    return a;
}

__device__ __forceinline__ void cp16(uint32_t s, const void* g) {
    asm volatile("cp.async.cg.shared.global [%0], [%1], 16;" :: "r"(s), "l"(g));
}

#define MMA_S8(c, a, b)                                                       \
    asm volatile(                                                             \
        "mma.sync.aligned.m16n8k32.row.col.s32.s8.s8.s32 "                    \
        "{%0,%1,%2,%3},{%4,%5,%6,%7},{%8,%9},{%0,%1,%2,%3};"                  \
        : "+r"((c)[0]), "+r"((c)[1]), "+r"((c)[2]), "+r"((c)[3])              \
        : "r"((a)[0]), "r"((a)[1]), "r"((a)[2]), "r"((a)[3]),                 \
          "r"((b)[0]), "r"((b)[1]))

#define LDMATRIX_X4(r0, r1, r2, r3, addr)                                     \
    asm volatile(                                                             \
        "ldmatrix.sync.aligned.m8n8.x4.shared.b16 {%0,%1,%2,%3}, [%4];"       \
        : "=r"(r0), "=r"(r1), "=r"(r2), "=r"(r3) : "r"(addr))

// quantize 4 floats -> two packed limb words (q1 = hi limb, q0 = lo limb)
__device__ __forceinline__ void quant4(const float* v, float inv,
                                       uint32_t& p1, uint32_t& p0) {
    uint32_t r1 = 0, r0 = 0;
#pragma unroll
    for (int j = 0; j < 4; j++) {
        float q = rintf(v[j] * inv);
        q = fminf(fmaxf(q, -QMAXF), QMAXF);
        float q1 = rintf(q * 0.0078125f);      // /128
        float q0 = q - 128.0f * q1;
        r1 |= ((uint32_t)(uint8_t)(int8_t)(int)q1) << (j * 8);
        r0 |= ((uint32_t)(uint8_t)(int8_t)(int)q0) << (j * 8);
    }
    p1 = r1; p0 = r0;
}

// ---------------------------------------------------------------------------
// 0) scale init + absmax
// ---------------------------------------------------------------------------
__global__ void init_scales() {
    if (threadIdx.x == 0) {
        g_sxb = 0; g_svb = 0;
        g_swb[0] = 0; g_swb[1] = 0; g_swb[2] = 0; g_swb[3] = 0;
    }
}

// blocks 0..4095: x (4096 elems each); then 256 blocks per weight
__global__ void absmax_all(const float* __restrict__ x,
                           const float* __restrict__ Wk, const float* __restrict__ Wv,
                           const float* __restrict__ Wr, const float* __restrict__ Wo) {
    __shared__ float sred[8];
    int blk = blockIdx.x;
    const float* base;
    unsigned* target;
    int rel;
    if (blk < 4096)      { base = x;  target = &g_sxb;    rel = blk; }
    else if (blk < 4352) { base = Wk; target = &g_swb[0]; rel = blk - 4096; }
    else if (blk < 4608) { base = Wv; target = &g_swb[1]; rel = blk - 4352; }
    else if (blk < 4864) { base = Wr; target = &g_swb[2]; rel = blk - 4608; }
    else                 { base = Wo; target = &g_swb[3]; rel = blk - 4864; }

    const float4* p = reinterpret_cast<const float4*>(base + (size_t)rel * 4096);
    float m = 0.f;
#pragma unroll
    for (int j = 0; j < 4; j++) {
        float4 v = p[threadIdx.x + j * 256];
        m = fmaxf(m, fmaxf(fmaxf(fabsf(v.x), fabsf(v.y)), fmaxf(fabsf(v.z), fabsf(v.w))));
    }
#pragma unroll
    for (int o = 16; o > 0; o >>= 1)
        m = fmaxf(m, __shfl_xor_sync(0xFFFFFFFF, m, o));
    if ((threadIdx.x & 31) == 0) sred[threadIdx.x >> 5] = m;
    __syncthreads();
    if (threadIdx.x < 8) {
        m = sred[threadIdx.x];
#pragma unroll
        for (int o = 4; o > 0; o >>= 1)
            m = fmaxf(m, __shfl_xor_sync(0xFF, m, o));
        if (threadIdx.x == 0) atomicMax(target, __float_as_uint(m));
    }
}

// ---------------------------------------------------------------------------
// 1) Time-mix + int8 limb quantization (scale = max|x| bound, exact)
// ---------------------------------------------------------------------------
__global__ void mix_quant(const float* __restrict__ x,
                          const float* __restrict__ mk,
                          const float* __restrict__ mv,
                          const float* __restrict__ mr) {
    int i = blockIdx.x * blockDim.x + threadIdx.x;
    if (i >= MTOT * HIDDEN / 4) return;
    int idx = i * 4;
    int h = idx & (HIDDEN - 1);
    int t = (idx / HIDDEN) & (SEQ - 1);

    float sx = __uint_as_float(g_sxb);
    float inv = (sx > 0.f) ? (QMAXF / sx) : 0.f;

    float4 xc = *reinterpret_cast<const float4*>(x + idx);
    float4 xp = (t == 0) ? make_float4(0.f, 0.f, 0.f, 0.f)
                         : *reinterpret_cast<const float4*>(x + idx - HIDDEN);
    float4 k4 = *reinterpret_cast<const float4*>(mk + h);
    float4 v4 = *reinterpret_cast<const float4*>(mv + h);
    float4 r4 = *reinterpret_cast<const float4*>(mr + h);

    float xcf[4] = {xc.x, xc.y, xc.z, xc.w};
    float xpf[4] = {xp.x, xp.y, xp.z, xp.w};
    float kf[4] = {k4.x, k4.y, k4.z, k4.w};
    float vf[4] = {v4.x, v4.y, v4.z, v4.w};
    float rf[4] = {r4.x, r4.y, r4.z, r4.w};
    float ok[4], ov[4], orr[4];
#pragma unroll
    for (int j = 0; j < 4; j++) {
        ok[j]  = xcf[j] * kf[j] + xpf[j] * (1.f - kf[j]);
        ov[j]  = xcf[j] * vf[j] + xpf[j] * (1.f - vf[j]);
        orr[j] = xcf[j] * rf[j] + xpf[j] * (1.f - rf[j]);
    }
    uint32_t p1, p0;
    quant4(ok, inv, p1, p0);
    *reinterpret_cast<uint32_t*>(g_xk1 + idx) = p1;
    *reinterpret_cast<uint32_t*>(g_xk0 + idx) = p0;
    quant4(ov, inv, p1, p0);
    *reinterpret_cast<uint32_t*>(g_xv1 + idx) = p1;
    *reinterpret_cast<uint32_t*>(g_xv0 + idx) = p0;
    quant4(orr, inv, p1, p0);
    *reinterpret_cast<uint32_t*>(g_xr1 + idx) = p1;
    *reinterpret_cast<uint32_t*>(g_xr0 + idx) = p0;
}

// all 4 weight quantizations in one launch
__global__ void wquant_all(const float* __restrict__ W0, const float* __restrict__ W1,
                           const float* __restrict__ W2, const float* __restrict__ W3) {
    int i = blockIdx.x * blockDim.x + threadIdx.x;
    if (i >= 4 * HIDDEN * HIDDEN / 4) return;
    int sel = i >> 18;
    int off = (i & 0x3FFFF) * 4;
    const float* W; int8_t *d1, *d0;
    switch (sel) {
        case 0: W = W0; d1 = g_Wk1; d0 = g_Wk0; break;
        case 1: W = W1; d1 = g_Wv1; d0 = g_Wv0; break;
        case 2: W = W2; d1 = g_Wr1; d0 = g_Wr0; break;
        default: W = W3; d1 = g_Wo1; d0 = g_Wo0; break;
    }
    float sw = __uint_as_float(g_swb[sel]);
    float inv = (sw > 0.f) ? (QMAXF / sw) : 0.f;
    float4 w = *reinterpret_cast<const float4*>(W + off);
    float wf[4] = {w.x, w.y, w.z, w.w};
    uint32_t p1, p0;
    quant4(wf, inv, p1, p0);
    *reinterpret_cast<uint32_t*>(d1 + off) = p1;
    *reinterpret_cast<uint32_t*>(d0 + off) = p0;
}

// ---------------------------------------------------------------------------
// 2) int8 IMMA GEMM, 2-limb. C[M,N] = A[M,K] * W[N,K]^T (fp32 out).
//    BM=BN=128, BK=64 bytes, 256 threads (8 warps 2x4), warp tile 64x32.
//    FUSED: z=0 k, z=1 v (+absmax of v), z=2 r (+sigmoid).
// ---------------------------------------------------------------------------
template <bool FUSED>
__global__ __launch_bounds__(256)
void gemm_imma(float* __restrict__ outC) {
    extern __shared__ __align__(128) char smem[];
    __shared__ unsigned s_vmax;

    const int8_t *A1g, *A0g, *B1g, *B0g;
    float* C;
    float sA, sB;
    bool sigmoid = false, vmax = false;
    if (FUSED) {
        int z = blockIdx.z;
        sA = __uint_as_float(g_sxb);
        sB = __uint_as_float(g_swb[z]);
        if (z == 0)      { A1g = g_xk1; A0g = g_xk0; B1g = g_Wk1; B0g = g_Wk0; C = g_k; }
        else if (z == 1) { A1g = g_xv1; A0g = g_xv0; B1g = g_Wv1; B0g = g_Wv0; C = g_v; vmax = true; }
        else             { A1g = g_xr1; A0g = g_xr0; B1g = g_Wr1; B0g = g_Wr0; C = g_r; sigmoid = true; }
    } else {
        A1g = g_o1; A0g = g_o0; B1g = g_Wo1; B0g = g_Wo0; C = outC;
        sA = __uint_as_float(g_svb);
        sB = __uint_as_float(g_swb[3]);
    }
    const float csc = sA * sB / (QMAXF * QMAXF);

    const int tid = threadIdx.x;
    const int wid = tid >> 5;
    const int lane = tid & 31;
    const int wm = wid >> 2;
    const int wn = wid & 3;
    const int gr = lane >> 2;
    const int tg = (lane & 3) * 2;
    const int bm = blockIdx.y * BM;
    const int bn = blockIdx.x * BN;
    const uint32_t sbase = smem_u32(smem);

    if (vmax && tid == 0) s_vmax = 0;

    // ldmatrix address components (byte units)
    const int a_row = lane & 15;
    const int a_kB  = (lane >> 4) * 16;
    const int b_row = (lane & 7) + ((lane >> 4) & 1) * 8;
    const int b_kB  = ((lane >> 3) & 1) * 16;

    auto load_stage = [&](int c, int stg) {
        const uint32_t sb = sbase + stg * STAGE_BYTES;
        const int k0 = c * BK;
#pragma unroll
        for (int i = 0; i < 2; i++) {
            int u = tid + i * 256;          // 0..511
            int row = u >> 2;               // 0..127
            int ch = u & 3;                 // 0..3 (16B chunks)
            uint32_t so = row * PITCH + ch * 16;
            size_t ga = (size_t)(bm + row) * HIDDEN + k0 + ch * 16;
            size_t gb = (size_t)(bn + row) * HIDDEN + k0 + ch * 16;
            cp16(sb + A1_OFF + so, A1g + ga);
            cp16(sb + A0_OFF + so, A0g + ga);
            cp16(sb + B1_OFF + so, B1g + gb);
            cp16(sb + B0_OFF + so, B0g + gb);
        }
        asm volatile("cp.async.commit_group;" ::: "memory");
    };

    int P2[4][4][4], P1[4][4][4];
#pragma unroll
    for (int i = 0; i < 4; i++)
#pragma unroll
        for (int j = 0; j < 4; j++)
#pragma unroll
            for (int q = 0; q < 4; q++) { P2[i][j][q] = 0; P1[i][j][q] = 0; }

    load_stage(0, 0);
    load_stage(1, 1);
    load_stage(2, 2);

#pragma unroll 1
    for (int c = 0; c < KITER; c++) {
        const int s = c % NSTAGE;
        asm volatile("cp.async.wait_group 2;" ::: "memory");
        __syncthreads();

        const uint32_t sb = sbase + s * STAGE_BYTES;

#pragma unroll
        for (int kh = 0; kh < 2; kh++) {
            const int kb = kh * 32;                 // 32-byte (k32) halves
            uint32_t b1f[4][2], b0f[4][2];
#pragma unroll
            for (int np = 0; np < 2; np++) {
                int n0 = wn * 32 + np * 16;
                uint32_t ro = (uint32_t)(n0 + b_row) * PITCH + kb + b_kB;
                LDMATRIX_X4(b1f[np * 2][0], b1f[np * 2][1],
                            b1f[np * 2 + 1][0], b1f[np * 2 + 1][1], sb + B1_OFF + ro);
                LDMATRIX_X4(b0f[np * 2][0], b0f[np * 2][1],
                            b0f[np * 2 + 1][0], b0f[np * 2 + 1][1], sb + B0_OFF + ro);
            }
#pragma unroll
            for (int mf = 0; mf < 4; mf++) {
                int r0 = wm * 64 + mf * 16;
                uint32_t ro = (uint32_t)(r0 + a_row) * PITCH + kb + a_kB;
                uint32_t a1f[4], a0f[4];
                LDMATRIX_X4(a1f[0], a1f[1], a1f[2], a1f[3], sb + A1_OFF + ro);
                LDMATRIX_X4(a0f[0], a0f[1], a0f[2], a0f[3], sb + A0_OFF + ro);
#pragma unroll
                for (int nf = 0; nf < 4; nf++) {
                    MMA_S8(P2[mf][nf], a1f, b1f[nf]);
                    MMA_S8(P1[mf][nf], a1f, b0f[nf]);
                    MMA_S8(P1[mf][nf], a0f, b1f[nf]);
                }
            }
        }
        __syncthreads();
        if (c + NSTAGE < KITER) load_stage(c + NSTAGE, (c + NSTAGE) % NSTAGE);
        else asm volatile("cp.async.commit_group;" ::: "memory");
    }

    // epilogue
    float lmax = 0.f;
#pragma unroll
    for (int mf = 0; mf < 4; mf++) {
        int r0 = bm + wm * 64 + mf * 16 + gr;
#pragma unroll
        for (int nf = 0; nf < 4; nf++) {
            int cc = bn + wn * 32 + nf * 8 + tg;
            float cv[4];
#pragma unroll
            for (int q = 0; q < 4; q++) {
                cv[q] = csc * (16384.0f * (float)P2[mf][nf][q] + 128.0f * (float)P1[mf][nf][q]);
                if (FUSED && vmax) lmax = fmaxf(lmax, fabsf(cv[q]));
                if (FUSED && sigmoid) cv[q] = 1.f / (1.f + __expf(-cv[q]));
            }
            *reinterpret_cast<float2*>(C + (size_t)r0 * HIDDEN + cc) = make_float2(cv[0], cv[1]);
            *reinterpret_cast<float2*>(C + (size_t)(r0 + 8) * HIDDEN + cc) = make_float2(cv[2], cv[3]);
        }
    }

    if (FUSED && vmax) {
        __syncthreads();
#pragma unroll
        for (int o = 16; o > 0; o >>= 1)
            lmax = fmaxf(lmax, __shfl_xor_sync(0xFFFFFFFF, lmax, o));
        if (lane == 0) atomicMax(&s_vmax, __float_as_uint(lmax));
        __syncthreads();
        if (tid == 0) atomicMax(&g_svb, s_vmax);
    }
}

// ---------------------------------------------------------------------------
// 3) Chunk-parallel WKV scan
// ---------------------------------------------------------------------------
__global__ void wkv_phase1(const float* __restrict__ td) {
    int idx = blockIdx.x * blockDim.x + threadIdx.x;
    if (idx >= CH * NCHUNK) return;
    int h = idx & (HIDDEN - 1);
    int bc = idx >> 10;
    int c = bc & (NCHUNK - 1);
    int b = bc >> 4;

    const float w = td[h];
    const size_t base = ((size_t)b * SEQ + (size_t)c * LCHUNK) * HIDDEN + h;
    const float* kp = g_k + base;
    const float* vp = g_v + base;

    float aa = 0.f, bb = 0.f, pp = NEG_INF;
#pragma unroll 4
    for (int t = 0; t < LCHUNK; t++) {
        float k = kp[(size_t)t * HIDDEN];
        float v = vp[(size_t)t * HIDDEN];
        float ww2 = w + pp;
        float p2 = fmaxf(ww2, k);
        float e1 = __expf(ww2 - p2);
        float e2 = __expf(k - p2);
        aa = e1 * aa + e2 * v;
        bb = e1 * bb + e2;
        pp = p2;
    }
    g_saa[idx] = aa;
    g_sbb[idx] = bb;
    g_spp[idx] = pp;
}

__global__ void wkv_phase2(const float* __restrict__ td) {
    int idx = blockIdx.x * blockDim.x + threadIdx.x;
    if (idx >= CH) return;
    int h = idx & (HIDDEN - 1);
    int b = idx >> 10;
    const float wl = td[h] * (float)LCHUNK;

    float aa = 0.f, bb = 0.f, pp = NEG_INF;
#pragma unroll
    for (int c = 0; c < NCHUNK; c++) {
        int s = (b * NCHUNK + c) * HIDDEN + h;
        g_iaa[s] = aa;
        g_ibb[s] = bb;
        g_ipp[s] = pp;
        float laa = g_saa[s], lbb = g_sbb[s], lpp = g_spp[s];
        float sp = pp + wl;
        float p = fmaxf(sp, lpp);
        float e1 = __expf(sp - p);
        float e2 = __expf(lpp - p);
        aa = e1 * aa + e2 * laa;
        bb = e1 * bb + e2 * lbb;
        pp = p;
    }
}

__global__ void wkv_phase3(const float* __restrict__ td,
                           const float* __restrict__ tf) {
    int idx = blockIdx.x * blockDim.x + threadIdx.x;
    if (idx >= CH * NCHUNK) return;
    int h = idx & (HIDDEN - 1);
    int bc = idx >> 10;
    int c = bc & (NCHUNK - 1);
    int b = bc >> 4;

    const float w = td[h];
    const float u = tf[h];
    float sv = __uint_as_float(g_svb);
    float inv = (sv > 0.f) ? (QMAXF / sv) : 0.f;

    const size_t base = ((size_t)b * SEQ + (size_t)c * LCHUNK) * HIDDEN + h;
    const float* kp = g_k + base;
    const float* vp = g_v + base;
    const float* rp = g_r + base;

    float aa = g_iaa[idx], bb = g_ibb[idx], pp = g_ipp[idx];

#pragma unroll 4
    for (int t = 0; t < LCHUNK; t++) {
        size_t off = (size_t)t * HIDDEN;
        float k = kp[off];
        float v = vp[off];

        float ww = u + k;
        float p = fmaxf(pp, ww);
        float e1 = __expf(pp - p);
        float e2 = __expf(ww - p);
        float wkv = (e1 * aa + e2 * v) / (e1 * bb + e2 + 1e-9f);
        float o = rp[off] * wkv;

        float q = rintf(o * inv);
        q = fminf(fmaxf(q, -QMAXF), QMAXF);
        float q1 = rintf(q * 0.0078125f);
        float q0 = q - 128.0f * q1;
        g_o1[base + off] = (int8_t)(int)q1;
        g_o0[base + off] = (int8_t)(int)q0;

        float ww2 = w + pp;
        float p2 = fmaxf(ww2, k);
        float e1b = __expf(ww2 - p2);
        float e2b = __expf(k - p2);
        aa = e1b * aa + e2b * v;
        bb = e1b * bb + e2b;
        pp = p2;
    }
}

// ---------------------------------------------------------------------------
// Launch
// ---------------------------------------------------------------------------
extern "C" void kernel_launch(void* const* d_in, const int* in_sizes, int n_in,
                              void* d_out, int out_size) {
    const float* x  = (const float*)d_in[0];
    const float* td = (const float*)d_in[1];
    const float* tf = (const float*)d_in[2];
    const float* mk = (const float*)d_in[3];
    const float* mv = (const float*)d_in[4];
    const float* mr = (const float*)d_in[5];
    const float* Wk = (const float*)d_in[6];
    const float* Wv = (const float*)d_in[7];
    const float* Wr = (const float*)d_in[8];
    const float* Wo = (const float*)d_in[9];
    float* out = (float*)d_out;

    cudaFuncSetAttribute(gemm_imma<true>,  cudaFuncAttributeMaxDynamicSharedMemorySize, SMEM_TOTAL);
    cudaFuncSetAttribute(gemm_imma<false>, cudaFuncAttributeMaxDynamicSharedMemorySize, SMEM_TOTAL);

    // 0) scales
    init_scales<<<1, 32>>>();
    absmax_all<<<4096 + 4 * 256, 256>>>(x, Wk, Wv, Wr, Wo);

    // 1) time-mix + quant, weight quant
    {
        int n4 = MTOT * HIDDEN / 4;
        mix_quant<<<(n4 + 255) / 256, 256>>>(x, mk, mv, mr);
        int nw = 4 * HIDDEN * HIDDEN / 4;
        wquant_all<<<(nw + 255) / 256, 256>>>(Wk, Wv, Wr, Wo);
    }

    // 2) fused k/v/r projections (int8 imma)
    dim3 ggrid(HIDDEN / BN, MTOT / BM, 3);   // (8, 128, 3)
    gemm_imma<true><<<ggrid, 256, SMEM_TOTAL>>>(nullptr);

    // 3) chunk-parallel wkv (writes int8 limbs of r*wkv)
    wkv_phase1<<<(CH * NCHUNK + 255) / 256, 256>>>(td);
    wkv_phase2<<<(CH + 255) / 256, 256>>>(td);
    wkv_phase3<<<(CH * NCHUNK + 255) / 256, 256>>>(td, tf);

    // 4) output projection
    dim3 ogrid(HIDDEN / BN, MTOT / BM, 1);
    gemm_imma<false><<<ogrid, 256, SMEM_TOTAL>>>(out);
}

// round 7
// speedup vs baseline: 5.8911x; 1.0270x over previous
#include <cuda_runtime.h>
#include <cuda_bf16.h>
#include <cstdint>

#define HIDDEN 1024
#define BATCH 8
#define SEQ 2048
#define MTOT (BATCH * SEQ)          // 16384 rows
#define NEG_INF -1e38f
#define CH (BATCH * HIDDEN)         // 8192 channels
#define LCHUNK 128
#define NCHUNK (SEQ / LCHUNK)       // 16
#define QMAXF 16256.0f              // 127 * 128

// GEMM tiling (imma m16n8k32, int8 2-limb)
#define BM 128
#define BN 128
#define BK 64                        // 64 int8 per row per stage
#define KITER (HIDDEN / BK)          // 16
#define PITCH 80                     // 64 + 16 pad bytes
#define TILE_BYTES (BM * PITCH)      // 10240
#define A1_OFF 0
#define A0_OFF TILE_BYTES
#define B1_OFF (2 * TILE_BYTES)
#define B0_OFF (3 * TILE_BYTES)
#define STAGE_BYTES (4 * TILE_BYTES) // 40960
#define NSTAGE 4
#define SMEM_TOTAL (NSTAGE * STAGE_BYTES)   // 163840
#define GTHREADS 512

// ---------------------------------------------------------------------------
// Scratch (device globals)
// ---------------------------------------------------------------------------
__device__ __align__(16) int8_t g_xk1[MTOT * HIDDEN];
__device__ __align__(16) int8_t g_xk0[MTOT * HIDDEN];
__device__ __align__(16) int8_t g_xv1[MTOT * HIDDEN];
__device__ __align__(16) int8_t g_xv0[MTOT * HIDDEN];
__device__ __align__(16) int8_t g_xr1[MTOT * HIDDEN];
__device__ __align__(16) int8_t g_xr0[MTOT * HIDDEN];
__device__ __align__(16) int8_t g_o1 [MTOT * HIDDEN];
__device__ __align__(16) int8_t g_o0 [MTOT * HIDDEN];

__device__ __align__(16) int8_t g_Wk1[HIDDEN * HIDDEN];
__device__ __align__(16) int8_t g_Wk0[HIDDEN * HIDDEN];
__device__ __align__(16) int8_t g_Wv1[HIDDEN * HIDDEN];
__device__ __align__(16) int8_t g_Wv0[HIDDEN * HIDDEN];
__device__ __align__(16) int8_t g_Wr1[HIDDEN * HIDDEN];
__device__ __align__(16) int8_t g_Wr0[HIDDEN * HIDDEN];
__device__ __align__(16) int8_t g_Wo1[HIDDEN * HIDDEN];
__device__ __align__(16) int8_t g_Wo0[HIDDEN * HIDDEN];

__device__ float g_k[MTOT * HIDDEN];
__device__ float g_v[MTOT * HIDDEN];
__device__ float g_r[MTOT * HIDDEN];

__device__ float g_saa[CH * NCHUNK];
__device__ float g_sbb[CH * NCHUNK];
__device__ float g_spp[CH * NCHUNK];
__device__ float g_iaa[CH * NCHUNK];
__device__ float g_ibb[CH * NCHUNK];
__device__ float g_ipp[CH * NCHUNK];

// scale scalars (abs-max as uint bits; reset each invocation)
__device__ unsigned g_sxb;
__device__ unsigned g_swb[4];
__device__ unsigned g_svb;

// ---------------------------------------------------------------------------
// Helpers
// ---------------------------------------------------------------------------
__device__ __forceinline__ uint32_t smem_u32(const void* p) {
    uint32_t a;
    asm("{ .reg .u64 t; cvta.to.shared.u64 t, %1; cvt.u32.u64 %0, t; }"
        : "=r"(a) : "l"(p));
    return a;
}

__device__ __forceinline__ void cp16(uint32_t s, const void* g) {
    asm volatile("cp.async.cg.shared.global [%0], [%1], 16;" :: "r"(s), "l"(g));
}

#define MMA_S8(c, a, b)                                                       \
    asm volatile(                                                             \
        "mma.sync.aligned.m16n8k32.row.col.s32.s8.s8.s32 "                    \
        "{%0,%1,%2,%3},{%4,%5,%6,%7},{%8,%9},{%0,%1,%2,%3};"                  \
        : "+r"((c)[0]), "+r"((c)[1]), "+r"((c)[2]), "+r"((c)[3])              \
        : "r"((a)[0]), "r"((a)[1]), "r"((a)[2]), "r"((a)[3]),                 \
          "r"((b)[0]), "r"((b)[1]))

#define LDMATRIX_X4(r0, r1, r2, r3, addr)                                     \
    asm volatile(                                                             \
        "ldmatrix.sync.aligned.m8n8.x4.shared.b16 {%0,%1,%2,%3}, [%4];"       \
        : "=r"(r0), "=r"(r1), "=r"(r2), "=r"(r3) : "r"(addr))

__device__ __forceinline__ void quant4(const float* v, float inv,
                                       uint32_t& p1, uint32_t& p0) {
    uint32_t r1 = 0, r0 = 0;
#pragma unroll
    for (int j = 0; j < 4; j++) {
        float q = rintf(v[j] * inv);
        q = fminf(fmaxf(q, -QMAXF), QMAXF);
        float q1 = rintf(q * 0.0078125f);      // /128
        float q0 = q - 128.0f * q1;
        r1 |= ((uint32_t)(uint8_t)(int8_t)(int)q1) << (j * 8);
        r0 |= ((uint32_t)(uint8_t)(int8_t)(int)q0) << (j * 8);
    }
    p1 = r1; p0 = r0;
}

// ---------------------------------------------------------------------------
// 0) scale init + absmax
// ---------------------------------------------------------------------------
__global__ void init_scales() {
    if (threadIdx.x == 0) {
        g_sxb = 0; g_svb = 0;
        g_swb[0] = 0; g_swb[1] = 0; g_swb[2] = 0; g_swb[3] = 0;
    }
}

__global__ void absmax_all(const float* __restrict__ x,
                           const float* __restrict__ Wk, const float* __restrict__ Wv,
                           const float* __restrict__ Wr, const float* __restrict__ Wo) {
    __shared__ float sred[8];
    int blk = blockIdx.x;
    const float* base;
    unsigned* target;
    int rel;
    if (blk < 4096)      { base = x;  target = &g_sxb;    rel = blk; }
    else if (blk < 4352) { base = Wk; target = &g_swb[0]; rel = blk - 4096; }
    else if (blk < 4608) { base = Wv; target = &g_swb[1]; rel = blk - 4352; }
    else if (blk < 4864) { base = Wr; target = &g_swb[2]; rel = blk - 4608; }
    else                 { base = Wo; target = &g_swb[3]; rel = blk - 4864; }

    const float4* p = reinterpret_cast<const float4*>(base + (size_t)rel * 4096);
    float m = 0.f;
#pragma unroll
    for (int j = 0; j < 4; j++) {
        float4 v = p[threadIdx.x + j * 256];
        m = fmaxf(m, fmaxf(fmaxf(fabsf(v.x), fabsf(v.y)), fmaxf(fabsf(v.z), fabsf(v.w))));
    }
#pragma unroll
    for (int o = 16; o > 0; o >>= 1)
        m = fmaxf(m, __shfl_xor_sync(0xFFFFFFFF, m, o));
    if ((threadIdx.x & 31) == 0) sred[threadIdx.x >> 5] = m;
    __syncthreads();
    if (threadIdx.x < 8) {
        m = sred[threadIdx.x];
#pragma unroll
        for (int o = 4; o > 0; o >>= 1)
            m = fmaxf(m, __shfl_xor_sync(0xFF, m, o));
        if (threadIdx.x == 0) atomicMax(target, __float_as_uint(m));
    }
}

// ---------------------------------------------------------------------------
// 1) Time-mix + int8 limb quantization
// ---------------------------------------------------------------------------
__global__ void mix_quant(const float* __restrict__ x,
                          const float* __restrict__ mk,
                          const float* __restrict__ mv,
                          const float* __restrict__ mr) {
    int i = blockIdx.x * blockDim.x + threadIdx.x;
    if (i >= MTOT * HIDDEN / 4) return;
    int idx = i * 4;
    int h = idx & (HIDDEN - 1);
    int t = (idx / HIDDEN) & (SEQ - 1);

    float sx = __uint_as_float(g_sxb);
    float inv = (sx > 0.f) ? (QMAXF / sx) : 0.f;

    float4 xc = *reinterpret_cast<const float4*>(x + idx);
    float4 xp = (t == 0) ? make_float4(0.f, 0.f, 0.f, 0.f)
                         : *reinterpret_cast<const float4*>(x + idx - HIDDEN);
    float4 k4 = *reinterpret_cast<const float4*>(mk + h);
    float4 v4 = *reinterpret_cast<const float4*>(mv + h);
    float4 r4 = *reinterpret_cast<const float4*>(mr + h);

    float xcf[4] = {xc.x, xc.y, xc.z, xc.w};
    float xpf[4] = {xp.x, xp.y, xp.z, xp.w};
    float kf[4] = {k4.x, k4.y, k4.z, k4.w};
    float vf[4] = {v4.x, v4.y, v4.z, v4.w};
    float rf[4] = {r4.x, r4.y, r4.z, r4.w};
    float ok[4], ov[4], orr[4];
#pragma unroll
    for (int j = 0; j < 4; j++) {
        ok[j]  = xcf[j] * kf[j] + xpf[j] * (1.f - kf[j]);
        ov[j]  = xcf[j] * vf[j] + xpf[j] * (1.f - vf[j]);
        orr[j] = xcf[j] * rf[j] + xpf[j] * (1.f - rf[j]);
    }
    uint32_t p1, p0;
    quant4(ok, inv, p1, p0);
    *reinterpret_cast<uint32_t*>(g_xk1 + idx) = p1;
    *reinterpret_cast<uint32_t*>(g_xk0 + idx) = p0;
    quant4(ov, inv, p1, p0);
    *reinterpret_cast<uint32_t*>(g_xv1 + idx) = p1;
    *reinterpret_cast<uint32_t*>(g_xv0 + idx) = p0;
    quant4(orr, inv, p1, p0);
    *reinterpret_cast<uint32_t*>(g_xr1 + idx) = p1;
    *reinterpret_cast<uint32_t*>(g_xr0 + idx) = p0;
}

__global__ void wquant_all(const float* __restrict__ W0, const float* __restrict__ W1,
                           const float* __restrict__ W2, const float* __restrict__ W3) {
    int i = blockIdx.x * blockDim.x + threadIdx.x;
    if (i >= 4 * HIDDEN * HIDDEN / 4) return;
    int sel = i >> 18;
    int off = (i & 0x3FFFF) * 4;
    const float* W; int8_t *d1, *d0;
    switch (sel) {
        case 0: W = W0; d1 = g_Wk1; d0 = g_Wk0; break;
        case 1: W = W1; d1 = g_Wv1; d0 = g_Wv0; break;
        case 2: W = W2; d1 = g_Wr1; d0 = g_Wr0; break;
        default: W = W3; d1 = g_Wo1; d0 = g_Wo0; break;
    }
    float sw = __uint_as_float(g_swb[sel]);
    float inv = (sw > 0.f) ? (QMAXF / sw) : 0.f;
    float4 w = *reinterpret_cast<const float4*>(W + off);
    float wf[4] = {w.x, w.y, w.z, w.w};
    uint32_t p1, p0;
    quant4(wf, inv, p1, p0);
    *reinterpret_cast<uint32_t*>(d1 + off) = p1;
    *reinterpret_cast<uint32_t*>(d0 + off) = p0;
}

// ---------------------------------------------------------------------------
// 2) int8 IMMA GEMM, 2-limb, 512 threads (16 warps 4x4, warp tile 32x32),
//    4-stage cp.async ring, one __syncthreads per k-iter.
// ---------------------------------------------------------------------------
template <bool FUSED>
__global__ __launch_bounds__(GTHREADS, 1)
void gemm_imma(float* __restrict__ outC) {
    extern __shared__ __align__(128) char smem[];
    __shared__ unsigned s_vmax;

    const int8_t *A1g, *A0g, *B1g, *B0g;
    float* C;
    float sA, sB;
    bool sigmoid = false, vmax = false;
    if (FUSED) {
        int z = blockIdx.z;
        sA = __uint_as_float(g_sxb);
        sB = __uint_as_float(g_swb[z]);
        if (z == 0)      { A1g = g_xk1; A0g = g_xk0; B1g = g_Wk1; B0g = g_Wk0; C = g_k; }
        else if (z == 1) { A1g = g_xv1; A0g = g_xv0; B1g = g_Wv1; B0g = g_Wv0; C = g_v; vmax = true; }
        else             { A1g = g_xr1; A0g = g_xr0; B1g = g_Wr1; B0g = g_Wr0; C = g_r; sigmoid = true; }
    } else {
        A1g = g_o1; A0g = g_o0; B1g = g_Wo1; B0g = g_Wo0; C = outC;
        sA = __uint_as_float(g_svb);
        sB = __uint_as_float(g_swb[3]);
    }
    const float csc = sA * sB / (QMAXF * QMAXF);

    const int tid = threadIdx.x;
    const int wid = tid >> 5;
    const int lane = tid & 31;
    const int wm = wid >> 2;        // 0..3
    const int wn = wid & 3;         // 0..3
    const int gr = lane >> 2;
    const int tg = (lane & 3) * 2;
    const int bm = blockIdx.y * BM;
    const int bn = blockIdx.x * BN;
    const uint32_t sbase = smem_u32(smem);

    if (vmax && tid == 0) s_vmax = 0;

    const int a_row = lane & 15;
    const int a_kB  = (lane >> 4) * 16;
    const int b_row = (lane & 7) + ((lane >> 4) & 1) * 8;
    const int b_kB  = ((lane >> 3) & 1) * 16;

    // loader: one 16B chunk per array per thread (512 threads cover 128x64)
    const int l_row = tid >> 2;
    const int l_ch  = tid & 3;
    auto load_stage = [&](int c, int stg) {
        const uint32_t sb = sbase + stg * STAGE_BYTES;
        const int k0 = c * BK;
        uint32_t so = l_row * PITCH + l_ch * 16;
        size_t ga = (size_t)(bm + l_row) * HIDDEN + k0 + l_ch * 16;
        size_t gb = (size_t)(bn + l_row) * HIDDEN + k0 + l_ch * 16;
        cp16(sb + A1_OFF + so, A1g + ga);
        cp16(sb + A0_OFF + so, A0g + ga);
        cp16(sb + B1_OFF + so, B1g + gb);
        cp16(sb + B0_OFF + so, B0g + gb);
        asm volatile("cp.async.commit_group;" ::: "memory");
    };

    int P2[2][4][4], P1[2][4][4];
#pragma unroll
    for (int i = 0; i < 2; i++)
#pragma unroll
        for (int j = 0; j < 4; j++)
#pragma unroll
            for (int q = 0; q < 4; q++) { P2[i][j][q] = 0; P1[i][j][q] = 0; }

    load_stage(0, 0);
    load_stage(1, 1);
    load_stage(2, 2);

#pragma unroll 1
    for (int c = 0; c < KITER; c++) {
        const int s = c & 3;
        asm volatile("cp.async.wait_group 2;" ::: "memory");
        __syncthreads();

        // issue loads into the slot consumed at iter c-1 (protected by sync)
        if (c + NSTAGE - 1 < KITER) load_stage(c + 3, (c + 3) & 3);
        else asm volatile("cp.async.commit_group;" ::: "memory");

        const uint32_t sb = sbase + s * STAGE_BYTES;

#pragma unroll
        for (int kh = 0; kh < 2; kh++) {
            const int kb = kh * 32;
            uint32_t b1f[4][2], b0f[4][2];
#pragma unroll
            for (int np = 0; np < 2; np++) {
                int n0 = wn * 32 + np * 16;
                uint32_t ro = (uint32_t)(n0 + b_row) * PITCH + kb + b_kB;
                LDMATRIX_X4(b1f[np * 2][0], b1f[np * 2][1],
                            b1f[np * 2 + 1][0], b1f[np * 2 + 1][1], sb + B1_OFF + ro);
                LDMATRIX_X4(b0f[np * 2][0], b0f[np * 2][1],
                            b0f[np * 2 + 1][0], b0f[np * 2 + 1][1], sb + B0_OFF + ro);
            }
#pragma unroll
            for (int mf = 0; mf < 2; mf++) {
                int r0 = wm * 32 + mf * 16;
                uint32_t ro = (uint32_t)(r0 + a_row) * PITCH + kb + a_kB;
                uint32_t a1f[4], a0f[4];
                LDMATRIX_X4(a1f[0], a1f[1], a1f[2], a1f[3], sb + A1_OFF + ro);
                LDMATRIX_X4(a0f[0], a0f[1], a0f[2], a0f[3], sb + A0_OFF + ro);
#pragma unroll
                for (int nf = 0; nf < 4; nf++) {
                    MMA_S8(P2[mf][nf], a1f, b1f[nf]);
                    MMA_S8(P1[mf][nf], a1f, b0f[nf]);
                    MMA_S8(P1[mf][nf], a0f, b1f[nf]);
                }
            }
        }
    }

    // epilogue
    float lmax = 0.f;
#pragma unroll
    for (int mf = 0; mf < 2; mf++) {
        int r0 = bm + wm * 32 + mf * 16 + gr;
#pragma unroll
        for (int nf = 0; nf < 4; nf++) {
            int cc = bn + wn * 32 + nf * 8 + tg;
            float cv[4];
#pragma unroll
            for (int q = 0; q < 4; q++) {
                cv[q] = csc * (16384.0f * (float)P2[mf][nf][q] + 128.0f * (float)P1[mf][nf][q]);
                if (FUSED && vmax) lmax = fmaxf(lmax, fabsf(cv[q]));
                if (FUSED && sigmoid) cv[q] = 1.f / (1.f + __expf(-cv[q]));
            }
            *reinterpret_cast<float2*>(C + (size_t)r0 * HIDDEN + cc) = make_float2(cv[0], cv[1]);
            *reinterpret_cast<float2*>(C + (size_t)(r0 + 8) * HIDDEN + cc) = make_float2(cv[2], cv[3]);
        }
    }

    if (FUSED && vmax) {
        __syncthreads();
#pragma unroll
        for (int o = 16; o > 0; o >>= 1)
            lmax = fmaxf(lmax, __shfl_xor_sync(0xFFFFFFFF, lmax, o));
        if (lane == 0) atomicMax(&s_vmax, __float_as_uint(lmax));
        __syncthreads();
        if (tid == 0) atomicMax(&g_svb, s_vmax);
    }
}

// ---------------------------------------------------------------------------
// 3) Chunk-parallel WKV scan
// ---------------------------------------------------------------------------
__global__ void wkv_phase1(const float* __restrict__ td) {
    int idx = blockIdx.x * blockDim.x + threadIdx.x;
    if (idx >= CH * NCHUNK) return;
    int h = idx & (HIDDEN - 1);
    int bc = idx >> 10;
    int c = bc & (NCHUNK - 1);
    int b = bc >> 4;

    const float w = td[h];
    const size_t base = ((size_t)b * SEQ + (size_t)c * LCHUNK) * HIDDEN + h;
    const float* kp = g_k + base;
    const float* vp = g_v + base;

    float aa = 0.f, bb = 0.f, pp = NEG_INF;
#pragma unroll 4
    for (int t = 0; t < LCHUNK; t++) {
        float k = kp[(size_t)t * HIDDEN];
        float v = vp[(size_t)t * HIDDEN];
        float ww2 = w + pp;
        float p2 = fmaxf(ww2, k);
        float e1 = __expf(ww2 - p2);
        float e2 = __expf(k - p2);
        aa = e1 * aa + e2 * v;
        bb = e1 * bb + e2;
        pp = p2;
    }
    g_saa[idx] = aa;
    g_sbb[idx] = bb;
    g_spp[idx] = pp;
}

__global__ void wkv_phase2(const float* __restrict__ td) {
    int idx = blockIdx.x * blockDim.x + threadIdx.x;
    if (idx >= CH) return;
    int h = idx & (HIDDEN - 1);
    int b = idx >> 10;
    const float wl = td[h] * (float)LCHUNK;

    float aa = 0.f, bb = 0.f, pp = NEG_INF;
#pragma unroll
    for (int c = 0; c < NCHUNK; c++) {
        int s = (b * NCHUNK + c) * HIDDEN + h;
        g_iaa[s] = aa;
        g_ibb[s] = bb;
        g_ipp[s] = pp;
        float laa = g_saa[s], lbb = g_sbb[s], lpp = g_spp[s];
        float sp = pp + wl;
        float p = fmaxf(sp, lpp);
        float e1 = __expf(sp - p);
        float e2 = __expf(lpp - p);
        aa = e1 * aa + e2 * laa;
        bb = e1 * bb + e2 * lbb;
        pp = p;
    }
}

__global__ void wkv_phase3(const float* __restrict__ td,
                           const float* __restrict__ tf) {
    int idx = blockIdx.x * blockDim.x + threadIdx.x;
    if (idx >= CH * NCHUNK) return;
    int h = idx & (HIDDEN - 1);
    int bc = idx >> 10;
    int c = bc & (NCHUNK - 1);
    int b = bc >> 4;

    const float w = td[h];
    const float u = tf[h];
    float sv = __uint_as_float(g_svb);
    float inv = (sv > 0.f) ? (QMAXF / sv) : 0.f;

    const size_t base = ((size_t)b * SEQ + (size_t)c * LCHUNK) * HIDDEN + h;
    const float* kp = g_k + base;
    const float* vp = g_v + base;
    const float* rp = g_r + base;

    float aa = g_iaa[idx], bb = g_ibb[idx], pp = g_ipp[idx];

#pragma unroll 4
    for (int t = 0; t < LCHUNK; t++) {
        size_t off = (size_t)t * HIDDEN;
        float k = kp[off];
        float v = vp[off];

        float ww = u + k;
        float p = fmaxf(pp, ww);
        float e1 = __expf(pp - p);
        float e2 = __expf(ww - p);
        float wkv = (e1 * aa + e2 * v) / (e1 * bb + e2 + 1e-9f);
        float o = rp[off] * wkv;

        float q = rintf(o * inv);
        q = fminf(fmaxf(q, -QMAXF), QMAXF);
        float q1 = rintf(q * 0.0078125f);
        float q0 = q - 128.0f * q1;
        g_o1[base + off] = (int8_t)(int)q1;
        g_o0[base + off] = (int8_t)(int)q0;

        float ww2 = w + pp;
        float p2 = fmaxf(ww2, k);
        float e1b = __expf(ww2 - p2);
        float e2b = __expf(k - p2);
        aa = e1b * aa + e2b * v;
        bb = e1b * bb + e2b;
        pp = p2;
    }
}

// ---------------------------------------------------------------------------
// Launch
// ---------------------------------------------------------------------------
extern "C" void kernel_launch(void* const* d_in, const int* in_sizes, int n_in,
                              void* d_out, int out_size) {
    const float* x  = (const float*)d_in[0];
    const float* td = (const float*)d_in[1];
    const float* tf = (const float*)d_in[2];
    const float* mk = (const float*)d_in[3];
    const float* mv = (const float*)d_in[4];
    const float* mr = (const float*)d_in[5];
    const float* Wk = (const float*)d_in[6];
    const float* Wv = (const float*)d_in[7];
    const float* Wr = (const float*)d_in[8];
    const float* Wo = (const float*)d_in[9];
    float* out = (float*)d_out;

    cudaFuncSetAttribute(gemm_imma<true>,  cudaFuncAttributeMaxDynamicSharedMemorySize, SMEM_TOTAL);
    cudaFuncSetAttribute(gemm_imma<false>, cudaFuncAttributeMaxDynamicSharedMemorySize, SMEM_TOTAL);

    // 0) scales
    init_scales<<<1, 32>>>();
    absmax_all<<<4096 + 4 * 256, 256>>>(x, Wk, Wv, Wr, Wo);

    // 1) time-mix + quant, weight quant
    {
        int n4 = MTOT * HIDDEN / 4;
        mix_quant<<<(n4 + 255) / 256, 256>>>(x, mk, mv, mr);
        int nw = 4 * HIDDEN * HIDDEN / 4;
        wquant_all<<<(nw + 255) / 256, 256>>>(Wk, Wv, Wr, Wo);
    }

    // 2) fused k/v/r projections (int8 imma)
    dim3 ggrid(HIDDEN / BN, MTOT / BM, 3);   // (8, 128, 3)
    gemm_imma<true><<<ggrid, GTHREADS, SMEM_TOTAL>>>(nullptr);

    // 3) chunk-parallel wkv (writes int8 limbs of r*wkv)
    wkv_phase1<<<(CH * NCHUNK + 255) / 256, 256>>>(td);
    wkv_phase2<<<(CH + 255) / 256, 256>>>(td);
    wkv_phase3<<<(CH * NCHUNK + 255) / 256, 256>>>(td, tf);

    // 4) output projection
    dim3 ogrid(HIDDEN / BN, MTOT / BM, 1);
    gemm_imma<false><<<ogrid, GTHREADS, SMEM_TOTAL>>>(out);
}

// round 9
// speedup vs baseline: 6.0270x; 1.0231x over previous
#include <cuda_runtime.h>
#include <cuda_bf16.h>
#include <cstdint>

#define HIDDEN 1024
#define BATCH 8
#define SEQ 2048
#define MTOT (BATCH * SEQ)          // 16384 rows
#define NEG_INF -1e38f
#define CH (BATCH * HIDDEN)         // 8192 channels
#define LCHUNK 64
#define NCHUNK (SEQ / LCHUNK)       // 32
#define QMAXF 16256.0f              // 127 * 128

// GEMM tiling (imma m16n8k32, int8 2-limb)
#define BM 128
#define BN 128
#define BK 64                        // 64 int8 per row per stage
#define KITER (HIDDEN / BK)          // 16
#define PITCH 80                     // 64 + 16 pad bytes
#define TILE_BYTES (BM * PITCH)      // 10240
#define A1_OFF 0
#define A0_OFF TILE_BYTES
#define B1_OFF (2 * TILE_BYTES)
#define B0_OFF (3 * TILE_BYTES)
#define STAGE_BYTES (4 * TILE_BYTES) // 40960
#define NSTAGE 5
#define SMEM_TOTAL (NSTAGE * STAGE_BYTES)   // 204800
#define GTHREADS 512

// ---------------------------------------------------------------------------
// Scratch (device globals)
// ---------------------------------------------------------------------------
__device__ __align__(16) int8_t g_xk1[MTOT * HIDDEN];
__device__ __align__(16) int8_t g_xk0[MTOT * HIDDEN];
__device__ __align__(16) int8_t g_xv1[MTOT * HIDDEN];
__device__ __align__(16) int8_t g_xv0[MTOT * HIDDEN];
__device__ __align__(16) int8_t g_xr1[MTOT * HIDDEN];
__device__ __align__(16) int8_t g_xr0[MTOT * HIDDEN];
__device__ __align__(16) int8_t g_o1 [MTOT * HIDDEN];
__device__ __align__(16) int8_t g_o0 [MTOT * HIDDEN];

__device__ __align__(16) int8_t g_Wk1[HIDDEN * HIDDEN];
__device__ __align__(16) int8_t g_Wk0[HIDDEN * HIDDEN];
__device__ __align__(16) int8_t g_Wv1[HIDDEN * HIDDEN];
__device__ __align__(16) int8_t g_Wv0[HIDDEN * HIDDEN];
__device__ __align__(16) int8_t g_Wr1[HIDDEN * HIDDEN];
__device__ __align__(16) int8_t g_Wr0[HIDDEN * HIDDEN];
__device__ __align__(16) int8_t g_Wo1[HIDDEN * HIDDEN];
__device__ __align__(16) int8_t g_Wo0[HIDDEN * HIDDEN];

__device__ float g_k[MTOT * HIDDEN];
__device__ float g_v[MTOT * HIDDEN];
__device__ float g_r[MTOT * HIDDEN];

__device__ float g_saa[CH * NCHUNK];
__device__ float g_sbb[CH * NCHUNK];
__device__ float g_spp[CH * NCHUNK];
__device__ float g_iaa[CH * NCHUNK];
__device__ float g_ibb[CH * NCHUNK];
__device__ float g_ipp[CH * NCHUNK];

// scale scalars (abs-max as uint bits; reset each invocation)
__device__ unsigned g_sxb;
__device__ unsigned g_swb[4];
__device__ unsigned g_svb;

// ---------------------------------------------------------------------------
// Helpers
// ---------------------------------------------------------------------------
__device__ __forceinline__ uint32_t smem_u32(const void* p) {
    uint32_t a;
    asm("{ .reg .u64 t; cvta.to.shared.u64 t, %1; cvt.u32.u64 %0, t; }"
        : "=r"(a) : "l"(p));
    return a;
}

__device__ __forceinline__ void cp16(uint32_t s, const void* g) {
    asm volatile("cp.async.cg.shared.global [%0], [%1], 16;" :: "r"(s), "l"(g));
}

#define MMA_S8(c, a, b)                                                       \
    asm volatile(                                                             \
        "mma.sync.aligned.m16n8k32.row.col.s32.s8.s8.s32 "                    \
        "{%0,%1,%2,%3},{%4,%5,%6,%7},{%8,%9},{%0,%1,%2,%3};"                  \
        : "+r"((c)[0]), "+r"((c)[1]), "+r"((c)[2]), "+r"((c)[3])              \
        : "r"((a)[0]), "r"((a)[1]), "r"((a)[2]), "r"((a)[3]),                 \
          "r"((b)[0]), "r"((b)[1]))

#define LDMATRIX_X4(r0, r1, r2, r3, addr)                                     \
    asm volatile(                                                             \
        "ldmatrix.sync.aligned.m8n8.x4.shared.b16 {%0,%1,%2,%3}, [%4];"       \
        : "=r"(r0), "=r"(r1), "=r"(r2), "=r"(r3) : "r"(addr))

__device__ __forceinline__ void quant4(const float* v, float inv,
                                       uint32_t& p1, uint32_t& p0) {
    uint32_t r1 = 0, r0 = 0;
#pragma unroll
    for (int j = 0; j < 4; j++) {
        float q = rintf(v[j] * inv);
        q = fminf(fmaxf(q, -QMAXF), QMAXF);
        float q1 = rintf(q * 0.0078125f);      // /128
        float q0 = q - 128.0f * q1;
        r1 |= ((uint32_t)(uint8_t)(int8_t)(int)q1) << (j * 8);
        r0 |= ((uint32_t)(uint8_t)(int8_t)(int)q0) << (j * 8);
    }
    p1 = r1; p0 = r0;
}

// ---------------------------------------------------------------------------
// 0) scale init + absmax
// ---------------------------------------------------------------------------
__global__ void init_scales() {
    if (threadIdx.x == 0) {
        g_sxb = 0; g_svb = 0;
        g_swb[0] = 0; g_swb[1] = 0; g_swb[2] = 0; g_swb[3] = 0;
    }
}

__global__ void absmax_all(const float* __restrict__ x,
                           const float* __restrict__ Wk, const float* __restrict__ Wv,
                           const float* __restrict__ Wr, const float* __restrict__ Wo) {
    __shared__ float sred[8];
    int blk = blockIdx.x;
    const float* base;
    unsigned* target;
    int rel;
    if (blk < 4096)      { base = x;  target = &g_sxb;    rel = blk; }
    else if (blk < 4352) { base = Wk; target = &g_swb[0]; rel = blk - 4096; }
    else if (blk < 4608) { base = Wv; target = &g_swb[1]; rel = blk - 4352; }
    else if (blk < 4864) { base = Wr; target = &g_swb[2]; rel = blk - 4608; }
    else                 { base = Wo; target = &g_swb[3]; rel = blk - 4864; }

    const float4* p = reinterpret_cast<const float4*>(base + (size_t)rel * 4096);
    float m = 0.f;
#pragma unroll
    for (int j = 0; j < 4; j++) {
        float4 v = p[threadIdx.x + j * 256];
        m = fmaxf(m, fmaxf(fmaxf(fabsf(v.x), fabsf(v.y)), fmaxf(fabsf(v.z), fabsf(v.w))));
    }
#pragma unroll
    for (int o = 16; o > 0; o >>= 1)
        m = fmaxf(m, __shfl_xor_sync(0xFFFFFFFF, m, o));
    if ((threadIdx.x & 31) == 0) sred[threadIdx.x >> 5] = m;
    __syncthreads();
    if (threadIdx.x < 8) {
        m = sred[threadIdx.x];
#pragma unroll
        for (int o = 4; o > 0; o >>= 1)
            m = fmaxf(m, __shfl_xor_sync(0xFF, m, o));
        if (threadIdx.x == 0) atomicMax(target, __float_as_uint(m));
    }
}

// ---------------------------------------------------------------------------
// 1) Merged prep: time-mix quant (blocks 0..16383) + weight quant (16384..20479)
// ---------------------------------------------------------------------------
__global__ void prep_quant(const float* __restrict__ x,
                           const float* __restrict__ mk,
                           const float* __restrict__ mv,
                           const float* __restrict__ mr,
                           const float* __restrict__ W0, const float* __restrict__ W1,
                           const float* __restrict__ W2, const float* __restrict__ W3) {
    int blk = blockIdx.x;
    if (blk < 16384) {
        int i = blk * blockDim.x + threadIdx.x;
        int idx = i * 4;
        int h = idx & (HIDDEN - 1);
        int t = (idx / HIDDEN) & (SEQ - 1);

        float sx = __uint_as_float(g_sxb);
        float inv = (sx > 0.f) ? (QMAXF / sx) : 0.f;

        float4 xc = *reinterpret_cast<const float4*>(x + idx);
        float4 xp = (t == 0) ? make_float4(0.f, 0.f, 0.f, 0.f)
                             : *reinterpret_cast<const float4*>(x + idx - HIDDEN);
        float4 k4 = *reinterpret_cast<const float4*>(mk + h);
        float4 v4 = *reinterpret_cast<const float4*>(mv + h);
        float4 r4 = *reinterpret_cast<const float4*>(mr + h);

        float xcf[4] = {xc.x, xc.y, xc.z, xc.w};
        float xpf[4] = {xp.x, xp.y, xp.z, xp.w};
        float kf[4] = {k4.x, k4.y, k4.z, k4.w};
        float vf[4] = {v4.x, v4.y, v4.z, v4.w};
        float rf[4] = {r4.x, r4.y, r4.z, r4.w};
        float ok[4], ov[4], orr[4];
#pragma unroll
        for (int j = 0; j < 4; j++) {
            ok[j]  = xcf[j] * kf[j] + xpf[j] * (1.f - kf[j]);
            ov[j]  = xcf[j] * vf[j] + xpf[j] * (1.f - vf[j]);
            orr[j] = xcf[j] * rf[j] + xpf[j] * (1.f - rf[j]);
        }
        uint32_t p1, p0;
        quant4(ok, inv, p1, p0);
        *reinterpret_cast<uint32_t*>(g_xk1 + idx) = p1;
        *reinterpret_cast<uint32_t*>(g_xk0 + idx) = p0;
        quant4(ov, inv, p1, p0);
        *reinterpret_cast<uint32_t*>(g_xv1 + idx) = p1;
        *reinterpret_cast<uint32_t*>(g_xv0 + idx) = p0;
        quant4(orr, inv, p1, p0);
        *reinterpret_cast<uint32_t*>(g_xr1 + idx) = p1;
        *reinterpret_cast<uint32_t*>(g_xr0 + idx) = p0;
    } else {
        int i = (blk - 16384) * blockDim.x + threadIdx.x;
        int sel = i >> 18;                  // 262144 float4 per weight (2^18)
        int off = (i & 0x3FFFF) * 4;
        const float* W; int8_t *d1, *d0;
        switch (sel) {
            case 0: W = W0; d1 = g_Wk1; d0 = g_Wk0; break;
            case 1: W = W1; d1 = g_Wv1; d0 = g_Wv0; break;
            case 2: W = W2; d1 = g_Wr1; d0 = g_Wr0; break;
            default: W = W3; d1 = g_Wo1; d0 = g_Wo0; break;
        }
        float sw = __uint_as_float(g_swb[sel]);
        float inv = (sw > 0.f) ? (QMAXF / sw) : 0.f;
        float4 w = *reinterpret_cast<const float4*>(W + off);
        float wf[4] = {w.x, w.y, w.z, w.w};
        uint32_t p1, p0;
        quant4(wf, inv, p1, p0);
        *reinterpret_cast<uint32_t*>(d1 + off) = p1;
        *reinterpret_cast<uint32_t*>(d0 + off) = p0;
    }
}

// ---------------------------------------------------------------------------
// 2) int8 IMMA GEMM, 2-limb, 512 threads (16 warps 4x4, warp tile 32x32),
//    5-stage cp.async ring: sync -> prefetch -> wait -> compute.
// ---------------------------------------------------------------------------
template <bool FUSED>
__global__ __launch_bounds__(GTHREADS, 1)
void gemm_imma(float* __restrict__ outC) {
    extern __shared__ __align__(128) char smem[];
    __shared__ unsigned s_vmax;

    const int8_t *A1g, *A0g, *B1g, *B0g;
    float* C;
    float sA, sB;
    bool sigmoid = false, vmax = false;
    if (FUSED) {
        int z = blockIdx.z;
        sA = __uint_as_float(g_sxb);
        sB = __uint_as_float(g_swb[z]);
        if (z == 0)      { A1g = g_xk1; A0g = g_xk0; B1g = g_Wk1; B0g = g_Wk0; C = g_k; }
        else if (z == 1) { A1g = g_xv1; A0g = g_xv0; B1g = g_Wv1; B0g = g_Wv0; C = g_v; vmax = true; }
        else             { A1g = g_xr1; A0g = g_xr0; B1g = g_Wr1; B0g = g_Wr0; C = g_r; sigmoid = true; }
    } else {
        A1g = g_o1; A0g = g_o0; B1g = g_Wo1; B0g = g_Wo0; C = outC;
        sA = __uint_as_float(g_svb);
        sB = __uint_as_float(g_swb[3]);
    }
    const float csc = sA * sB / (QMAXF * QMAXF);

    const int tid = threadIdx.x;
    const int wid = tid >> 5;
    const int lane = tid & 31;
    const int wm = wid >> 2;
    const int wn = wid & 3;
    const int gr = lane >> 2;
    const int tg = (lane & 3) * 2;
    const int bm = blockIdx.y * BM;
    const int bn = blockIdx.x * BN;
    const uint32_t sbase = smem_u32(smem);

    if (vmax && tid == 0) s_vmax = 0;

    const int a_row = lane & 15;
    const int a_kB  = (lane >> 4) * 16;
    const int b_row = (lane & 7) + ((lane >> 4) & 1) * 8;
    const int b_kB  = ((lane >> 3) & 1) * 16;

    const int l_row = tid >> 2;
    const int l_ch  = tid & 3;
    auto load_stage = [&](int c, int stg) {
        const uint32_t sb = sbase + stg * STAGE_BYTES;
        const int k0 = c * BK;
        uint32_t so = l_row * PITCH + l_ch * 16;
        size_t ga = (size_t)(bm + l_row) * HIDDEN + k0 + l_ch * 16;
        size_t gb = (size_t)(bn + l_row) * HIDDEN + k0 + l_ch * 16;
        cp16(sb + A1_OFF + so, A1g + ga);
        cp16(sb + A0_OFF + so, A0g + ga);
        cp16(sb + B1_OFF + so, B1g + gb);
        cp16(sb + B0_OFF + so, B0g + gb);
        asm volatile("cp.async.commit_group;" ::: "memory");
    };

    int P2[2][4][4], P1[2][4][4];
#pragma unroll
    for (int i = 0; i < 2; i++)
#pragma unroll
        for (int j = 0; j < 4; j++)
#pragma unroll
            for (int q = 0; q < 4; q++) { P2[i][j][q] = 0; P1[i][j][q] = 0; }

    load_stage(0, 0);
    load_stage(1, 1);
    load_stage(2, 2);
    load_stage(3, 3);

    int stg = 0, nstg = NSTAGE - 1;   // stage index of iter c, and load target
#pragma unroll 1
    for (int c = 0; c < KITER; c++) {
        __syncthreads();               // protects reuse of slot consumed at iter c-1

        if (c + NSTAGE - 1 < KITER) load_stage(c + NSTAGE - 1, nstg);
        else asm volatile("cp.async.commit_group;" ::: "memory");

        asm volatile("cp.async.wait_group 4;" ::: "memory");

        const uint32_t sb = sbase + stg * STAGE_BYTES;
        if (++stg == NSTAGE) stg = 0;
        if (++nstg == NSTAGE) nstg = 0;

#pragma unroll
        for (int kh = 0; kh < 2; kh++) {
            const int kb = kh * 32;
            uint32_t b1f[4][2], b0f[4][2];
#pragma unroll
            for (int np = 0; np < 2; np++) {
                int n0 = wn * 32 + np * 16;
                uint32_t ro = (uint32_t)(n0 + b_row) * PITCH + kb + b_kB;
                LDMATRIX_X4(b1f[np * 2][0], b1f[np * 2][1],
                            b1f[np * 2 + 1][0], b1f[np * 2 + 1][1], sb + B1_OFF + ro);
                LDMATRIX_X4(b0f[np * 2][0], b0f[np * 2][1],
                            b0f[np * 2 + 1][0], b0f[np * 2 + 1][1], sb + B0_OFF + ro);
            }
#pragma unroll
            for (int mf = 0; mf < 2; mf++) {
                int r0 = wm * 32 + mf * 16;
                uint32_t ro = (uint32_t)(r0 + a_row) * PITCH + kb + a_kB;
                uint32_t a1f[4], a0f[4];
                LDMATRIX_X4(a1f[0], a1f[1], a1f[2], a1f[3], sb + A1_OFF + ro);
                LDMATRIX_X4(a0f[0], a0f[1], a0f[2], a0f[3], sb + A0_OFF + ro);
#pragma unroll
                for (int nf = 0; nf < 4; nf++) {
                    MMA_S8(P2[mf][nf], a1f, b1f[nf]);
                    MMA_S8(P1[mf][nf], a1f, b0f[nf]);
                    MMA_S8(P1[mf][nf], a0f, b1f[nf]);
                }
            }
        }
    }

    // epilogue
    float lmax = 0.f;
#pragma unroll
    for (int mf = 0; mf < 2; mf++) {
        int r0 = bm + wm * 32 + mf * 16 + gr;
#pragma unroll
        for (int nf = 0; nf < 4; nf++) {
            int cc = bn + wn * 32 + nf * 8 + tg;
            float cv[4];
#pragma unroll
            for (int q = 0; q < 4; q++) {
                cv[q] = csc * (16384.0f * (float)P2[mf][nf][q] + 128.0f * (float)P1[mf][nf][q]);
                if (FUSED && vmax) lmax = fmaxf(lmax, fabsf(cv[q]));
                if (FUSED && sigmoid) cv[q] = 1.f / (1.f + __expf(-cv[q]));
            }
            *reinterpret_cast<float2*>(C + (size_t)r0 * HIDDEN + cc) = make_float2(cv[0], cv[1]);
            *reinterpret_cast<float2*>(C + (size_t)(r0 + 8) * HIDDEN + cc) = make_float2(cv[2], cv[3]);
        }
    }

    if (FUSED && vmax) {
        __syncthreads();
#pragma unroll
        for (int o = 16; o > 0; o >>= 1)
            lmax = fmaxf(lmax, __shfl_xor_sync(0xFFFFFFFF, lmax, o));
        if (lane == 0) atomicMax(&s_vmax, __float_as_uint(lmax));
        __syncthreads();
        if (tid == 0) atomicMax(&g_svb, s_vmax);
    }
}

// ---------------------------------------------------------------------------
// 3) Chunk-parallel WKV scan (LCHUNK=64, NCHUNK=32)
// ---------------------------------------------------------------------------
__global__ void wkv_phase1(const float* __restrict__ td) {
    int idx = blockIdx.x * blockDim.x + threadIdx.x;
    if (idx >= CH * NCHUNK) return;
    int h = idx & (HIDDEN - 1);
    int bc = idx >> 10;                 // b * NCHUNK + c
    int c = bc & (NCHUNK - 1);
    int b = bc >> 5;

    const float w = td[h];
    const size_t base = ((size_t)b * SEQ + (size_t)c * LCHUNK) * HIDDEN + h;
    const float* kp = g_k + base;
    const float* vp = g_v + base;

    float aa = 0.f, bb = 0.f, pp = NEG_INF;
#pragma unroll 4
    for (int t = 0; t < LCHUNK; t++) {
        float k = kp[(size_t)t * HIDDEN];
        float v = vp[(size_t)t * HIDDEN];
        float ww2 = w + pp;
        float p2 = fmaxf(ww2, k);
        float e1 = __expf(ww2 - p2);
        float e2 = __expf(k - p2);
        aa = e1 * aa + e2 * v;
        bb = e1 * bb + e2;
        pp = p2;
    }
    g_saa[idx] = aa;
    g_sbb[idx] = bb;
    g_spp[idx] = pp;
}

__global__ void wkv_phase2(const float* __restrict__ td) {
    int idx = blockIdx.x * blockDim.x + threadIdx.x;
    if (idx >= CH) return;
    int h = idx & (HIDDEN - 1);
    int b = idx >> 10;
    const float wl = td[h] * (float)LCHUNK;

    float aa = 0.f, bb = 0.f, pp = NEG_INF;
#pragma unroll
    for (int c = 0; c < NCHUNK; c++) {
        int s = (b * NCHUNK + c) * HIDDEN + h;
        g_iaa[s] = aa;
        g_ibb[s] = bb;
        g_ipp[s] = pp;
        float laa = g_saa[s], lbb = g_sbb[s], lpp = g_spp[s];
        float sp = pp + wl;
        float p = fmaxf(sp, lpp);
        float e1 = __expf(sp - p);
        float e2 = __expf(lpp - p);
        aa = e1 * aa + e2 * laa;
        bb = e1 * bb + e2 * lbb;
        pp = p;
    }
}

__global__ void wkv_phase3(const float* __restrict__ td,
                           const float* __restrict__ tf) {
    int idx = blockIdx.x * blockDim.x + threadIdx.x;
    if (idx >= CH * NCHUNK) return;
    int h = idx & (HIDDEN - 1);
    int bc = idx >> 10;
    int c = bc & (NCHUNK - 1);
    int b = bc >> 5;

    const float w = td[h];
    const float u = tf[h];
    float sv = __uint_as_float(g_svb);
    float inv = (sv > 0.f) ? (QMAXF / sv) : 0.f;

    const size_t base = ((size_t)b * SEQ + (size_t)c * LCHUNK) * HIDDEN + h;
    const float* kp = g_k + base;
    const float* vp = g_v + base;
    const float* rp = g_r + base;

    float aa = g_iaa[idx], bb = g_ibb[idx], pp = g_ipp[idx];

#pragma unroll 4
    for (int t = 0; t < LCHUNK; t++) {
        size_t off = (size_t)t * HIDDEN;
        float k = kp[off];
        float v = vp[off];

        float ww = u + k;
        float p = fmaxf(pp, ww);
        float e1 = __expf(pp - p);
        float e2 = __expf(ww - p);
        float wkv = (e1 * aa + e2 * v) / (e1 * bb + e2 + 1e-9f);
        float o = rp[off] * wkv;

        float q = rintf(o * inv);
        q = fminf(fmaxf(q, -QMAXF), QMAXF);
        float q1 = rintf(q * 0.0078125f);
        float q0 = q - 128.0f * q1;
        g_o1[base + off] = (int8_t)(int)q1;
        g_o0[base + off] = (int8_t)(int)q0;

        float ww2 = w + pp;
        float p2 = fmaxf(ww2, k);
        float e1b = __expf(ww2 - p2);
        float e2b = __expf(k - p2);
        aa = e1b * aa + e2b * v;
        bb = e1b * bb + e2b;
        pp = p2;
    }
}

// ---------------------------------------------------------------------------
// Launch
// ---------------------------------------------------------------------------
extern "C" void kernel_launch(void* const* d_in, const int* in_sizes, int n_in,
                              void* d_out, int out_size) {
    const float* x  = (const float*)d_in[0];
    const float* td = (const float*)d_in[1];
    const float* tf = (const float*)d_in[2];
    const float* mk = (const float*)d_in[3];
    const float* mv = (const float*)d_in[4];
    const float* mr = (const float*)d_in[5];
    const float* Wk = (const float*)d_in[6];
    const float* Wv = (const float*)d_in[7];
    const float* Wr = (const float*)d_in[8];
    const float* Wo = (const float*)d_in[9];
    float* out = (float*)d_out;

    cudaFuncSetAttribute(gemm_imma<true>,  cudaFuncAttributeMaxDynamicSharedMemorySize, SMEM_TOTAL);
    cudaFuncSetAttribute(gemm_imma<false>, cudaFuncAttributeMaxDynamicSharedMemorySize, SMEM_TOTAL);

    // 0) scales
    init_scales<<<1, 32>>>();
    absmax_all<<<4096 + 4 * 256, 256>>>(x, Wk, Wv, Wr, Wo);

    // 1) merged mix-quant + weight-quant
    prep_quant<<<16384 + 4096, 256>>>(x, mk, mv, mr, Wk, Wv, Wr, Wo);

    // 2) fused k/v/r projections (int8 imma)
    dim3 ggrid(HIDDEN / BN, MTOT / BM, 3);   // (8, 128, 3)
    gemm_imma<true><<<ggrid, GTHREADS, SMEM_TOTAL>>>(nullptr);

    // 3) chunk-parallel wkv (writes int8 limbs of r*wkv)
    wkv_phase1<<<(CH * NCHUNK + 255) / 256, 256>>>(td);
    wkv_phase2<<<(CH + 255) / 256, 256>>>(td);
    wkv_phase3<<<(CH * NCHUNK + 255) / 256, 256>>>(td, tf);

    // 4) output projection
    dim3 ogrid(HIDDEN / BN, MTOT / BM, 1);
    gemm_imma<false><<<ogrid, GTHREADS, SMEM_TOTAL>>>(out);
}

// round 10
// speedup vs baseline: 6.8932x; 1.1437x over previous
#include <cuda_runtime.h>
#include <cuda_bf16.h>
#include <cstdint>

#define HIDDEN 1024
#define BATCH 8
#define SEQ 2048
#define MTOT (BATCH * SEQ)          // 16384 rows
#define NEG_INF -1e38f
#define CH (BATCH * HIDDEN)         // 8192 channels
#define LCHUNK 64
#define NCHUNK (SEQ / LCHUNK)       // 32
#define QMAXF 16256.0f              // 127 * 128

// GEMM tiling (imma m16n8k32, int8 2-limb)
#define BM 128
#define BN 128
#define BK 64
#define KITER (HIDDEN / BK)          // 16
#define PITCH 80
#define TILE_BYTES (BM * PITCH)      // 10240
#define A1_OFF 0
#define A0_OFF TILE_BYTES
#define B1_OFF (2 * TILE_BYTES)
#define B0_OFF (3 * TILE_BYTES)
#define STAGE_BYTES (4 * TILE_BYTES) // 40960
#define NSTAGE 5
#define SMEM_TOTAL (NSTAGE * STAGE_BYTES)   // 204800
#define GTHREADS 512

// ---------------------------------------------------------------------------
// Scratch (device globals)
// ---------------------------------------------------------------------------
__device__ __align__(16) int8_t g_xk1[MTOT * HIDDEN];
__device__ __align__(16) int8_t g_xk0[MTOT * HIDDEN];
__device__ __align__(16) int8_t g_xv1[MTOT * HIDDEN];
__device__ __align__(16) int8_t g_xv0[MTOT * HIDDEN];
__device__ __align__(16) int8_t g_xr1[MTOT * HIDDEN];
__device__ __align__(16) int8_t g_xr0[MTOT * HIDDEN];
__device__ __align__(16) int8_t g_o1 [MTOT * HIDDEN];
__device__ __align__(16) int8_t g_o0 [MTOT * HIDDEN];

__device__ __align__(16) int8_t g_Wk1[HIDDEN * HIDDEN];
__device__ __align__(16) int8_t g_Wk0[HIDDEN * HIDDEN];
__device__ __align__(16) int8_t g_Wv1[HIDDEN * HIDDEN];
__device__ __align__(16) int8_t g_Wv0[HIDDEN * HIDDEN];
__device__ __align__(16) int8_t g_Wr1[HIDDEN * HIDDEN];
__device__ __align__(16) int8_t g_Wr0[HIDDEN * HIDDEN];
__device__ __align__(16) int8_t g_Wo1[HIDDEN * HIDDEN];
__device__ __align__(16) int8_t g_Wo0[HIDDEN * HIDDEN];

__device__ float g_k[MTOT * HIDDEN];
__device__ float g_v[MTOT * HIDDEN];
__device__ float g_r[MTOT * HIDDEN];

__device__ float g_saa[CH * NCHUNK];
__device__ float g_sbb[CH * NCHUNK];
__device__ float g_spp[CH * NCHUNK];
__device__ float g_iaa[CH * NCHUNK];
__device__ float g_ibb[CH * NCHUNK];
__device__ float g_ipp[CH * NCHUNK];

// scale scalars
__device__ unsigned g_sxb;
__device__ unsigned g_swb[4];
__device__ unsigned g_svb;

// ---------------------------------------------------------------------------
// Helpers
// ---------------------------------------------------------------------------
__device__ __forceinline__ uint32_t smem_u32(const void* p) {
    uint32_t a;
    asm("{ .reg .u64 t; cvta.to.shared.u64 t, %1; cvt.u32.u64 %0, t; }"
        : "=r"(a) : "l"(p));
    return a;
}

__device__ __forceinline__ void cp16(uint32_t s, const void* g) {
    asm volatile("cp.async.cg.shared.global [%0], [%1], 16;" :: "r"(s), "l"(g));
}

#define MMA_S8(c, a, b)                                                       \
    asm volatile(                                                             \
        "mma.sync.aligned.m16n8k32.row.col.s32.s8.s8.s32 "                    \
        "{%0,%1,%2,%3},{%4,%5,%6,%7},{%8,%9},{%0,%1,%2,%3};"                  \
        : "+r"((c)[0]), "+r"((c)[1]), "+r"((c)[2]), "+r"((c)[3])              \
        : "r"((a)[0]), "r"((a)[1]), "r"((a)[2]), "r"((a)[3]),                 \
          "r"((b)[0]), "r"((b)[1]))

#define LDMATRIX_X4(r0, r1, r2, r3, addr)                                     \
    asm volatile(                                                             \
        "ldmatrix.sync.aligned.m8n8.x4.shared.b16 {%0,%1,%2,%3}, [%4];"       \
        : "=r"(r0), "=r"(r1), "=r"(r2), "=r"(r3) : "r"(addr))

__device__ __forceinline__ void quant4(const float* v, float inv,
                                       uint32_t& p1, uint32_t& p0) {
    uint32_t r1 = 0, r0 = 0;
#pragma unroll
    for (int j = 0; j < 4; j++) {
        float q = rintf(v[j] * inv);
        q = fminf(fmaxf(q, -QMAXF), QMAXF);
        float q1 = rintf(q * 0.0078125f);      // /128
        float q0 = q - 128.0f * q1;
        r1 |= ((uint32_t)(uint8_t)(int8_t)(int)q1) << (j * 8);
        r0 |= ((uint32_t)(uint8_t)(int8_t)(int)q0) << (j * 8);
    }
    p1 = r1; p0 = r0;
}

// ---------------------------------------------------------------------------
// 0) scale init + absmax
// ---------------------------------------------------------------------------
__global__ void init_scales() {
    if (threadIdx.x == 0) {
        g_sxb = 0; g_svb = 0;
        g_swb[0] = 0; g_swb[1] = 0; g_swb[2] = 0; g_swb[3] = 0;
    }
}

__global__ void absmax_all(const float* __restrict__ x,
                           const float* __restrict__ Wk, const float* __restrict__ Wv,
                           const float* __restrict__ Wr, const float* __restrict__ Wo) {
    __shared__ float sred[8];
    int blk = blockIdx.x;
    const float* base;
    unsigned* target;
    int rel;
    if (blk < 4096)      { base = x;  target = &g_sxb;    rel = blk; }
    else if (blk < 4352) { base = Wk; target = &g_swb[0]; rel = blk - 4096; }
    else if (blk < 4608) { base = Wv; target = &g_swb[1]; rel = blk - 4352; }
    else if (blk < 4864) { base = Wr; target = &g_swb[2]; rel = blk - 4608; }
    else                 { base = Wo; target = &g_swb[3]; rel = blk - 4864; }

    const float4* p = reinterpret_cast<const float4*>(base + (size_t)rel * 4096);
    float m = 0.f;
#pragma unroll
    for (int j = 0; j < 4; j++) {
        float4 v = p[threadIdx.x + j * 256];
        m = fmaxf(m, fmaxf(fmaxf(fabsf(v.x), fabsf(v.y)), fmaxf(fabsf(v.z), fabsf(v.w))));
    }
#pragma unroll
    for (int o = 16; o > 0; o >>= 1)
        m = fmaxf(m, __shfl_xor_sync(0xFFFFFFFF, m, o));
    if ((threadIdx.x & 31) == 0) sred[threadIdx.x >> 5] = m;
    __syncthreads();
    if (threadIdx.x < 8) {
        m = sred[threadIdx.x];
#pragma unroll
        for (int o = 4; o > 0; o >>= 1)
            m = fmaxf(m, __shfl_xor_sync(0xFF, m, o));
        if (threadIdx.x == 0) atomicMax(target, __float_as_uint(m));
    }
}

// ---------------------------------------------------------------------------
// 1) Merged prep: time-mix quant (blocks 0..16383) + weight quant (16384..20479)
// ---------------------------------------------------------------------------
__global__ void prep_quant(const float* __restrict__ x,
                           const float* __restrict__ mk,
                           const float* __restrict__ mv,
                           const float* __restrict__ mr,
                           const float* __restrict__ W0, const float* __restrict__ W1,
                           const float* __restrict__ W2, const float* __restrict__ W3) {
    int blk = blockIdx.x;
    if (blk < 16384) {
        int i = blk * blockDim.x + threadIdx.x;
        int idx = i * 4;
        int h = idx & (HIDDEN - 1);
        int t = (idx / HIDDEN) & (SEQ - 1);

        float sx = __uint_as_float(g_sxb);
        float inv = (sx > 0.f) ? (QMAXF / sx) : 0.f;

        float4 xc = *reinterpret_cast<const float4*>(x + idx);
        float4 xp = (t == 0) ? make_float4(0.f, 0.f, 0.f, 0.f)
                             : *reinterpret_cast<const float4*>(x + idx - HIDDEN);
        float4 k4 = *reinterpret_cast<const float4*>(mk + h);
        float4 v4 = *reinterpret_cast<const float4*>(mv + h);
        float4 r4 = *reinterpret_cast<const float4*>(mr + h);

        float xcf[4] = {xc.x, xc.y, xc.z, xc.w};
        float xpf[4] = {xp.x, xp.y, xp.z, xp.w};
        float kf[4] = {k4.x, k4.y, k4.z, k4.w};
        float vf[4] = {v4.x, v4.y, v4.z, v4.w};
        float rf[4] = {r4.x, r4.y, r4.z, r4.w};
        float ok[4], ov[4], orr[4];
#pragma unroll
        for (int j = 0; j < 4; j++) {
            ok[j]  = xcf[j] * kf[j] + xpf[j] * (1.f - kf[j]);
            ov[j]  = xcf[j] * vf[j] + xpf[j] * (1.f - vf[j]);
            orr[j] = xcf[j] * rf[j] + xpf[j] * (1.f - rf[j]);
        }
        uint32_t p1, p0;
        quant4(ok, inv, p1, p0);
        *reinterpret_cast<uint32_t*>(g_xk1 + idx) = p1;
        *reinterpret_cast<uint32_t*>(g_xk0 + idx) = p0;
        quant4(ov, inv, p1, p0);
        *reinterpret_cast<uint32_t*>(g_xv1 + idx) = p1;
        *reinterpret_cast<uint32_t*>(g_xv0 + idx) = p0;
        quant4(orr, inv, p1, p0);
        *reinterpret_cast<uint32_t*>(g_xr1 + idx) = p1;
        *reinterpret_cast<uint32_t*>(g_xr0 + idx) = p0;
    } else {
        int i = (blk - 16384) * blockDim.x + threadIdx.x;
        int sel = i >> 18;                  // 262144 float4 per weight (2^18)
        int off = (i & 0x3FFFF) * 4;
        const float* W; int8_t *d1, *d0;
        switch (sel) {
            case 0: W = W0; d1 = g_Wk1; d0 = g_Wk0; break;
            case 1: W = W1; d1 = g_Wv1; d0 = g_Wv0; break;
            case 2: W = W2; d1 = g_Wr1; d0 = g_Wr0; break;
            default: W = W3; d1 = g_Wo1; d0 = g_Wo0; break;
        }
        float sw = __uint_as_float(g_swb[sel]);
        float inv = (sw > 0.f) ? (QMAXF / sw) : 0.f;
        float4 w = *reinterpret_cast<const float4*>(W + off);
        float wf[4] = {w.x, w.y, w.z, w.w};
        uint32_t p1, p0;
        quant4(wf, inv, p1, p0);
        *reinterpret_cast<uint32_t*>(d1 + off) = p1;
        *reinterpret_cast<uint32_t*>(d0 + off) = p0;
    }
}

// ---------------------------------------------------------------------------
// 2) int8 IMMA GEMM, 2-limb, 512 threads, 5-slot ring, depth-3 prefetch,
//    __syncthreads every 2 k-iters.
// ---------------------------------------------------------------------------
template <bool FUSED>
__global__ __launch_bounds__(GTHREADS, 1)
void gemm_imma(float* __restrict__ outC) {
    extern __shared__ __align__(128) char smem[];
    __shared__ unsigned s_vmax;

    const int8_t *A1g, *A0g, *B1g, *B0g;
    float* C;
    float sA, sB;
    bool sigmoid = false, vmax = false;
    if (FUSED) {
        int z = blockIdx.z;
        sA = __uint_as_float(g_sxb);
        sB = __uint_as_float(g_swb[z]);
        if (z == 0)      { A1g = g_xk1; A0g = g_xk0; B1g = g_Wk1; B0g = g_Wk0; C = g_k; }
        else if (z == 1) { A1g = g_xv1; A0g = g_xv0; B1g = g_Wv1; B0g = g_Wv0; C = g_v; vmax = true; }
        else             { A1g = g_xr1; A0g = g_xr0; B1g = g_Wr1; B0g = g_Wr0; C = g_r; sigmoid = true; }
    } else {
        A1g = g_o1; A0g = g_o0; B1g = g_Wo1; B0g = g_Wo0; C = outC;
        sA = __uint_as_float(g_svb);
        sB = __uint_as_float(g_swb[3]);
    }
    const float csc = sA * sB / (QMAXF * QMAXF);

    const int tid = threadIdx.x;
    const int wid = tid >> 5;
    const int lane = tid & 31;
    const int wm = wid >> 2;
    const int wn = wid & 3;
    const int gr = lane >> 2;
    const int tg = (lane & 3) * 2;
    const int bm = blockIdx.y * BM;
    const int bn = blockIdx.x * BN;
    const uint32_t sbase = smem_u32(smem);

    if (vmax && tid == 0) s_vmax = 0;

    const int a_row = lane & 15;
    const int a_kB  = (lane >> 4) * 16;
    const int b_row = (lane & 7) + ((lane >> 4) & 1) * 8;
    const int b_kB  = ((lane >> 3) & 1) * 16;

    const int l_row = tid >> 2;
    const int l_ch  = tid & 3;
    auto load_stage = [&](int c, int stg) {
        const uint32_t sb = sbase + stg * STAGE_BYTES;
        const int k0 = c * BK;
        uint32_t so = l_row * PITCH + l_ch * 16;
        size_t ga = (size_t)(bm + l_row) * HIDDEN + k0 + l_ch * 16;
        size_t gb = (size_t)(bn + l_row) * HIDDEN + k0 + l_ch * 16;
        cp16(sb + A1_OFF + so, A1g + ga);
        cp16(sb + A0_OFF + so, A0g + ga);
        cp16(sb + B1_OFF + so, B1g + gb);
        cp16(sb + B0_OFF + so, B0g + gb);
        asm volatile("cp.async.commit_group;" ::: "memory");
    };

    int P2[2][4][4], P1[2][4][4];
#pragma unroll
    for (int i = 0; i < 2; i++)
#pragma unroll
        for (int j = 0; j < 4; j++)
#pragma unroll
            for (int q = 0; q < 4; q++) { P2[i][j][q] = 0; P1[i][j][q] = 0; }

    load_stage(0, 0);
    load_stage(1, 1);
    load_stage(2, 2);

    int stg = 0, nstg = 3;   // stage of iter c; slot for prefetch of c+3
#pragma unroll 1
    for (int c = 0; c < KITER; c++) {
        if ((c & 1) == 0) __syncthreads();   // protects slot reuse (5 slots, 2-iter spread)

        if (c + 3 < KITER) load_stage(c + 3, nstg);
        else asm volatile("cp.async.commit_group;" ::: "memory");

        asm volatile("cp.async.wait_group 3;" ::: "memory");

        const uint32_t sb = sbase + stg * STAGE_BYTES;
        if (++stg == NSTAGE) stg = 0;
        if (++nstg == NSTAGE) nstg = 0;

#pragma unroll
        for (int kh = 0; kh < 2; kh++) {
            const int kb = kh * 32;
            uint32_t b1f[4][2], b0f[4][2];
#pragma unroll
            for (int np = 0; np < 2; np++) {
                int n0 = wn * 32 + np * 16;
                uint32_t ro = (uint32_t)(n0 + b_row) * PITCH + kb + b_kB;
                LDMATRIX_X4(b1f[np * 2][0], b1f[np * 2][1],
                            b1f[np * 2 + 1][0], b1f[np * 2 + 1][1], sb + B1_OFF + ro);
                LDMATRIX_X4(b0f[np * 2][0], b0f[np * 2][1],
                            b0f[np * 2 + 1][0], b0f[np * 2 + 1][1], sb + B0_OFF + ro);
            }
#pragma unroll
            for (int mf = 0; mf < 2; mf++) {
                int r0 = wm * 32 + mf * 16;
                uint32_t ro = (uint32_t)(r0 + a_row) * PITCH + kb + a_kB;
                uint32_t a1f[4], a0f[4];
                LDMATRIX_X4(a1f[0], a1f[1], a1f[2], a1f[3], sb + A1_OFF + ro);
                LDMATRIX_X4(a0f[0], a0f[1], a0f[2], a0f[3], sb + A0_OFF + ro);
#pragma unroll
                for (int nf = 0; nf < 4; nf++) {
                    MMA_S8(P2[mf][nf], a1f, b1f[nf]);
                    MMA_S8(P1[mf][nf], a1f, b0f[nf]);
                    MMA_S8(P1[mf][nf], a0f, b1f[nf]);
                }
            }
        }
    }

    // epilogue
    float lmax = 0.f;
#pragma unroll
    for (int mf = 0; mf < 2; mf++) {
        int r0 = bm + wm * 32 + mf * 16 + gr;
#pragma unroll
        for (int nf = 0; nf < 4; nf++) {
            int cc = bn + wn * 32 + nf * 8 + tg;
            float cv[4];
#pragma unroll
            for (int q = 0; q < 4; q++) {
                cv[q] = csc * (16384.0f * (float)P2[mf][nf][q] + 128.0f * (float)P1[mf][nf][q]);
                if (FUSED && vmax) lmax = fmaxf(lmax, fabsf(cv[q]));
                if (FUSED && sigmoid) cv[q] = 1.f / (1.f + __expf(-cv[q]));
            }
            *reinterpret_cast<float2*>(C + (size_t)r0 * HIDDEN + cc) = make_float2(cv[0], cv[1]);
            *reinterpret_cast<float2*>(C + (size_t)(r0 + 8) * HIDDEN + cc) = make_float2(cv[2], cv[3]);
        }
    }

    if (FUSED && vmax) {
        __syncthreads();
#pragma unroll
        for (int o = 16; o > 0; o >>= 1)
            lmax = fmaxf(lmax, __shfl_xor_sync(0xFFFFFFFF, lmax, o));
        if (lane == 0) atomicMax(&s_vmax, __float_as_uint(lmax));
        __syncthreads();
        if (tid == 0) atomicMax(&g_svb, s_vmax);
    }
}

// ---------------------------------------------------------------------------
// 3) Chunk-parallel WKV scan, 4 channels per thread (ILP across exp chains)
// ---------------------------------------------------------------------------
__global__ void wkv_phase1(const float* __restrict__ td) {
    int idx = blockIdx.x * blockDim.x + threadIdx.x;   // over CH*NCHUNK/4
    if (idx >= CH * NCHUNK / 4) return;
    int h4 = (idx & 255) * 4;
    int bc = idx >> 8;                  // b * NCHUNK + c
    int c = bc & (NCHUNK - 1);
    int b = bc >> 5;

    float4 w4 = *reinterpret_cast<const float4*>(td + h4);
    const float wv[4] = {w4.x, w4.y, w4.z, w4.w};

    const size_t base = ((size_t)b * SEQ + (size_t)c * LCHUNK) * HIDDEN + h4;
    const float* kp = g_k + base;
    const float* vp = g_v + base;

    float aa[4], bb[4], pp[4];
#pragma unroll
    for (int j = 0; j < 4; j++) { aa[j] = 0.f; bb[j] = 0.f; pp[j] = NEG_INF; }

#pragma unroll 2
    for (int t = 0; t < LCHUNK; t++) {
        float4 k4 = *reinterpret_cast<const float4*>(kp + (size_t)t * HIDDEN);
        float4 v4 = *reinterpret_cast<const float4*>(vp + (size_t)t * HIDDEN);
        float kf[4] = {k4.x, k4.y, k4.z, k4.w};
        float vf[4] = {v4.x, v4.y, v4.z, v4.w};
#pragma unroll
        for (int j = 0; j < 4; j++) {
            float ww2 = wv[j] + pp[j];
            float p2 = fmaxf(ww2, kf[j]);
            float e1 = __expf(ww2 - p2);
            float e2 = __expf(kf[j] - p2);
            aa[j] = e1 * aa[j] + e2 * vf[j];
            bb[j] = e1 * bb[j] + e2;
            pp[j] = p2;
        }
    }
    int s = bc * HIDDEN + h4;
    *reinterpret_cast<float4*>(g_saa + s) = make_float4(aa[0], aa[1], aa[2], aa[3]);
    *reinterpret_cast<float4*>(g_sbb + s) = make_float4(bb[0], bb[1], bb[2], bb[3]);
    *reinterpret_cast<float4*>(g_spp + s) = make_float4(pp[0], pp[1], pp[2], pp[3]);
}

__global__ void wkv_phase2(const float* __restrict__ td) {
    int idx = blockIdx.x * blockDim.x + threadIdx.x;
    if (idx >= CH) return;
    int h = idx & (HIDDEN - 1);
    int b = idx >> 10;
    const float wl = td[h] * (float)LCHUNK;

    float aa = 0.f, bb = 0.f, pp = NEG_INF;
#pragma unroll
    for (int c = 0; c < NCHUNK; c++) {
        int s = (b * NCHUNK + c) * HIDDEN + h;
        g_iaa[s] = aa;
        g_ibb[s] = bb;
        g_ipp[s] = pp;
        float laa = g_saa[s], lbb = g_sbb[s], lpp = g_spp[s];
        float sp = pp + wl;
        float p = fmaxf(sp, lpp);
        float e1 = __expf(sp - p);
        float e2 = __expf(lpp - p);
        aa = e1 * aa + e2 * laa;
        bb = e1 * bb + e2 * lbb;
        pp = p;
    }
}

__global__ void wkv_phase3(const float* __restrict__ td,
                           const float* __restrict__ tf) {
    int idx = blockIdx.x * blockDim.x + threadIdx.x;   // over CH*NCHUNK/4
    if (idx >= CH * NCHUNK / 4) return;
    int h4 = (idx & 255) * 4;
    int bc = idx >> 8;
    int c = bc & (NCHUNK - 1);
    int b = bc >> 5;

    float4 w4 = *reinterpret_cast<const float4*>(td + h4);
    float4 u4 = *reinterpret_cast<const float4*>(tf + h4);
    const float wv[4] = {w4.x, w4.y, w4.z, w4.w};
    const float uv[4] = {u4.x, u4.y, u4.z, u4.w};

    float sv = __uint_as_float(g_svb);
    float inv = (sv > 0.f) ? (QMAXF / sv) : 0.f;

    const size_t base = ((size_t)b * SEQ + (size_t)c * LCHUNK) * HIDDEN + h4;
    const float* kp = g_k + base;
    const float* vp = g_v + base;
    const float* rp = g_r + base;

    int s = bc * HIDDEN + h4;
    float4 a4 = *reinterpret_cast<const float4*>(g_iaa + s);
    float4 b4 = *reinterpret_cast<const float4*>(g_ibb + s);
    float4 p4 = *reinterpret_cast<const float4*>(g_ipp + s);
    float aa[4] = {a4.x, a4.y, a4.z, a4.w};
    float bb[4] = {b4.x, b4.y, b4.z, b4.w};
    float pp[4] = {p4.x, p4.y, p4.z, p4.w};

#pragma unroll 2
    for (int t = 0; t < LCHUNK; t++) {
        size_t off = (size_t)t * HIDDEN;
        float4 k4 = *reinterpret_cast<const float4*>(kp + off);
        float4 v4 = *reinterpret_cast<const float4*>(vp + off);
        float4 r4 = *reinterpret_cast<const float4*>(rp + off);
        float kf[4] = {k4.x, k4.y, k4.z, k4.w};
        float vf[4] = {v4.x, v4.y, v4.z, v4.w};
        float rf[4] = {r4.x, r4.y, r4.z, r4.w};
        uint32_t o1 = 0, o0 = 0;
#pragma unroll
        for (int j = 0; j < 4; j++) {
            float ww = uv[j] + kf[j];
            float p = fmaxf(pp[j], ww);
            float e1 = __expf(pp[j] - p);
            float e2 = __expf(ww - p);
            float wkv = (e1 * aa[j] + e2 * vf[j]) / (e1 * bb[j] + e2 + 1e-9f);
            float o = rf[j] * wkv;

            float q = rintf(o * inv);
            q = fminf(fmaxf(q, -QMAXF), QMAXF);
            float q1 = rintf(q * 0.0078125f);
            float q0 = q - 128.0f * q1;
            o1 |= ((uint32_t)(uint8_t)(int8_t)(int)q1) << (j * 8);
            o0 |= ((uint32_t)(uint8_t)(int8_t)(int)q0) << (j * 8);

            float ww2 = wv[j] + pp[j];
            float p2 = fmaxf(ww2, kf[j]);
            float e1b = __expf(ww2 - p2);
            float e2b = __expf(kf[j] - p2);
            aa[j] = e1b * aa[j] + e2b * vf[j];
            bb[j] = e1b * bb[j] + e2b;
            pp[j] = p2;
        }
        *reinterpret_cast<uint32_t*>(g_o1 + base + off) = o1;
        *reinterpret_cast<uint32_t*>(g_o0 + base + off) = o0;
    }
}

// ---------------------------------------------------------------------------
// Launch
// ---------------------------------------------------------------------------
extern "C" void kernel_launch(void* const* d_in, const int* in_sizes, int n_in,
                              void* d_out, int out_size) {
    const float* x  = (const float*)d_in[0];
    const float* td = (const float*)d_in[1];
    const float* tf = (const float*)d_in[2];
    const float* mk = (const float*)d_in[3];
    const float* mv = (const float*)d_in[4];
    const float* mr = (const float*)d_in[5];
    const float* Wk = (const float*)d_in[6];
    const float* Wv = (const float*)d_in[7];
    const float* Wr = (const float*)d_in[8];
    const float* Wo = (const float*)d_in[9];
    float* out = (float*)d_out;

    cudaFuncSetAttribute(gemm_imma<true>,  cudaFuncAttributeMaxDynamicSharedMemorySize, SMEM_TOTAL);
    cudaFuncSetAttribute(gemm_imma<false>, cudaFuncAttributeMaxDynamicSharedMemorySize, SMEM_TOTAL);

    // 0) scales
    init_scales<<<1, 32>>>();
    absmax_all<<<4096 + 4 * 256, 256>>>(x, Wk, Wv, Wr, Wo);

    // 1) merged mix-quant + weight-quant
    prep_quant<<<16384 + 4096, 256>>>(x, mk, mv, mr, Wk, Wv, Wr, Wo);

    // 2) fused k/v/r projections (int8 imma)
    dim3 ggrid(HIDDEN / BN, MTOT / BM, 3);   // (8, 128, 3)
    gemm_imma<true><<<ggrid, GTHREADS, SMEM_TOTAL>>>(nullptr);

    // 3) chunk-parallel wkv (4 channels/thread)
    wkv_phase1<<<(CH * NCHUNK / 4 + 255) / 256, 256>>>(td);
    wkv_phase2<<<(CH + 255) / 256, 256>>>(td);
    wkv_phase3<<<(CH * NCHUNK / 4 + 255) / 256, 256>>>(td, tf);

    // 4) output projection
    dim3 ogrid(HIDDEN / BN, MTOT / BM, 1);
    gemm_imma<false><<<ogrid, GTHREADS, SMEM_TOTAL>>>(out);
}

// round 11
// speedup vs baseline: 6.9446x; 1.0075x over previous
#include <cuda_runtime.h>
#include <cuda_bf16.h>
#include <cstdint>

#define HIDDEN 1024
#define BATCH 8
#define SEQ 2048
#define MTOT (BATCH * SEQ)          // 16384 rows
#define NEG_INF -1e38f
#define CH (BATCH * HIDDEN)         // 8192 channels
#define LCHUNK 64
#define NCHUNK (SEQ / LCHUNK)       // 32
#define QMAXF 16256.0f              // 127 * 128

// GEMM tiling (imma m16n8k32, int8 2-limb)
#define BM 128
#define BN 128
#define BK 64
#define KITER (HIDDEN / BK)          // 16
#define PITCH 80
#define TILE_BYTES (BM * PITCH)      // 10240
#define A1_OFF 0
#define A0_OFF TILE_BYTES
#define B1_OFF (2 * TILE_BYTES)
#define B0_OFF (3 * TILE_BYTES)
#define STAGE_BYTES (4 * TILE_BYTES) // 40960
#define NSTAGE 5
#define SMEM_TOTAL (NSTAGE * STAGE_BYTES)   // 204800
#define GTHREADS 512

// ---------------------------------------------------------------------------
// Scratch (device globals)
// ---------------------------------------------------------------------------
__device__ __align__(16) int8_t g_xk1[MTOT * HIDDEN];
__device__ __align__(16) int8_t g_xk0[MTOT * HIDDEN];
__device__ __align__(16) int8_t g_xv1[MTOT * HIDDEN];
__device__ __align__(16) int8_t g_xv0[MTOT * HIDDEN];
__device__ __align__(16) int8_t g_xr1[MTOT * HIDDEN];
__device__ __align__(16) int8_t g_xr0[MTOT * HIDDEN];
__device__ __align__(16) int8_t g_o1 [MTOT * HIDDEN];
__device__ __align__(16) int8_t g_o0 [MTOT * HIDDEN];

__device__ __align__(16) int8_t g_Wk1[HIDDEN * HIDDEN];
__device__ __align__(16) int8_t g_Wk0[HIDDEN * HIDDEN];
__device__ __align__(16) int8_t g_Wv1[HIDDEN * HIDDEN];
__device__ __align__(16) int8_t g_Wv0[HIDDEN * HIDDEN];
__device__ __align__(16) int8_t g_Wr1[HIDDEN * HIDDEN];
__device__ __align__(16) int8_t g_Wr0[HIDDEN * HIDDEN];
__device__ __align__(16) int8_t g_Wo1[HIDDEN * HIDDEN];
__device__ __align__(16) int8_t g_Wo0[HIDDEN * HIDDEN];

__device__ float g_k[MTOT * HIDDEN];
__device__ float g_v[MTOT * HIDDEN];
__device__ float g_r[MTOT * HIDDEN];

__device__ float g_saa[CH * NCHUNK];
__device__ float g_sbb[CH * NCHUNK];
__device__ float g_spp[CH * NCHUNK];
__device__ float g_iaa[CH * NCHUNK];
__device__ float g_ibb[CH * NCHUNK];
__device__ float g_ipp[CH * NCHUNK];

// fine-grained scales
__device__ float g_xsc[MTOT];          // per token-row absmax of x (bounds mixes)
__device__ float g_wsc[4 * HIDDEN];    // per output-row absmax of each W
__device__ unsigned g_svb;             // global max|v| (bounds r*wkv)

// ---------------------------------------------------------------------------
// Helpers
// ---------------------------------------------------------------------------
__device__ __forceinline__ uint32_t smem_u32(const void* p) {
    uint32_t a;
    asm("{ .reg .u64 t; cvta.to.shared.u64 t, %1; cvt.u32.u64 %0, t; }"
        : "=r"(a) : "l"(p));
    return a;
}

__device__ __forceinline__ void cp16(uint32_t s, const void* g) {
    asm volatile("cp.async.cg.shared.global [%0], [%1], 16;" :: "r"(s), "l"(g));
}

#define MMA_S8(c, a, b)                                                       \
    asm volatile(                                                             \
        "mma.sync.aligned.m16n8k32.row.col.s32.s8.s8.s32 "                    \
        "{%0,%1,%2,%3},{%4,%5,%6,%7},{%8,%9},{%0,%1,%2,%3};"                  \
        : "+r"((c)[0]), "+r"((c)[1]), "+r"((c)[2]), "+r"((c)[3])              \
        : "r"((a)[0]), "r"((a)[1]), "r"((a)[2]), "r"((a)[3]),                 \
          "r"((b)[0]), "r"((b)[1]))

#define LDMATRIX_X4(r0, r1, r2, r3, addr)                                     \
    asm volatile(                                                             \
        "ldmatrix.sync.aligned.m8n8.x4.shared.b16 {%0,%1,%2,%3}, [%4];"       \
        : "=r"(r0), "=r"(r1), "=r"(r2), "=r"(r3) : "r"(addr))

__device__ __forceinline__ void quant4(const float* v, float inv,
                                       uint32_t& p1, uint32_t& p0) {
    uint32_t r1 = 0, r0 = 0;
#pragma unroll
    for (int j = 0; j < 4; j++) {
        float q = rintf(v[j] * inv);
        q = fminf(fmaxf(q, -QMAXF), QMAXF);
        float q1 = rintf(q * 0.0078125f);      // /128
        float q0 = q - 128.0f * q1;
        r1 |= ((uint32_t)(uint8_t)(int8_t)(int)q1) << (j * 8);
        r0 |= ((uint32_t)(uint8_t)(int8_t)(int)q0) << (j * 8);
    }
    p1 = r1; p0 = r0;
}

// block max over 256 threads; returns broadcast value
__device__ __forceinline__ float block_max256(float m, float* sred, float* sbc) {
    int tid = threadIdx.x;
#pragma unroll
    for (int o = 16; o > 0; o >>= 1)
        m = fmaxf(m, __shfl_xor_sync(0xFFFFFFFF, m, o));
    if ((tid & 31) == 0) sred[tid >> 5] = m;
    __syncthreads();
    if (tid < 8) {
        m = sred[tid];
#pragma unroll
        for (int o = 4; o > 0; o >>= 1)
            m = fmaxf(m, __shfl_xor_sync(0xFF, m, o));
        if (tid == 0) *sbc = m;
    }
    __syncthreads();
    return *sbc;
}

// ---------------------------------------------------------------------------
// 1) Prep: per-row mix quant (blocks 0..16383, one block per token row)
//          + per-row weight quant (blocks 16384..20479, one per W output row)
// ---------------------------------------------------------------------------
__global__ void prep_quant(const float* __restrict__ x,
                           const float* __restrict__ mk,
                           const float* __restrict__ mv,
                           const float* __restrict__ mr,
                           const float* __restrict__ W0, const float* __restrict__ W1,
                           const float* __restrict__ W2, const float* __restrict__ W3) {
    __shared__ float sred[8];
    __shared__ float sbc;
    int blk = blockIdx.x;
    int tid = threadIdx.x;
    if (blk == 0 && tid == 0) g_svb = 0;   // reset v-scale for this invocation

    if (blk < MTOT) {
        int m = blk;                       // token row
        int t = m & (SEQ - 1);
        size_t idx = (size_t)m * HIDDEN + tid * 4;
        int h = tid * 4;

        float4 xc = *reinterpret_cast<const float4*>(x + idx);
        float4 xp = (t == 0) ? make_float4(0.f, 0.f, 0.f, 0.f)
                             : *reinterpret_cast<const float4*>(x + idx - HIDDEN);

        float lm = fmaxf(fmaxf(fmaxf(fabsf(xc.x), fabsf(xc.y)),
                               fmaxf(fabsf(xc.z), fabsf(xc.w))),
                         fmaxf(fmaxf(fabsf(xp.x), fabsf(xp.y)),
                               fmaxf(fabsf(xp.z), fabsf(xp.w))));
        float rmax = block_max256(lm, sred, &sbc);
        if (tid == 0) g_xsc[m] = rmax;
        float inv = (rmax > 0.f) ? (QMAXF / rmax) : 0.f;

        float4 k4 = *reinterpret_cast<const float4*>(mk + h);
        float4 v4 = *reinterpret_cast<const float4*>(mv + h);
        float4 r4 = *reinterpret_cast<const float4*>(mr + h);

        float xcf[4] = {xc.x, xc.y, xc.z, xc.w};
        float xpf[4] = {xp.x, xp.y, xp.z, xp.w};
        float kf[4] = {k4.x, k4.y, k4.z, k4.w};
        float vf[4] = {v4.x, v4.y, v4.z, v4.w};
        float rf[4] = {r4.x, r4.y, r4.z, r4.w};
        float ok[4], ov[4], orr[4];
#pragma unroll
        for (int j = 0; j < 4; j++) {
            ok[j]  = xcf[j] * kf[j] + xpf[j] * (1.f - kf[j]);
            ov[j]  = xcf[j] * vf[j] + xpf[j] * (1.f - vf[j]);
            orr[j] = xcf[j] * rf[j] + xpf[j] * (1.f - rf[j]);
        }
        uint32_t p1, p0;
        quant4(ok, inv, p1, p0);
        *reinterpret_cast<uint32_t*>(g_xk1 + idx) = p1;
        *reinterpret_cast<uint32_t*>(g_xk0 + idx) = p0;
        quant4(ov, inv, p1, p0);
        *reinterpret_cast<uint32_t*>(g_xv1 + idx) = p1;
        *reinterpret_cast<uint32_t*>(g_xv0 + idx) = p0;
        quant4(orr, inv, p1, p0);
        *reinterpret_cast<uint32_t*>(g_xr1 + idx) = p1;
        *reinterpret_cast<uint32_t*>(g_xr0 + idx) = p0;
    } else {
        int w = blk - MTOT;                // 0..4095
        int sel = w >> 10;
        int n = w & (HIDDEN - 1);
        const float* W; int8_t *d1, *d0;
        switch (sel) {
            case 0: W = W0; d1 = g_Wk1; d0 = g_Wk0; break;
            case 1: W = W1; d1 = g_Wv1; d0 = g_Wv0; break;
            case 2: W = W2; d1 = g_Wr1; d0 = g_Wr0; break;
            default: W = W3; d1 = g_Wo1; d0 = g_Wo0; break;
        }
        size_t idx = (size_t)n * HIDDEN + tid * 4;
        float4 wvv = *reinterpret_cast<const float4*>(W + idx);
        float lm = fmaxf(fmaxf(fabsf(wvv.x), fabsf(wvv.y)),
                         fmaxf(fabsf(wvv.z), fabsf(wvv.w)));
        float rmax = block_max256(lm, sred, &sbc);
        if (tid == 0) g_wsc[w] = rmax;
        float inv = (rmax > 0.f) ? (QMAXF / rmax) : 0.f;

        float wf[4] = {wvv.x, wvv.y, wvv.z, wvv.w};
        uint32_t p1, p0;
        quant4(wf, inv, p1, p0);
        *reinterpret_cast<uint32_t*>(d1 + idx) = p1;
        *reinterpret_cast<uint32_t*>(d0 + idx) = p0;
    }
}

// ---------------------------------------------------------------------------
// 2) int8 IMMA GEMM, 2-limb, 512 threads, 5-slot ring, depth-3 prefetch,
//    __syncthreads every 2 k-iters. Per-row x per-col scales in epilogue.
// ---------------------------------------------------------------------------
template <bool FUSED>
__global__ __launch_bounds__(GTHREADS, 1)
void gemm_imma(float* __restrict__ outC) {
    extern __shared__ __align__(128) char smem[];
    __shared__ unsigned s_vmax;

    const int8_t *A1g, *A0g, *B1g, *B0g;
    float* C;
    const float* wscp;
    float sA = 0.f;
    bool sigmoid = false, vmax = false;
    if (FUSED) {
        int z = blockIdx.z;
        wscp = g_wsc + z * HIDDEN;
        if (z == 0)      { A1g = g_xk1; A0g = g_xk0; B1g = g_Wk1; B0g = g_Wk0; C = g_k; }
        else if (z == 1) { A1g = g_xv1; A0g = g_xv0; B1g = g_Wv1; B0g = g_Wv0; C = g_v; vmax = true; }
        else             { A1g = g_xr1; A0g = g_xr0; B1g = g_Wr1; B0g = g_Wr0; C = g_r; sigmoid = true; }
    } else {
        A1g = g_o1; A0g = g_o0; B1g = g_Wo1; B0g = g_Wo0; C = outC;
        wscp = g_wsc + 3 * HIDDEN;
        sA = __uint_as_float(g_svb);
    }
    const float qi2 = 1.0f / (QMAXF * QMAXF);

    const int tid = threadIdx.x;
    const int wid = tid >> 5;
    const int lane = tid & 31;
    const int wm = wid >> 2;
    const int wn = wid & 3;
    const int gr = lane >> 2;
    const int tg = (lane & 3) * 2;
    const int bm = blockIdx.y * BM;
    const int bn = blockIdx.x * BN;
    const uint32_t sbase = smem_u32(smem);

    if (vmax && tid == 0) s_vmax = 0;

    const int a_row = lane & 15;
    const int a_kB  = (lane >> 4) * 16;
    const int b_row = (lane & 7) + ((lane >> 4) & 1) * 8;
    const int b_kB  = ((lane >> 3) & 1) * 16;

    const int l_row = tid >> 2;
    const int l_ch  = tid & 3;
    auto load_stage = [&](int c, int stg) {
        const uint32_t sb = sbase + stg * STAGE_BYTES;
        const int k0 = c * BK;
        uint32_t so = l_row * PITCH + l_ch * 16;
        size_t ga = (size_t)(bm + l_row) * HIDDEN + k0 + l_ch * 16;
        size_t gb = (size_t)(bn + l_row) * HIDDEN + k0 + l_ch * 16;
        cp16(sb + A1_OFF + so, A1g + ga);
        cp16(sb + A0_OFF + so, A0g + ga);
        cp16(sb + B1_OFF + so, B1g + gb);
        cp16(sb + B0_OFF + so, B0g + gb);
        asm volatile("cp.async.commit_group;" ::: "memory");
    };

    int P2[2][4][4], P1[2][4][4];
#pragma unroll
    for (int i = 0; i < 2; i++)
#pragma unroll
        for (int j = 0; j < 4; j++)
#pragma unroll
            for (int q = 0; q < 4; q++) { P2[i][j][q] = 0; P1[i][j][q] = 0; }

    load_stage(0, 0);
    load_stage(1, 1);
    load_stage(2, 2);

    int stg = 0, nstg = 3;
#pragma unroll 1
    for (int c = 0; c < KITER; c++) {
        if ((c & 1) == 0) __syncthreads();

        if (c + 3 < KITER) load_stage(c + 3, nstg);
        else asm volatile("cp.async.commit_group;" ::: "memory");

        asm volatile("cp.async.wait_group 3;" ::: "memory");

        const uint32_t sb = sbase + stg * STAGE_BYTES;
        if (++stg == NSTAGE) stg = 0;
        if (++nstg == NSTAGE) nstg = 0;

#pragma unroll
        for (int kh = 0; kh < 2; kh++) {
            const int kb = kh * 32;
            uint32_t b1f[4][2], b0f[4][2];
#pragma unroll
            for (int np = 0; np < 2; np++) {
                int n0 = wn * 32 + np * 16;
                uint32_t ro = (uint32_t)(n0 + b_row) * PITCH + kb + b_kB;
                LDMATRIX_X4(b1f[np * 2][0], b1f[np * 2][1],
                            b1f[np * 2 + 1][0], b1f[np * 2 + 1][1], sb + B1_OFF + ro);
                LDMATRIX_X4(b0f[np * 2][0], b0f[np * 2][1],
                            b0f[np * 2 + 1][0], b0f[np * 2 + 1][1], sb + B0_OFF + ro);
            }
#pragma unroll
            for (int mf = 0; mf < 2; mf++) {
                int r0 = wm * 32 + mf * 16;
                uint32_t ro = (uint32_t)(r0 + a_row) * PITCH + kb + a_kB;
                uint32_t a1f[4], a0f[4];
                LDMATRIX_X4(a1f[0], a1f[1], a1f[2], a1f[3], sb + A1_OFF + ro);
                LDMATRIX_X4(a0f[0], a0f[1], a0f[2], a0f[3], sb + A0_OFF + ro);
#pragma unroll
                for (int nf = 0; nf < 4; nf++) {
                    MMA_S8(P2[mf][nf], a1f, b1f[nf]);
                    MMA_S8(P1[mf][nf], a1f, b0f[nf]);
                    MMA_S8(P1[mf][nf], a0f, b1f[nf]);
                }
            }
        }
    }

    // epilogue: per-row (A) x per-col (B) scales
    float lmax = 0.f;
#pragma unroll
    for (int mf = 0; mf < 2; mf++) {
        int r0 = bm + wm * 32 + mf * 16 + gr;
        float ra = FUSED ? g_xsc[r0] : sA;
        float rb = FUSED ? g_xsc[r0 + 8] : sA;
#pragma unroll
        for (int nf = 0; nf < 4; nf++) {
            int cc = bn + wn * 32 + nf * 8 + tg;
            float cs0 = wscp[cc] * qi2;
            float cs1 = wscp[cc + 1] * qi2;
            float cv[4];
            cv[0] = ra * cs0 * (16384.0f * (float)P2[mf][nf][0] + 128.0f * (float)P1[mf][nf][0]);
            cv[1] = ra * cs1 * (16384.0f * (float)P2[mf][nf][1] + 128.0f * (float)P1[mf][nf][1]);
            cv[2] = rb * cs0 * (16384.0f * (float)P2[mf][nf][2] + 128.0f * (float)P1[mf][nf][2]);
            cv[3] = rb * cs1 * (16384.0f * (float)P2[mf][nf][3] + 128.0f * (float)P1[mf][nf][3]);
#pragma unroll
            for (int q = 0; q < 4; q++) {
                if (FUSED && vmax) lmax = fmaxf(lmax, fabsf(cv[q]));
                if (FUSED && sigmoid) cv[q] = 1.f / (1.f + __expf(-cv[q]));
            }
            *reinterpret_cast<float2*>(C + (size_t)r0 * HIDDEN + cc) = make_float2(cv[0], cv[1]);
            *reinterpret_cast<float2*>(C + (size_t)(r0 + 8) * HIDDEN + cc) = make_float2(cv[2], cv[3]);
        }
    }

    if (FUSED && vmax) {
        __syncthreads();
#pragma unroll
        for (int o = 16; o > 0; o >>= 1)
            lmax = fmaxf(lmax, __shfl_xor_sync(0xFFFFFFFF, lmax, o));
        if (lane == 0) atomicMax(&s_vmax, __float_as_uint(lmax));
        __syncthreads();
        if (tid == 0) atomicMax(&g_svb, s_vmax);
    }
}

// ---------------------------------------------------------------------------
// 3) Chunk-parallel WKV scan, 4 channels per thread (ILP across exp chains)
// ---------------------------------------------------------------------------
__global__ void wkv_phase1(const float* __restrict__ td) {
    int idx = blockIdx.x * blockDim.x + threadIdx.x;   // over CH*NCHUNK/4
    if (idx >= CH * NCHUNK / 4) return;
    int h4 = (idx & 255) * 4;
    int bc = idx >> 8;                  // b * NCHUNK + c
    int c = bc & (NCHUNK - 1);
    int b = bc >> 5;

    float4 w4 = *reinterpret_cast<const float4*>(td + h4);
    const float wv[4] = {w4.x, w4.y, w4.z, w4.w};

    const size_t base = ((size_t)b * SEQ + (size_t)c * LCHUNK) * HIDDEN + h4;
    const float* kp = g_k + base;
    const float* vp = g_v + base;

    float aa[4], bb[4], pp[4];
#pragma unroll
    for (int j = 0; j < 4; j++) { aa[j] = 0.f; bb[j] = 0.f; pp[j] = NEG_INF; }

#pragma unroll 2
    for (int t = 0; t < LCHUNK; t++) {
        float4 k4 = *reinterpret_cast<const float4*>(kp + (size_t)t * HIDDEN);
        float4 v4 = *reinterpret_cast<const float4*>(vp + (size_t)t * HIDDEN);
        float kf[4] = {k4.x, k4.y, k4.z, k4.w};
        float vf[4] = {v4.x, v4.y, v4.z, v4.w};
#pragma unroll
        for (int j = 0; j < 4; j++) {
            float ww2 = wv[j] + pp[j];
            float p2 = fmaxf(ww2, kf[j]);
            float e1 = __expf(ww2 - p2);
            float e2 = __expf(kf[j] - p2);
            aa[j] = e1 * aa[j] + e2 * vf[j];
            bb[j] = e1 * bb[j] + e2;
            pp[j] = p2;
        }
    }
    int s = bc * HIDDEN + h4;
    *reinterpret_cast<float4*>(g_saa + s) = make_float4(aa[0], aa[1], aa[2], aa[3]);
    *reinterpret_cast<float4*>(g_sbb + s) = make_float4(bb[0], bb[1], bb[2], bb[3]);
    *reinterpret_cast<float4*>(g_spp + s) = make_float4(pp[0], pp[1], pp[2], pp[3]);
}

__global__ void wkv_phase2(const float* __restrict__ td) {
    int idx = blockIdx.x * blockDim.x + threadIdx.x;
    if (idx >= CH) return;
    int h = idx & (HIDDEN - 1);
    int b = idx >> 10;
    const float wl = td[h] * (float)LCHUNK;

    float aa = 0.f, bb = 0.f, pp = NEG_INF;
#pragma unroll
    for (int c = 0; c < NCHUNK; c++) {
        int s = (b * NCHUNK + c) * HIDDEN + h;
        g_iaa[s] = aa;
        g_ibb[s] = bb;
        g_ipp[s] = pp;
        float laa = g_saa[s], lbb = g_sbb[s], lpp = g_spp[s];
        float sp = pp + wl;
        float p = fmaxf(sp, lpp);
        float e1 = __expf(sp - p);
        float e2 = __expf(lpp - p);
        aa = e1 * aa + e2 * laa;
        bb = e1 * bb + e2 * lbb;
        pp = p;
    }
}

__global__ void wkv_phase3(const float* __restrict__ td,
                           const float* __restrict__ tf) {
    int idx = blockIdx.x * blockDim.x + threadIdx.x;   // over CH*NCHUNK/4
    if (idx >= CH * NCHUNK / 4) return;
    int h4 = (idx & 255) * 4;
    int bc = idx >> 8;
    int c = bc & (NCHUNK - 1);
    int b = bc >> 5;

    float4 w4 = *reinterpret_cast<const float4*>(td + h4);
    float4 u4 = *reinterpret_cast<const float4*>(tf + h4);
    const float wv[4] = {w4.x, w4.y, w4.z, w4.w};
    const float uv[4] = {u4.x, u4.y, u4.z, u4.w};

    float sv = __uint_as_float(g_svb);
    float inv = (sv > 0.f) ? (QMAXF / sv) : 0.f;

    const size_t base = ((size_t)b * SEQ + (size_t)c * LCHUNK) * HIDDEN + h4;
    const float* kp = g_k + base;
    const float* vp = g_v + base;
    const float* rp = g_r + base;

    int s = bc * HIDDEN + h4;
    float4 a4 = *reinterpret_cast<const float4*>(g_iaa + s);
    float4 b4 = *reinterpret_cast<const float4*>(g_ibb + s);
    float4 p4 = *reinterpret_cast<const float4*>(g_ipp + s);
    float aa[4] = {a4.x, a4.y, a4.z, a4.w};
    float bb[4] = {b4.x, b4.y, b4.z, b4.w};
    float pp[4] = {p4.x, p4.y, p4.z, p4.w};

#pragma unroll 2
    for (int t = 0; t < LCHUNK; t++) {
        size_t off = (size_t)t * HIDDEN;
        float4 k4 = *reinterpret_cast<const float4*>(kp + off);
        float4 v4 = *reinterpret_cast<const float4*>(vp + off);
        float4 r4 = *reinterpret_cast<const float4*>(rp + off);
        float kf[4] = {k4.x, k4.y, k4.z, k4.w};
        float vf[4] = {v4.x, v4.y, v4.z, v4.w};
        float rf[4] = {r4.x, r4.y, r4.z, r4.w};
        uint32_t o1 = 0, o0 = 0;
#pragma unroll
        for (int j = 0; j < 4; j++) {
            float ww = uv[j] + kf[j];
            float p = fmaxf(pp[j], ww);
            float e1 = __expf(pp[j] - p);
            float e2 = __expf(ww - p);
            float wkv = (e1 * aa[j] + e2 * vf[j]) / (e1 * bb[j] + e2 + 1e-9f);
            float o = rf[j] * wkv;

            float q = rintf(o * inv);
            q = fminf(fmaxf(q, -QMAXF), QMAXF);
            float q1 = rintf(q * 0.0078125f);
            float q0 = q - 128.0f * q1;
            o1 |= ((uint32_t)(uint8_t)(int8_t)(int)q1) << (j * 8);
            o0 |= ((uint32_t)(uint8_t)(int8_t)(int)q0) << (j * 8);

            float ww2 = wv[j] + pp[j];
            float p2 = fmaxf(ww2, kf[j]);
            float e1b = __expf(ww2 - p2);
            float e2b = __expf(kf[j] - p2);
            aa[j] = e1b * aa[j] + e2b * vf[j];
            bb[j] = e1b * bb[j] + e2b;
            pp[j] = p2;
        }
        *reinterpret_cast<uint32_t*>(g_o1 + base + off) = o1;
        *reinterpret_cast<uint32_t*>(g_o0 + base + off) = o0;
    }
}

// ---------------------------------------------------------------------------
// Launch
// ---------------------------------------------------------------------------
extern "C" void kernel_launch(void* const* d_in, const int* in_sizes, int n_in,
                              void* d_out, int out_size) {
    const float* x  = (const float*)d_in[0];
    const float* td = (const float*)d_in[1];
    const float* tf = (const float*)d_in[2];
    const float* mk = (const float*)d_in[3];
    const float* mv = (const float*)d_in[4];
    const float* mr = (const float*)d_in[5];
    const float* Wk = (const float*)d_in[6];
    const float* Wv = (const float*)d_in[7];
    const float* Wr = (const float*)d_in[8];
    const float* Wo = (const float*)d_in[9];
    float* out = (float*)d_out;

    cudaFuncSetAttribute(gemm_imma<true>,  cudaFuncAttributeMaxDynamicSharedMemorySize, SMEM_TOTAL);
    cudaFuncSetAttribute(gemm_imma<false>, cudaFuncAttributeMaxDynamicSharedMemorySize, SMEM_TOTAL);

    // 1) prep: per-row mix quant + per-row weight quant (also resets g_svb)
    prep_quant<<<MTOT + 4 * HIDDEN, 256>>>(x, mk, mv, mr, Wk, Wv, Wr, Wo);

    // 2) fused k/v/r projections (int8 imma)
    dim3 ggrid(HIDDEN / BN, MTOT / BM, 3);   // (8, 128, 3)
    gemm_imma<true><<<ggrid, GTHREADS, SMEM_TOTAL>>>(nullptr);

    // 3) chunk-parallel wkv (4 channels/thread)
    wkv_phase1<<<(CH * NCHUNK / 4 + 255) / 256, 256>>>(td);
    wkv_phase2<<<(CH + 255) / 256, 256>>>(td);
    wkv_phase3<<<(CH * NCHUNK / 4 + 255) / 256, 256>>>(td, tf);

    // 4) output projection
    dim3 ogrid(HIDDEN / BN, MTOT / BM, 1);
    gemm_imma<false><<<ogrid, GTHREADS, SMEM_TOTAL>>>(out);
}

// round 12
// speedup vs baseline: 7.0294x; 1.0122x over previous
#include <cuda_runtime.h>
#include <cuda_bf16.h>
#include <cstdint>

#define HIDDEN 1024
#define BATCH 8
#define SEQ 2048
#define MTOT (BATCH * SEQ)          // 16384 rows
#define NEG_INF -1e38f
#define CH (BATCH * HIDDEN)         // 8192 channels
#define LCHUNK 64
#define NCHUNK (SEQ / LCHUNK)       // 32
#define QMAXF 16256.0f              // 127 * 128

// GEMM tiling (imma m16n8k32, int8 2-limb)
#define BM 128
#define BN 128
#define BK 64
#define KITER (HIDDEN / BK)          // 16
#define PITCH 80
#define TILE_BYTES (BM * PITCH)      // 10240
#define A1_OFF 0
#define A0_OFF TILE_BYTES
#define B1_OFF (2 * TILE_BYTES)
#define B0_OFF (3 * TILE_BYTES)
#define STAGE_BYTES (4 * TILE_BYTES) // 40960
#define NSTAGE 5
#define SMEM_TOTAL (NSTAGE * STAGE_BYTES)   // 204800
#define GTHREADS 512

// ---------------------------------------------------------------------------
// Scratch (device globals)
// ---------------------------------------------------------------------------
__device__ __align__(16) int8_t g_xk1[MTOT * HIDDEN];
__device__ __align__(16) int8_t g_xk0[MTOT * HIDDEN];
__device__ __align__(16) int8_t g_xv1[MTOT * HIDDEN];
__device__ __align__(16) int8_t g_xv0[MTOT * HIDDEN];
__device__ __align__(16) int8_t g_xr1[MTOT * HIDDEN];
__device__ __align__(16) int8_t g_xr0[MTOT * HIDDEN];
__device__ __align__(16) int8_t g_o1 [MTOT * HIDDEN];
__device__ __align__(16) int8_t g_o0 [MTOT * HIDDEN];

__device__ __align__(16) int8_t g_Wk1[HIDDEN * HIDDEN];
__device__ __align__(16) int8_t g_Wk0[HIDDEN * HIDDEN];
__device__ __align__(16) int8_t g_Wv1[HIDDEN * HIDDEN];
__device__ __align__(16) int8_t g_Wv0[HIDDEN * HIDDEN];
__device__ __align__(16) int8_t g_Wr1[HIDDEN * HIDDEN];
__device__ __align__(16) int8_t g_Wr0[HIDDEN * HIDDEN];
__device__ __align__(16) int8_t g_Wo1[HIDDEN * HIDDEN];
__device__ __align__(16) int8_t g_Wo0[HIDDEN * HIDDEN];

__device__ float g_k[MTOT * HIDDEN];
__device__ float g_v[MTOT * HIDDEN];
__device__ float g_r[MTOT * HIDDEN];

__device__ float g_saa[CH * NCHUNK];
__device__ float g_sbb[CH * NCHUNK];
__device__ float g_spp[CH * NCHUNK];
__device__ float g_iaa[CH * NCHUNK];
__device__ float g_ibb[CH * NCHUNK];
__device__ float g_ipp[CH * NCHUNK];

// fine-grained scales
__device__ float g_xsc[MTOT];          // per token-row absmax of x (bounds mixes)
__device__ float g_wsc[4 * HIDDEN];    // per output-row absmax of each W
__device__ unsigned g_svb;             // global max|v| (bounds r*wkv)

// ---------------------------------------------------------------------------
// Helpers
// ---------------------------------------------------------------------------
__device__ __forceinline__ uint32_t smem_u32(const void* p) {
    uint32_t a;
    asm("{ .reg .u64 t; cvta.to.shared.u64 t, %1; cvt.u32.u64 %0, t; }"
        : "=r"(a) : "l"(p));
    return a;
}

__device__ __forceinline__ void cp16(uint32_t s, const void* g) {
    asm volatile("cp.async.cg.shared.global [%0], [%1], 16;" :: "r"(s), "l"(g));
}

#define MMA_S8(c, a, b)                                                       \
    asm volatile(                                                             \
        "mma.sync.aligned.m16n8k32.row.col.s32.s8.s8.s32 "                    \
        "{%0,%1,%2,%3},{%4,%5,%6,%7},{%8,%9},{%0,%1,%2,%3};"                  \
        : "+r"((c)[0]), "+r"((c)[1]), "+r"((c)[2]), "+r"((c)[3])              \
        : "r"((a)[0]), "r"((a)[1]), "r"((a)[2]), "r"((a)[3]),                 \
          "r"((b)[0]), "r"((b)[1]))

#define LDMATRIX_X4(r0, r1, r2, r3, addr)                                     \
    asm volatile(                                                             \
        "ldmatrix.sync.aligned.m8n8.x4.shared.b16 {%0,%1,%2,%3}, [%4];"       \
        : "=r"(r0), "=r"(r1), "=r"(r2), "=r"(r3) : "r"(addr))

__device__ __forceinline__ void quant4(const float* v, float inv,
                                       uint32_t& p1, uint32_t& p0) {
    uint32_t r1 = 0, r0 = 0;
#pragma unroll
    for (int j = 0; j < 4; j++) {
        float q = rintf(v[j] * inv);
        q = fminf(fmaxf(q, -QMAXF), QMAXF);
        float q1 = rintf(q * 0.0078125f);      // /128
        float q0 = q - 128.0f * q1;
        r1 |= ((uint32_t)(uint8_t)(int8_t)(int)q1) << (j * 8);
        r0 |= ((uint32_t)(uint8_t)(int8_t)(int)q0) << (j * 8);
    }
    p1 = r1; p0 = r0;
}

// block max over 256 threads; returns broadcast value
__device__ __forceinline__ float block_max256(float m, float* sred, float* sbc) {
    int tid = threadIdx.x;
#pragma unroll
    for (int o = 16; o > 0; o >>= 1)
        m = fmaxf(m, __shfl_xor_sync(0xFFFFFFFF, m, o));
    if ((tid & 31) == 0) sred[tid >> 5] = m;
    __syncthreads();
    if (tid < 8) {
        m = sred[tid];
#pragma unroll
        for (int o = 4; o > 0; o >>= 1)
            m = fmaxf(m, __shfl_xor_sync(0xFF, m, o));
        if (tid == 0) *sbc = m;
    }
    __syncthreads();
    return *sbc;
}

// ---------------------------------------------------------------------------
// 1) Prep: per-row mix quant (blocks 0..16383) + per-row weight quant
// ---------------------------------------------------------------------------
__global__ void prep_quant(const float* __restrict__ x,
                           const float* __restrict__ mk,
                           const float* __restrict__ mv,
                           const float* __restrict__ mr,
                           const float* __restrict__ W0, const float* __restrict__ W1,
                           const float* __restrict__ W2, const float* __restrict__ W3) {
    __shared__ float sred[8];
    __shared__ float sbc;
    int blk = blockIdx.x;
    int tid = threadIdx.x;
    if (blk == 0 && tid == 0) g_svb = 0;   // reset v-scale for this invocation

    if (blk < MTOT) {
        int m = blk;
        int t = m & (SEQ - 1);
        size_t idx = (size_t)m * HIDDEN + tid * 4;
        int h = tid * 4;

        float4 xc = *reinterpret_cast<const float4*>(x + idx);
        float4 xp = (t == 0) ? make_float4(0.f, 0.f, 0.f, 0.f)
                             : *reinterpret_cast<const float4*>(x + idx - HIDDEN);

        float lm = fmaxf(fmaxf(fmaxf(fabsf(xc.x), fabsf(xc.y)),
                               fmaxf(fabsf(xc.z), fabsf(xc.w))),
                         fmaxf(fmaxf(fabsf(xp.x), fabsf(xp.y)),
                               fmaxf(fabsf(xp.z), fabsf(xp.w))));
        float rmax = block_max256(lm, sred, &sbc);
        if (tid == 0) g_xsc[m] = rmax;
        float inv = (rmax > 0.f) ? (QMAXF / rmax) : 0.f;

        float4 k4 = *reinterpret_cast<const float4*>(mk + h);
        float4 v4 = *reinterpret_cast<const float4*>(mv + h);
        float4 r4 = *reinterpret_cast<const float4*>(mr + h);

        float xcf[4] = {xc.x, xc.y, xc.z, xc.w};
        float xpf[4] = {xp.x, xp.y, xp.z, xp.w};
        float kf[4] = {k4.x, k4.y, k4.z, k4.w};
        float vf[4] = {v4.x, v4.y, v4.z, v4.w};
        float rf[4] = {r4.x, r4.y, r4.z, r4.w};
        float ok[4], ov[4], orr[4];
#pragma unroll
        for (int j = 0; j < 4; j++) {
            ok[j]  = xcf[j] * kf[j] + xpf[j] * (1.f - kf[j]);
            ov[j]  = xcf[j] * vf[j] + xpf[j] * (1.f - vf[j]);
            orr[j] = xcf[j] * rf[j] + xpf[j] * (1.f - rf[j]);
        }
        uint32_t p1, p0;
        quant4(ok, inv, p1, p0);
        *reinterpret_cast<uint32_t*>(g_xk1 + idx) = p1;
        *reinterpret_cast<uint32_t*>(g_xk0 + idx) = p0;
        quant4(ov, inv, p1, p0);
        *reinterpret_cast<uint32_t*>(g_xv1 + idx) = p1;
        *reinterpret_cast<uint32_t*>(g_xv0 + idx) = p0;
        quant4(orr, inv, p1, p0);
        *reinterpret_cast<uint32_t*>(g_xr1 + idx) = p1;
        *reinterpret_cast<uint32_t*>(g_xr0 + idx) = p0;
    } else {
        int w = blk - MTOT;                // 0..4095
        int sel = w >> 10;
        int n = w & (HIDDEN - 1);
        const float* W; int8_t *d1, *d0;
        switch (sel) {
            case 0: W = W0; d1 = g_Wk1; d0 = g_Wk0; break;
            case 1: W = W1; d1 = g_Wv1; d0 = g_Wv0; break;
            case 2: W = W2; d1 = g_Wr1; d0 = g_Wr0; break;
            default: W = W3; d1 = g_Wo1; d0 = g_Wo0; break;
        }
        size_t idx = (size_t)n * HIDDEN + tid * 4;
        float4 wvv = *reinterpret_cast<const float4*>(W + idx);
        float lm = fmaxf(fmaxf(fabsf(wvv.x), fabsf(wvv.y)),
                         fmaxf(fabsf(wvv.z), fabsf(wvv.w)));
        float rmax = block_max256(lm, sred, &sbc);
        if (tid == 0) g_wsc[w] = rmax;
        float inv = (rmax > 0.f) ? (QMAXF / rmax) : 0.f;

        float wf[4] = {wvv.x, wvv.y, wvv.z, wvv.w};
        uint32_t p1, p0;
        quant4(wf, inv, p1, p0);
        *reinterpret_cast<uint32_t*>(d1 + idx) = p1;
        *reinterpret_cast<uint32_t*>(d0 + idx) = p0;
    }
}

// ---------------------------------------------------------------------------
// 2) int8 IMMA GEMM (unchanged mainloop; per-row x per-col scales)
// ---------------------------------------------------------------------------
template <bool FUSED>
__global__ __launch_bounds__(GTHREADS, 1)
void gemm_imma(float* __restrict__ outC) {
    extern __shared__ __align__(128) char smem[];
    __shared__ unsigned s_vmax;

    const int8_t *A1g, *A0g, *B1g, *B0g;
    float* C;
    const float* wscp;
    float sA = 0.f;
    bool sigmoid = false, vmax = false;
    if (FUSED) {
        int z = blockIdx.z;
        wscp = g_wsc + z * HIDDEN;
        if (z == 0)      { A1g = g_xk1; A0g = g_xk0; B1g = g_Wk1; B0g = g_Wk0; C = g_k; }
        else if (z == 1) { A1g = g_xv1; A0g = g_xv0; B1g = g_Wv1; B0g = g_Wv0; C = g_v; vmax = true; }
        else             { A1g = g_xr1; A0g = g_xr0; B1g = g_Wr1; B0g = g_Wr0; C = g_r; sigmoid = true; }
    } else {
        A1g = g_o1; A0g = g_o0; B1g = g_Wo1; B0g = g_Wo0; C = outC;
        wscp = g_wsc + 3 * HIDDEN;
        sA = __uint_as_float(g_svb);
    }
    const float qi2 = 1.0f / (QMAXF * QMAXF);

    const int tid = threadIdx.x;
    const int wid = tid >> 5;
    const int lane = tid & 31;
    const int wm = wid >> 2;
    const int wn = wid & 3;
    const int gr = lane >> 2;
    const int tg = (lane & 3) * 2;
    const int bm = blockIdx.y * BM;
    const int bn = blockIdx.x * BN;
    const uint32_t sbase = smem_u32(smem);

    if (vmax && tid == 0) s_vmax = 0;

    const int a_row = lane & 15;
    const int a_kB  = (lane >> 4) * 16;
    const int b_row = (lane & 7) + ((lane >> 4) & 1) * 8;
    const int b_kB  = ((lane >> 3) & 1) * 16;

    const int l_row = tid >> 2;
    const int l_ch  = tid & 3;
    auto load_stage = [&](int c, int stg) {
        const uint32_t sb = sbase + stg * STAGE_BYTES;
        const int k0 = c * BK;
        uint32_t so = l_row * PITCH + l_ch * 16;
        size_t ga = (size_t)(bm + l_row) * HIDDEN + k0 + l_ch * 16;
        size_t gb = (size_t)(bn + l_row) * HIDDEN + k0 + l_ch * 16;
        cp16(sb + A1_OFF + so, A1g + ga);
        cp16(sb + A0_OFF + so, A0g + ga);
        cp16(sb + B1_OFF + so, B1g + gb);
        cp16(sb + B0_OFF + so, B0g + gb);
        asm volatile("cp.async.commit_group;" ::: "memory");
    };

    int P2[2][4][4], P1[2][4][4];
#pragma unroll
    for (int i = 0; i < 2; i++)
#pragma unroll
        for (int j = 0; j < 4; j++)
#pragma unroll
            for (int q = 0; q < 4; q++) { P2[i][j][q] = 0; P1[i][j][q] = 0; }

    load_stage(0, 0);
    load_stage(1, 1);
    load_stage(2, 2);

    int stg = 0, nstg = 3;
#pragma unroll 1
    for (int c = 0; c < KITER; c++) {
        if ((c & 1) == 0) __syncthreads();

        if (c + 3 < KITER) load_stage(c + 3, nstg);
        else asm volatile("cp.async.commit_group;" ::: "memory");

        asm volatile("cp.async.wait_group 3;" ::: "memory");

        const uint32_t sb = sbase + stg * STAGE_BYTES;
        if (++stg == NSTAGE) stg = 0;
        if (++nstg == NSTAGE) nstg = 0;

#pragma unroll
        for (int kh = 0; kh < 2; kh++) {
            const int kb = kh * 32;
            uint32_t b1f[4][2], b0f[4][2];
#pragma unroll
            for (int np = 0; np < 2; np++) {
                int n0 = wn * 32 + np * 16;
                uint32_t ro = (uint32_t)(n0 + b_row) * PITCH + kb + b_kB;
                LDMATRIX_X4(b1f[np * 2][0], b1f[np * 2][1],
                            b1f[np * 2 + 1][0], b1f[np * 2 + 1][1], sb + B1_OFF + ro);
                LDMATRIX_X4(b0f[np * 2][0], b0f[np * 2][1],
                            b0f[np * 2 + 1][0], b0f[np * 2 + 1][1], sb + B0_OFF + ro);
            }
#pragma unroll
            for (int mf = 0; mf < 2; mf++) {
                int r0 = wm * 32 + mf * 16;
                uint32_t ro = (uint32_t)(r0 + a_row) * PITCH + kb + a_kB;
                uint32_t a1f[4], a0f[4];
                LDMATRIX_X4(a1f[0], a1f[1], a1f[2], a1f[3], sb + A1_OFF + ro);
                LDMATRIX_X4(a0f[0], a0f[1], a0f[2], a0f[3], sb + A0_OFF + ro);
#pragma unroll
                for (int nf = 0; nf < 4; nf++) {
                    MMA_S8(P2[mf][nf], a1f, b1f[nf]);
                    MMA_S8(P1[mf][nf], a1f, b0f[nf]);
                    MMA_S8(P1[mf][nf], a0f, b1f[nf]);
                }
            }
        }
    }

    // epilogue: per-row (A) x per-col (B) scales
    float lmax = 0.f;
#pragma unroll
    for (int mf = 0; mf < 2; mf++) {
        int r0 = bm + wm * 32 + mf * 16 + gr;
        float ra = FUSED ? g_xsc[r0] : sA;
        float rb = FUSED ? g_xsc[r0 + 8] : sA;
#pragma unroll
        for (int nf = 0; nf < 4; nf++) {
            int cc = bn + wn * 32 + nf * 8 + tg;
            float cs0 = wscp[cc] * qi2;
            float cs1 = wscp[cc + 1] * qi2;
            float cv[4];
            cv[0] = ra * cs0 * (16384.0f * (float)P2[mf][nf][0] + 128.0f * (float)P1[mf][nf][0]);
            cv[1] = ra * cs1 * (16384.0f * (float)P2[mf][nf][1] + 128.0f * (float)P1[mf][nf][1]);
            cv[2] = rb * cs0 * (16384.0f * (float)P2[mf][nf][2] + 128.0f * (float)P1[mf][nf][2]);
            cv[3] = rb * cs1 * (16384.0f * (float)P2[mf][nf][3] + 128.0f * (float)P1[mf][nf][3]);
#pragma unroll
            for (int q = 0; q < 4; q++) {
                if (FUSED && vmax) lmax = fmaxf(lmax, fabsf(cv[q]));
                if (FUSED && sigmoid) cv[q] = 1.f / (1.f + __expf(-cv[q]));
            }
            *reinterpret_cast<float2*>(C + (size_t)r0 * HIDDEN + cc) = make_float2(cv[0], cv[1]);
            *reinterpret_cast<float2*>(C + (size_t)(r0 + 8) * HIDDEN + cc) = make_float2(cv[2], cv[3]);
        }
    }

    if (FUSED && vmax) {
        __syncthreads();
#pragma unroll
        for (int o = 16; o > 0; o >>= 1)
            lmax = fmaxf(lmax, __shfl_xor_sync(0xFFFFFFFF, lmax, o));
        if (lane == 0) atomicMax(&s_vmax, __float_as_uint(lmax));
        __syncthreads();
        if (tid == 0) atomicMax(&g_svb, s_vmax);
    }
}

// ---------------------------------------------------------------------------
// 3) Chunk-parallel WKV scan
// ---------------------------------------------------------------------------
__global__ void wkv_phase1(const float* __restrict__ td) {
    int idx = blockIdx.x * blockDim.x + threadIdx.x;   // over CH*NCHUNK/4
    if (idx >= CH * NCHUNK / 4) return;
    int h4 = (idx & 255) * 4;
    int bc = idx >> 8;                  // b * NCHUNK + c
    int c = bc & (NCHUNK - 1);
    int b = bc >> 5;

    float4 w4 = *reinterpret_cast<const float4*>(td + h4);
    const float wv[4] = {w4.x, w4.y, w4.z, w4.w};

    const size_t base = ((size_t)b * SEQ + (size_t)c * LCHUNK) * HIDDEN + h4;
    const float* kp = g_k + base;
    const float* vp = g_v + base;

    float aa[4], bb[4], pp[4];
#pragma unroll
    for (int j = 0; j < 4; j++) { aa[j] = 0.f; bb[j] = 0.f; pp[j] = NEG_INF; }

#pragma unroll 2
    for (int t = 0; t < LCHUNK; t++) {
        float4 k4 = *reinterpret_cast<const float4*>(kp + (size_t)t * HIDDEN);
        float4 v4 = *reinterpret_cast<const float4*>(vp + (size_t)t * HIDDEN);
        float kf[4] = {k4.x, k4.y, k4.z, k4.w};
        float vf[4] = {v4.x, v4.y, v4.z, v4.w};
#pragma unroll
        for (int j = 0; j < 4; j++) {
            float ww2 = wv[j] + pp[j];
            float p2 = fmaxf(ww2, kf[j]);
            float e1 = __expf(ww2 - p2);
            float e2 = __expf(kf[j] - p2);
            aa[j] = e1 * aa[j] + e2 * vf[j];
            bb[j] = e1 * bb[j] + e2;
            pp[j] = p2;
        }
    }
    int s = bc * HIDDEN + h4;
    *reinterpret_cast<float4*>(g_saa + s) = make_float4(aa[0], aa[1], aa[2], aa[3]);
    *reinterpret_cast<float4*>(g_sbb + s) = make_float4(bb[0], bb[1], bb[2], bb[3]);
    *reinterpret_cast<float4*>(g_spp + s) = make_float4(pp[0], pp[1], pp[2], pp[3]);
}

// Warp Kogge-Stone scan over chunks: one warp per (b,h) channel, lane = chunk.
// At step offset d, the right operand spans exactly d chunks for lanes >= d,
// so the left state decays by w * d * LCHUNK. Exclusive prefix via shfl_up(1).
__global__ void wkv_phase2(const float* __restrict__ td) {
    int gwarp = (blockIdx.x * blockDim.x + threadIdx.x) >> 5;
    if (gwarp >= CH) return;
    int lane = threadIdx.x & 31;
    int h = gwarp & (HIDDEN - 1);
    int b = gwarp >> 10;
    const float w = td[h];

    int s = (b * NCHUNK + lane) * HIDDEN + h;
    float aa = g_saa[s], bb = g_sbb[s], pp = g_spp[s];

#pragma unroll
    for (int d = 1; d < NCHUNK; d <<= 1) {
        float oaa = __shfl_up_sync(0xFFFFFFFF, aa, d);
        float obb = __shfl_up_sync(0xFFFFFFFF, bb, d);
        float opp = __shfl_up_sync(0xFFFFFFFF, pp, d);
        if (lane >= d) {
            float sp = opp + w * (float)(d * LCHUNK);
            float p = fmaxf(sp, pp);
            float e1 = __expf(sp - p);
            float e2 = __expf(pp - p);
            aa = e1 * oaa + e2 * aa;
            bb = e1 * obb + e2 * bb;
            pp = p;
        }
    }

    // exclusive prefix
    float exaa = __shfl_up_sync(0xFFFFFFFF, aa, 1);
    float exbb = __shfl_up_sync(0xFFFFFFFF, bb, 1);
    float expp = __shfl_up_sync(0xFFFFFFFF, pp, 1);
    if (lane == 0) { exaa = 0.f; exbb = 0.f; expp = NEG_INF; }
    g_iaa[s] = exaa;
    g_ibb[s] = exbb;
    g_ipp[s] = expp;
}

__global__ void wkv_phase3(const float* __restrict__ td,
                           const float* __restrict__ tf) {
    int idx = blockIdx.x * blockDim.x + threadIdx.x;   // over CH*NCHUNK/4
    if (idx >= CH * NCHUNK / 4) return;
    int h4 = (idx & 255) * 4;
    int bc = idx >> 8;
    int c = bc & (NCHUNK - 1);
    int b = bc >> 5;

    float4 w4 = *reinterpret_cast<const float4*>(td + h4);
    float4 u4 = *reinterpret_cast<const float4*>(tf + h4);
    const float wv[4] = {w4.x, w4.y, w4.z, w4.w};
    const float uv[4] = {u4.x, u4.y, u4.z, u4.w};

    float sv = __uint_as_float(g_svb);
    float inv = (sv > 0.f) ? (QMAXF / sv) : 0.f;

    const size_t base = ((size_t)b * SEQ + (size_t)c * LCHUNK) * HIDDEN + h4;
    const float* kp = g_k + base;
    const float* vp = g_v + base;
    const float* rp = g_r + base;

    int s = bc * HIDDEN + h4;
    float4 a4 = *reinterpret_cast<const float4*>(g_iaa + s);
    float4 b4 = *reinterpret_cast<const float4*>(g_ibb + s);
    float4 p4 = *reinterpret_cast<const float4*>(g_ipp + s);
    float aa[4] = {a4.x, a4.y, a4.z, a4.w};
    float bb[4] = {b4.x, b4.y, b4.z, b4.w};
    float pp[4] = {p4.x, p4.y, p4.z, p4.w};

#pragma unroll 2
    for (int t = 0; t < LCHUNK; t++) {
        size_t off = (size_t)t * HIDDEN;
        float4 k4 = *reinterpret_cast<const float4*>(kp + off);
        float4 v4 = *reinterpret_cast<const float4*>(vp + off);
        float4 r4 = *reinterpret_cast<const float4*>(rp + off);
        float kf[4] = {k4.x, k4.y, k4.z, k4.w};
        float vf[4] = {v4.x, v4.y, v4.z, v4.w};
        float rf[4] = {r4.x, r4.y, r4.z, r4.w};
        uint32_t o1 = 0, o0 = 0;
#pragma unroll
        for (int j = 0; j < 4; j++) {
            float ww = uv[j] + kf[j];
            float p = fmaxf(pp[j], ww);
            float e1 = __expf(pp[j] - p);
            float e2 = __expf(ww - p);
            float wkv = (e1 * aa[j] + e2 * vf[j]) / (e1 * bb[j] + e2 + 1e-9f);
            float o = rf[j] * wkv;

            float q = rintf(o * inv);
            q = fminf(fmaxf(q, -QMAXF), QMAXF);
            float q1 = rintf(q * 0.0078125f);
            float q0 = q - 128.0f * q1;
            o1 |= ((uint32_t)(uint8_t)(int8_t)(int)q1) << (j * 8);
            o0 |= ((uint32_t)(uint8_t)(int8_t)(int)q0) << (j * 8);

            float ww2 = wv[j] + pp[j];
            float p2 = fmaxf(ww2, kf[j]);
            float e1b = __expf(ww2 - p2);
            float e2b = __expf(kf[j] - p2);
            aa[j] = e1b * aa[j] + e2b * vf[j];
            bb[j] = e1b * bb[j] + e2b;
            pp[j] = p2;
        }
        *reinterpret_cast<uint32_t*>(g_o1 + base + off) = o1;
        *reinterpret_cast<uint32_t*>(g_o0 + base + off) = o0;
    }
}

// ---------------------------------------------------------------------------
// Launch
// ---------------------------------------------------------------------------
extern "C" void kernel_launch(void* const* d_in, const int* in_sizes, int n_in,
                              void* d_out, int out_size) {
    const float* x  = (const float*)d_in[0];
    const float* td = (const float*)d_in[1];
    const float* tf = (const float*)d_in[2];
    const float* mk = (const float*)d_in[3];
    const float* mv = (const float*)d_in[4];
    const float* mr = (const float*)d_in[5];
    const float* Wk = (const float*)d_in[6];
    const float* Wv = (const float*)d_in[7];
    const float* Wr = (const float*)d_in[8];
    const float* Wo = (const float*)d_in[9];
    float* out = (float*)d_out;

    cudaFuncSetAttribute(gemm_imma<true>,  cudaFuncAttributeMaxDynamicSharedMemorySize, SMEM_TOTAL);
    cudaFuncSetAttribute(gemm_imma<false>, cudaFuncAttributeMaxDynamicSharedMemorySize, SMEM_TOTAL);

    // 1) prep: per-row mix quant + per-row weight quant (also resets g_svb)
    prep_quant<<<MTOT + 4 * HIDDEN, 256>>>(x, mk, mv, mr, Wk, Wv, Wr, Wo);

    // 2) fused k/v/r projections (int8 imma)
    dim3 ggrid(HIDDEN / BN, MTOT / BM, 3);   // (8, 128, 3)
    gemm_imma<true><<<ggrid, GTHREADS, SMEM_TOTAL>>>(nullptr);

    // 3) chunk-parallel wkv
    wkv_phase1<<<(CH * NCHUNK / 4 + 255) / 256, 256>>>(td);
    wkv_phase2<<<(CH * 32 + 255) / 256, 256>>>(td);   // one warp per channel
    wkv_phase3<<<(CH * NCHUNK / 4 + 255) / 256, 256>>>(td, tf);

    // 4) output projection
    dim3 ogrid(HIDDEN / BN, MTOT / BM, 1);
    gemm_imma<false><<<ogrid, GTHREADS, SMEM_TOTAL>>>(out);
}